// round 9
// baseline (speedup 1.0000x reference)
#include <cuda_runtime.h>
#include <cstdint>
#include <math.h>

#define BB     4096
#define TT     56
#define NSTEPS 28
#define HH     126
#define GG     378
#define ANN_   30
#define ENC_   20
#define DEC_   15

#define HS     128      // padded hidden stride
#define ROWS   14
#define NBLK   ((BB + ROWS - 1) / ROWS)   // 293
#define PIN    20       // s_in pitch

// ---------------- scratch (device globals; no allocations) ----------------
__device__ float g_h0[BB * HS];
__device__ float g_h1[BB * HS];
__device__ float g_enc_out[TT * BB * HS];
__device__ float g_Uo[TT * BB * HS];
__device__ float g_giE[(size_t)TT * BB * 384];
__device__ float g_giD[(size_t)NSTEPS * BB * 384];
__device__ float g_Wenc[128 * 384];
__device__ float g_Wdec[256 * 384];
__device__ float g_WgiE[ENC_ * 384];
__device__ float g_WgiD[DEC_ * 384];
__device__ float g_bgE[384];
__device__ float g_bgD[384];
__device__ float g_UWTp[HH * HS];
__device__ float g_WlTp[HH * HS];
__device__ float g_Ubp[HS];
__device__ float g_Wlbp[HS];
__device__ float g_Vp[HS];

// ---------------- fast transcendentals ----------------
__device__ __forceinline__ float ex2f(float x) { float y; asm("ex2.approx.f32 %0, %1;" : "=f"(y) : "f"(x)); return y; }
__device__ __forceinline__ float rcpf(float x) { float y; asm("rcp.approx.f32 %0, %1;" : "=f"(y) : "f"(x)); return y; }
__device__ __forceinline__ float tanha(float x) { float y; asm("tanh.approx.f32 %0, %1;" : "=f"(y) : "f"(x)); return y; }
#define LOG2E_ 1.4426950408889634f
__device__ __forceinline__ float sigf(float v)  { return rcpf(1.0f + ex2f(-v * LOG2E_)); }
__device__ __forceinline__ float tanhp(float v) { return 2.0f * rcpf(1.0f + ex2f(-2.0f * v * LOG2E_)) - 1.0f; }

// ---------------- cp.async helpers ----------------
__device__ __forceinline__ void cpa16(unsigned dst, const void* src) {
    asm volatile("cp.async.cg.shared.global [%0], [%1], 16;" :: "r"(dst), "l"(src));
}
__device__ __forceinline__ void cpa_commit() { asm volatile("cp.async.commit_group;"); }
__device__ __forceinline__ void cpa_wait0()  { asm volatile("cp.async.wait_group 0;"); }

// ---------------- weight prep ----------------
__global__ void prep_weights(const float* __restrict__ eWih, const float* __restrict__ eWhh,
                             const float* __restrict__ dWih, const float* __restrict__ dWhh,
                             const float* __restrict__ U,    const float* __restrict__ Ub,
                             const float* __restrict__ Wl,   const float* __restrict__ Wlb,
                             const float* __restrict__ V,
                             const float* __restrict__ ebih, const float* __restrict__ ebhh,
                             const float* __restrict__ dbih, const float* __restrict__ dbhh) {
    int i = blockIdx.x * 256 + threadIdx.x;
    const int Nwe = 128 * 384, Nwd = 256 * 384, Nge = ENC_ * 384, Ngd = DEC_ * 384;
    const int Nuw = HH * HS;
    if (i < Nwe) {
        int k = i / 384, j = i % 384;
        g_Wenc[i] = (j < GG && k < HH) ? eWhh[j * HH + k] : 0.0f;
        return;
    }
    i -= Nwe;
    if (i < Nwd) {
        int k = i / 384, j = i % 384;
        float v = 0.0f;
        if (j < GG) {
            if (k < 126) v = dWih[j * 142 + 16 + k];
            else if (k == 126) v = dWih[j * 142 + 0];
            else if (k >= 128 && k < 254) v = dWhh[j * HH + (k - 128)];
        }
        g_Wdec[i] = v; return;
    }
    i -= Nwd;
    if (i < Nge) {
        int k = i / 384, j = i % 384;
        g_WgiE[i] = (j < GG) ? eWih[j * ENC_ + k] : 0.0f;
        return;
    }
    i -= Nge;
    if (i < Ngd) {
        int k = i / 384, j = i % 384;
        g_WgiD[i] = (j < GG) ? dWih[j * 142 + 1 + k] : 0.0f;
        return;
    }
    i -= Ngd;
    if (i < 384) {
        g_bgE[i] = (i < GG) ? (ebih[i] + ((i < 2 * HH) ? ebhh[i] : 0.0f)) : 0.0f;
        g_bgD[i] = (i < GG) ? (dbih[i] + ((i < 2 * HH) ? dbhh[i] : 0.0f)) : 0.0f;
        return;
    }
    i -= 384;
    if (i < Nuw) { int k = i / HS, j = i % HS; g_UWTp[i] = (j < HH) ? U[j * HH + k] : 0.0f; return; }
    i -= Nuw;
    if (i < Nuw) { int k = i / HS, j = i % HS; g_WlTp[i] = (j < HH) ? Wl[j * HH + k] : 0.0f; return; }
    i -= Nuw;
    if (i < HS) { g_Ubp[i] = (i < HH) ? Ub[i] : 0.0f; return; }
    i -= HS;
    if (i < HS) { g_Wlbp[i] = (i < HH) ? Wlb[i] : 0.0f; return; }
    i -= HS;
    if (i < HS) { g_Vp[i] = (i < HH) ? V[i] : 0.0f; }
}

// ---------------- s2h MLP ----------------
__global__ void s2h_kernel(const float* __restrict__ ann,
                           const float* __restrict__ W1, const float* __restrict__ b1,
                           const float* __restrict__ W2, const float* __restrict__ b2,
                           float* __restrict__ h) {
    __shared__ float a[ANN_];
    __shared__ float mid[96];
    int b = blockIdx.x;
    int tid = threadIdx.x;
    if (tid < ANN_) a[tid] = ann[b * ANN_ + tid];
    __syncthreads();
    if (tid < 96) {
        float acc = b1[tid];
        #pragma unroll
        for (int k = 0; k < ANN_; k++) acc += W1[tid * ANN_ + k] * a[k];
        mid[tid] = fmaxf(acc, 0.0f);
    }
    __syncthreads();
    if (tid < HH) {
        float acc = b2[tid];
        #pragma unroll 4
        for (int k = 0; k < 96; k++) acc += W2[tid * 96 + k] * mid[k];
        h[(size_t)b * HS + tid] = acc;
    }
}

// ---------------- gi GEMM (bias folded) ----------------
template <int KD>
__global__ __launch_bounds__(384) void gi_kernel(const float* __restrict__ in,
                                                 const float* __restrict__ Wg,
                                                 const float* __restrict__ bg,
                                                 float* __restrict__ gi) {
    __shared__ float s_w[KD * 384];
    __shared__ float s_in[KD * 16];
    const int tid = threadIdx.x;
    const int b0 = blockIdx.x * 16;
    for (int i = tid; i < KD * 96; i += 384)
        reinterpret_cast<float4*>(s_w)[i] = reinterpret_cast<const float4*>(Wg)[i];
    for (int i = tid; i < KD * 16; i += 384) {
        int r = i / KD, k = i % KD;
        s_in[k * 16 + r] = in[(size_t)(b0 + r) * KD + k];
    }
    __syncthreads();
    float acc[16];
    #pragma unroll
    for (int r = 0; r < 16; r++) acc[r] = 0.0f;
    #pragma unroll 4
    for (int k = 0; k < KD; k++) {
        float w = s_w[k * 384 + tid];
        const float4* sp = reinterpret_cast<const float4*>(s_in + k * 16);
        float4 v0 = sp[0], v1 = sp[1], v2 = sp[2], v3 = sp[3];
        acc[0]  += w * v0.x; acc[1]  += w * v0.y; acc[2]  += w * v0.z; acc[3]  += w * v0.w;
        acc[4]  += w * v1.x; acc[5]  += w * v1.y; acc[6]  += w * v1.z; acc[7]  += w * v1.w;
        acc[8]  += w * v2.x; acc[9]  += w * v2.y; acc[10] += w * v2.z; acc[11] += w * v2.w;
        acc[12] += w * v3.x; acc[13] += w * v3.y; acc[14] += w * v3.z; acc[15] += w * v3.w;
    }
    float bb = bg[tid];
    #pragma unroll
    for (int r = 0; r < 16; r++) gi[(size_t)(b0 + r) * 384 + tid] = acc[r] + bb;
}

// ---------------- encoder GRU step ----------------
__global__ __launch_bounds__(384, 2) void gruE_kernel(
        const float* __restrict__ h_in,
        const float* __restrict__ W,      // [128][384]
        const float* __restrict__ gi,     // [row][384], biases folded
        const float* __restrict__ bhh,
        float* __restrict__ h_out) {
    constexpr int KP = 128, NC = 8, CHF = 16 * 384;
    extern __shared__ float sm[];
    float* s_in   = sm;                        // 128*PIN
    float* pool   = sm + KP * PIN;             // 2*CHF
    float* s_preA = pool;                      // 378*15
    float* s_preB = pool + GG * 15;            // 126*15

    const int tid = threadIdx.x;
    const int b0 = blockIdx.x * ROWS;
    const int nrow = min(ROWS, BB - b0);
    unsigned pool_sa = (unsigned)__cvta_generic_to_shared(pool);

    {
        const float* src = W + (size_t)tid * 4;
        #pragma unroll
        for (int v = 0; v < 4; v++)
            cpa16(pool_sa + (unsigned)(tid + 384 * v) * 16u, src + 1536 * v);
        cpa_commit();
    }
    for (int i = tid; i < HH * ROWS; i += 384) {
        int r = i / HH, k = i % HH;
        s_in[k * PIN + r] = (r < nrow) ? h_in[(size_t)(b0 + r) * HS + k] : 0.0f;
    }
    if (tid < 2 * ROWS) {
        int k = tid / ROWS, r = tid % ROWS;
        s_in[(HH + k) * PIN + r] = 0.0f;
    }
    cpa_wait0();
    __syncthreads();

    float acc[ROWS];
    #pragma unroll
    for (int r = 0; r < ROWS; r++) acc[r] = 0.0f;

    for (int c = 0; c < NC; c++) {
        const int cur = c & 1;
        if (c + 1 < NC) {
            const float* src = W + (size_t)(c + 1) * CHF + (size_t)tid * 4;
            unsigned dst = pool_sa + (unsigned)((1 - cur) * CHF + tid * 4) * 4u;
            #pragma unroll
            for (int v = 0; v < 4; v++)
                cpa16(dst + (unsigned)v * 384u * 16u, src + 1536 * v);
            cpa_commit();
        }
        const float* wp = pool + cur * CHF + tid;
        const float* ip = s_in + c * 16 * PIN;
        #pragma unroll
        for (int kk = 0; kk < 16; kk++) {
            float w = wp[kk * 384];
            const float* sp = ip + kk * PIN;
            float4 v0 = *reinterpret_cast<const float4*>(sp);
            float4 v1 = *reinterpret_cast<const float4*>(sp + 4);
            float4 v2 = *reinterpret_cast<const float4*>(sp + 8);
            float2 v3 = *reinterpret_cast<const float2*>(sp + 12);
            acc[0]  += w * v0.x; acc[1]  += w * v0.y; acc[2]  += w * v0.z; acc[3]  += w * v0.w;
            acc[4]  += w * v1.x; acc[5]  += w * v1.y; acc[6]  += w * v1.z; acc[7]  += w * v1.w;
            acc[8]  += w * v2.x; acc[9]  += w * v2.y; acc[10] += w * v2.z; acc[11] += w * v2.w;
            acc[12] += w * v3.x; acc[13] += w * v3.y;
        }
        if (c + 1 < NC) cpa_wait0();
        __syncthreads();
    }

    float giv[ROWS];
    #pragma unroll
    for (int r = 0; r < ROWS; r++)
        giv[r] = (r < nrow) ? gi[(size_t)(b0 + r) * 384 + tid] : 0.0f;
    if (tid < GG) {
        #pragma unroll
        for (int r = 0; r < ROWS; r++) s_preA[tid * 15 + r] = acc[r] + giv[r];
        if (tid >= 2 * HH) {
            #pragma unroll
            for (int r = 0; r < ROWS; r++) s_preB[(tid - 2 * HH) * 15 + r] = giv[r];
        }
    }
    __syncthreads();

    for (int i = tid; i < ROWS * 128; i += 384) {
        int r = i >> 7;
        int j = i & 127;
        if (r >= nrow) continue;
        if (j < HH) {
            float pr = s_preA[j * 15 + r];
            float pz = s_preA[(HH + j) * 15 + r];
            float nx = s_preB[j * 15 + r];
            float nh = s_preA[(2 * HH + j) * 15 + r] - nx + bhh[2 * HH + j];
            float rg = sigf(pr);
            float zg = sigf(pz);
            float nn = tanhp(nx + rg * nh);
            float hv = s_in[j * PIN + r];
            h_out[(size_t)(b0 + r) * HS + j] = (1.0f - zg) * nn + zg * hv;
        } else {
            h_out[(size_t)(b0 + r) * HS + j] = 0.0f;
        }
    }
}

// ---------------- fully fused decoder step ----------------
__global__ __launch_bounds__(384, 2) void gruD_kernel(
        const float* __restrict__ h_in,
        const float* __restrict__ W,      // [256][384]
        const float* __restrict__ gi,     // [row][384], biases folded
        const float* __restrict__ bhh,
        float* __restrict__ h_out,
        const float* __restrict__ Uo, const float* __restrict__ enc_out,
        const float* __restrict__ WlTp, const float* __restrict__ Wlbp,
        const float* __restrict__ Vp, const float* __restrict__ Vb,
        const float* __restrict__ enc_data, const float* __restrict__ prevout,
        int step,
        const float* __restrict__ h2oW, const float* __restrict__ h2ob,
        float* __restrict__ out) {
    constexpr int KP = 256, NC = 16, XDP = 128, CHF = 16 * 384;
    extern __shared__ float sm[];
    float* s_in  = sm;                         // 256*PIN = 5120
    float* pool  = sm + KP * PIN;              // 2*CHF = 12288
    float* s_wh  = pool + 2 * CHF;             // 14*132
    float* sal   = s_wh + ROWS * 132;          // 56*14
    float* s_preA = pool;                      // aliased after GEMM
    float* s_preB = pool + GG * 15;
    float* s_out  = pool + GG * 15 + HH * 15;  // 14

    const int tid = threadIdx.x;
    const int warp = tid >> 5, lane = tid & 31;
    const int b0 = blockIdx.x * ROWS;
    const int nrow = min(ROWS, BB - b0);
    unsigned pool_sa = (unsigned)__cvta_generic_to_shared(pool);

    // stage weight chunk 0 early (completes during attention phases)
    {
        const float* src = W + (size_t)tid * 4;
        #pragma unroll
        for (int v = 0; v < 4; v++)
            cpa16(pool_sa + (unsigned)(tid + 384 * v) * 16u, src + 1536 * v);
        cpa_commit();
    }

    // fill h part of s_in (k = 128..253), zero pads (254,255)
    for (int i = tid; i < HH * ROWS; i += 384) {
        int r = i / HH, k = i % HH;
        s_in[(XDP + k) * PIN + r] = (r < nrow) ? h_in[(size_t)(b0 + r) * HS + k] : 0.0f;
    }
    if (tid < 2 * ROWS) {
        int k = tid / ROWS, r = tid % ROWS;
        s_in[(XDP + HH + k) * PIN + r] = 0.0f;
    }
    // prev-output column (126) + zero pad col (127): written ONCE here,
    // never touched by the context writers (they stop at col 125).
    if (tid < ROWS) {
        int r = tid;
        float prev = 0.0f;
        if (r < nrow)
            prev = (step == 0) ? enc_data[((size_t)(TT - 1) * BB + b0 + r) * ENC_]
                               : prevout[(size_t)(step - 1) * BB + b0 + r];
        s_in[126 * PIN + r] = prev;
        s_in[127 * PIN + r] = 0.0f;
    }
    // zero x-cols of tail rows (blocks with nrow < ROWS)
    for (int i = tid; i < (ROWS - nrow) * 126; i += 384) {
        int r = nrow + i / 126, k = i % 126;
        s_in[k * PIN + r] = 0.0f;
    }
    __syncthreads();

    // Phase 0: Wh = h @ Wl^T + b for our 14 rows
    if (tid < 256) {
        int j = tid & 127, half = tid >> 7;
        float acc[7];
        #pragma unroll
        for (int i = 0; i < 7; i++) acc[i] = 0.0f;
        #pragma unroll 2
        for (int k = 0; k < HH; k++) {
            float w = WlTp[k * HS + j];
            const float* sp = s_in + (XDP + k) * PIN + half * 7;
            #pragma unroll
            for (int i = 0; i < 7; i++) acc[i] += w * sp[i];
        }
        float bj = Wlbp[j];
        #pragma unroll
        for (int i = 0; i < 7; i++) {
            int r = half * 7 + i;
            s_wh[r * 132 + j] = acc[i] + bj;
        }
    }
    __syncthreads();

    // Phase 1: scores over Uo stream
    {
        const float4 vv = *(reinterpret_cast<const float4*>(Vp) + lane);
        const float vb = Vb[0];
        for (int r = warp; r < ROWS; r += 12) {
            if (r >= nrow) continue;
            const float4 whv = *(reinterpret_cast<const float4*>(s_wh + r * 132) + lane);
            #pragma unroll 2
            for (int t = 0; t < TT; t++) {
                float4 u = *(reinterpret_cast<const float4*>(Uo + ((size_t)t * BB + b0 + r) * HS) + lane);
                float a = tanha(u.x + whv.x) * vv.x + tanha(u.y + whv.y) * vv.y
                        + tanha(u.z + whv.z) * vv.z + tanha(u.w + whv.w) * vv.w;
                #pragma unroll
                for (int off = 16; off; off >>= 1) a += __shfl_down_sync(0xffffffffu, a, off);
                if (lane == 0) sal[t * ROWS + r] = a + vb;
            }
        }
    }
    __syncthreads();

    // Phase 2: softmax over t, per row
    if (tid < nrow) {
        float mx = -1e30f;
        for (int t = 0; t < TT; t++) mx = fmaxf(mx, sal[t * ROWS + tid]);
        float sum = 0.0f;
        for (int t = 0; t < TT; t++) {
            float e = ex2f((sal[t * ROWS + tid] - mx) * LOG2E_);
            sal[t * ROWS + tid] = e;
            sum += e;
        }
        float inv = rcpf(sum);
        for (int t = 0; t < TT; t++) sal[t * ROWS + tid] *= inv;
    }
    __syncthreads();

    // Phase 3: context from enc_out stream -> s_in x-cols 0..125 ONLY
    // (cols 126/127 are owned by the prev/pad writer above — do not touch)
    for (int r = warp; r < ROWS; r += 12) {
        if (r >= nrow) continue;
        float4 a = {0.f, 0.f, 0.f, 0.f};
        #pragma unroll 2
        for (int t = 0; t < TT; t++) {
            float al = sal[t * ROWS + r];
            float4 e = *(reinterpret_cast<const float4*>(enc_out + ((size_t)t * BB + b0 + r) * HS) + lane);
            a.x += al * e.x; a.y += al * e.y; a.z += al * e.z; a.w += al * e.w;
        }
        s_in[(4 * lane + 0) * PIN + r] = a.x;
        s_in[(4 * lane + 1) * PIN + r] = a.y;
        if (lane < 31) {
            s_in[(4 * lane + 2) * PIN + r] = a.z;
            s_in[(4 * lane + 3) * PIN + r] = a.w;
        }
    }
    cpa_wait0();
    __syncthreads();

    // Phase 4: GRU GEMM
    float acc[ROWS], accx[ROWS];
    #pragma unroll
    for (int r = 0; r < ROWS; r++) { acc[r] = 0.0f; accx[r] = 0.0f; }

    for (int c = 0; c < NC; c++) {
        const int cur = c & 1;
        if (c + 1 < NC) {
            const float* src = W + (size_t)(c + 1) * CHF + (size_t)tid * 4;
            unsigned dst = pool_sa + (unsigned)((1 - cur) * CHF + tid * 4) * 4u;
            #pragma unroll
            for (int v = 0; v < 4; v++)
                cpa16(dst + (unsigned)v * 384u * 16u, src + 1536 * v);
            cpa_commit();
        }
        const float* wp = pool + cur * CHF + tid;
        const float* ip = s_in + c * 16 * PIN;
        #pragma unroll
        for (int kk = 0; kk < 16; kk++) {
            float w = wp[kk * 384];
            const float* sp = ip + kk * PIN;
            float4 v0 = *reinterpret_cast<const float4*>(sp);
            float4 v1 = *reinterpret_cast<const float4*>(sp + 4);
            float4 v2 = *reinterpret_cast<const float4*>(sp + 8);
            float2 v3 = *reinterpret_cast<const float2*>(sp + 12);
            acc[0]  += w * v0.x; acc[1]  += w * v0.y; acc[2]  += w * v0.z; acc[3]  += w * v0.w;
            acc[4]  += w * v1.x; acc[5]  += w * v1.y; acc[6]  += w * v1.z; acc[7]  += w * v1.w;
            acc[8]  += w * v2.x; acc[9]  += w * v2.y; acc[10] += w * v2.z; acc[11] += w * v2.w;
            acc[12] += w * v3.x; acc[13] += w * v3.y;
        }
        if (c == 7) {
            #pragma unroll
            for (int r = 0; r < ROWS; r++) accx[r] = acc[r];
        }
        if (c + 1 < NC) cpa_wait0();
        __syncthreads();
    }

    // add gi (coalesced), write preacts into pool (weights dead now)
    float giv[ROWS];
    #pragma unroll
    for (int r = 0; r < ROWS; r++)
        giv[r] = (r < nrow) ? gi[(size_t)(b0 + r) * 384 + tid] : 0.0f;
    if (tid < GG) {
        #pragma unroll
        for (int r = 0; r < ROWS; r++) s_preA[tid * 15 + r] = acc[r] + giv[r];
        if (tid >= 2 * HH) {
            #pragma unroll
            for (int r = 0; r < ROWS; r++) s_preB[(tid - 2 * HH) * 15 + r] = accx[r] + giv[r];
        }
    }
    if (tid < ROWS) s_out[tid] = 0.0f;
    __syncthreads();

    // gates + h2o (warp-reduced)
    for (int i = tid; i < ROWS * 128; i += 384) {
        int r = i >> 7;
        int j = i & 127;
        float val = 0.0f;
        if (r < nrow && j < HH) {
            float pr = s_preA[j * 15 + r];
            float pz = s_preA[(HH + j) * 15 + r];
            float nx = s_preB[j * 15 + r];
            float nh = s_preA[(2 * HH + j) * 15 + r] - nx + bhh[2 * HH + j];
            float rg = sigf(pr);
            float zg = sigf(pz);
            float nn = tanhp(nx + rg * nh);
            float hv = s_in[(XDP + j) * PIN + r];
            float hnew = (1.0f - zg) * nn + zg * hv;
            h_out[(size_t)(b0 + r) * HS + j] = hnew;
            val = hnew * h2oW[j];
        }
        #pragma unroll
        for (int off = 16; off; off >>= 1) val += __shfl_down_sync(0xffffffffu, val, off);
        if (lane == 0 && r < nrow) atomicAdd(&s_out[r], val);
    }
    __syncthreads();
    if (tid < nrow) out[b0 + tid] = s_out[tid] + h2ob[0];
}

// ---------------- Uo = enc_out @ U^T + b ----------------
__global__ __launch_bounds__(256, 2) void uo_kernel(const float* __restrict__ in,
                                                    const float* __restrict__ Wp,
                                                    const float* __restrict__ biasp,
                                                    float* __restrict__ out) {
    constexpr int P2 = 36;
    extern __shared__ float sm[];
    float* s_w  = sm;
    float* s_in = sm + HH * HS;
    const int tid = threadIdx.x;
    const int b0 = blockIdx.x * 32;

    {
        const float4* src = reinterpret_cast<const float4*>(Wp);
        float4* dst = reinterpret_cast<float4*>(s_w);
        for (int v = tid; v < HH * HS / 4; v += 256) dst[v] = src[v];
    }
    for (int idx = tid; idx < HH * 32; idx += 256) {
        int r = idx / HH, k = idx % HH;
        s_in[k * P2 + r] = in[(size_t)(b0 + r) * HS + k];
    }
    __syncthreads();

    const int j = tid & 127;
    const int half = tid >> 7;
    float acc[16];
    #pragma unroll
    for (int r = 0; r < 16; r++) acc[r] = 0.0f;
    #pragma unroll 2
    for (int k = 0; k < HH; k++) {
        float w = s_w[k * HS + j];
        const float4* sp = reinterpret_cast<const float4*>(s_in + k * P2 + half * 16);
        float4 v0 = sp[0], v1 = sp[1], v2 = sp[2], v3 = sp[3];
        acc[0]  += w * v0.x; acc[1]  += w * v0.y; acc[2]  += w * v0.z; acc[3]  += w * v0.w;
        acc[4]  += w * v1.x; acc[5]  += w * v1.y; acc[6]  += w * v1.z; acc[7]  += w * v1.w;
        acc[8]  += w * v2.x; acc[9]  += w * v2.y; acc[10] += w * v2.z; acc[11] += w * v2.w;
        acc[12] += w * v3.x; acc[13] += w * v3.y; acc[14] += w * v3.z; acc[15] += w * v3.w;
    }
    float bj = biasp[j];
    #pragma unroll
    for (int r = 0; r < 16; r++)
        out[(size_t)(b0 + half * 16 + r) * HS + j] = acc[r] + bj;
}

// ---------------- host side ----------------
extern "C" void kernel_launch(void* const* d_in, const int* in_sizes, int n_in,
                              void* d_out, int out_size) {
    const float* ann      = (const float*)d_in[0];
    const float* enc_data = (const float*)d_in[1];
    const float* dec_data = (const float*)d_in[2];
    const float* s2h_W1   = (const float*)d_in[3];
    const float* s2h_b1   = (const float*)d_in[4];
    const float* s2h_W2   = (const float*)d_in[5];
    const float* s2h_b2   = (const float*)d_in[6];
    const float* enc_Wih  = (const float*)d_in[7];
    const float* enc_Whh  = (const float*)d_in[8];
    const float* enc_bih  = (const float*)d_in[9];
    const float* enc_bhh  = (const float*)d_in[10];
    const float* dec_Wih  = (const float*)d_in[11];
    const float* dec_Whh  = (const float*)d_in[12];
    const float* dec_bih  = (const float*)d_in[13];
    const float* dec_bhh  = (const float*)d_in[14];
    const float* U_W      = (const float*)d_in[15];
    const float* U_b      = (const float*)d_in[16];
    const float* Wl_W     = (const float*)d_in[17];
    const float* Wl_b     = (const float*)d_in[18];
    const float* V_W      = (const float*)d_in[19];
    const float* V_b      = (const float*)d_in[20];
    const float* h2o_W    = (const float*)d_in[21];
    const float* h2o_b    = (const float*)d_in[22];
    float* outp = (float*)d_out;

    float *h0, *h1, *enc_out, *Uo, *giE, *giD;
    float *Wenc, *Wdec, *WgiE, *WgiD, *bgE, *bgD, *UWTp, *WlTp, *Ubp, *Wlbp, *Vp;
    cudaGetSymbolAddress((void**)&h0, g_h0);
    cudaGetSymbolAddress((void**)&h1, g_h1);
    cudaGetSymbolAddress((void**)&enc_out, g_enc_out);
    cudaGetSymbolAddress((void**)&Uo, g_Uo);
    cudaGetSymbolAddress((void**)&giE, g_giE);
    cudaGetSymbolAddress((void**)&giD, g_giD);
    cudaGetSymbolAddress((void**)&Wenc, g_Wenc);
    cudaGetSymbolAddress((void**)&Wdec, g_Wdec);
    cudaGetSymbolAddress((void**)&WgiE, g_WgiE);
    cudaGetSymbolAddress((void**)&WgiD, g_WgiD);
    cudaGetSymbolAddress((void**)&bgE, g_bgE);
    cudaGetSymbolAddress((void**)&bgD, g_bgD);
    cudaGetSymbolAddress((void**)&UWTp, g_UWTp);
    cudaGetSymbolAddress((void**)&WlTp, g_WlTp);
    cudaGetSymbolAddress((void**)&Ubp, g_Ubp);
    cudaGetSymbolAddress((void**)&Wlbp, g_Wlbp);
    cudaGetSymbolAddress((void**)&Vp, g_Vp);

    const size_t sm_enc = (size_t)(128 * PIN + 2 * 16 * 384) * 4;
    const size_t sm_dec = (size_t)(256 * PIN + 2 * 16 * 384 + ROWS * 132 + TT * ROWS) * 4;
    const size_t sm_uo  = (size_t)(HH * HS + HH * 36) * 4;
    cudaFuncSetAttribute((const void*)gruE_kernel,
                         cudaFuncAttributeMaxDynamicSharedMemorySize, (int)sm_enc);
    cudaFuncSetAttribute((const void*)gruD_kernel,
                         cudaFuncAttributeMaxDynamicSharedMemorySize, (int)sm_dec);
    cudaFuncSetAttribute((const void*)uo_kernel,
                         cudaFuncAttributeMaxDynamicSharedMemorySize, (int)sm_uo);

    const int total_w = 128 * 384 + 256 * 384 + ENC_ * 384 + DEC_ * 384 + 384
                      + 2 * HH * HS + 3 * HS;
    prep_weights<<<(total_w + 255) / 256, 256>>>(enc_Wih, enc_Whh, dec_Wih, dec_Whh,
                                                 U_W, U_b, Wl_W, Wl_b, V_W,
                                                 enc_bih, enc_bhh, dec_bih, dec_bhh);

    s2h_kernel<<<BB, 128>>>(ann, s2h_W1, s2h_b1, s2h_W2, s2h_b2, h0);

    gi_kernel<ENC_><<<TT * BB / 16, 384>>>(enc_data, WgiE, bgE, giE);
    gi_kernel<DEC_><<<NSTEPS * BB / 16, 384>>>(dec_data, WgiD, bgD, giD);

    for (int t = 0; t < TT; t++) {
        const float* hin = (t == 0) ? h0 : enc_out + (size_t)(t - 1) * BB * HS;
        gruE_kernel<<<NBLK, 384, sm_enc>>>(
            hin, Wenc, giE + (size_t)t * BB * 384, enc_bhh,
            enc_out + (size_t)t * BB * HS);
    }

    uo_kernel<<<TT * BB / 32, 256, sm_uo>>>(enc_out, UWTp, Ubp, Uo);

    const float* enc_last = enc_out + (size_t)(TT - 1) * BB * HS;
    for (int s = 0; s < NSTEPS; s++) {
        const float* hcur = (s == 0) ? enc_last : ((s & 1) ? h0 : h1);
        float* hnext      = (s & 1) ? h1 : h0;
        gruD_kernel<<<NBLK, 384, sm_dec>>>(
            hcur, Wdec, giD + (size_t)s * BB * 384, dec_bhh, hnext,
            Uo, enc_out, WlTp, Wlbp, Vp, V_b, enc_data, outp, s,
            h2o_W, h2o_b, outp + (size_t)s * BB);
    }
}

// round 10
// speedup vs baseline: 1.3540x; 1.3540x over previous
#include <cuda_runtime.h>
#include <cuda_bf16.h>
#include <cstdint>
#include <math.h>

#define BB     4096
#define TT     56
#define NSTEPS 28
#define HH     126
#define GG     378
#define ANN_   30
#define ENC_   20
#define DEC_   15

#define HS     128      // padded hidden stride
#define ROWS   14
#define NBLK   ((BB + ROWS - 1) / ROWS)   // 293
#define PIN    20       // s_in pitch

// ---------------- scratch (device globals; no allocations) ----------------
__device__ float g_h0[BB * HS];
__device__ float g_h1[BB * HS];
__device__ float g_enc_out[TT * BB * HS];
__device__ __nv_bfloat16 g_Uobf[(size_t)TT * BB * HS];
__device__ float g_Wh[BB * HS];
__device__ float g_scores[TT * BB];
__device__ float g_x[BB * HS];                 // [attn(126), prev, pad]
__device__ float g_giE[(size_t)TT * BB * 384];
__device__ float g_giD[(size_t)NSTEPS * BB * 384];
__device__ float g_Wenc[128 * 384];
__device__ float g_Wdec[256 * 384];
__device__ float g_WgiE[ENC_ * 384];
__device__ float g_WgiD[DEC_ * 384];
__device__ float g_bgE[384];
__device__ float g_bgD[384];
__device__ float g_UWTp[HH * HS];
__device__ float g_WlTp[HH * HS];
__device__ float g_Ubp[HS];
__device__ float g_Wlbp[HS];
__device__ float g_Vp[HS];

// ---------------- fast transcendentals ----------------
__device__ __forceinline__ float ex2f(float x) { float y; asm("ex2.approx.f32 %0, %1;" : "=f"(y) : "f"(x)); return y; }
__device__ __forceinline__ float rcpf(float x) { float y; asm("rcp.approx.f32 %0, %1;" : "=f"(y) : "f"(x)); return y; }
__device__ __forceinline__ float tanha(float x) { float y; asm("tanh.approx.f32 %0, %1;" : "=f"(y) : "f"(x)); return y; }
#define LOG2E_ 1.4426950408889634f
__device__ __forceinline__ float sigf(float v)  { return rcpf(1.0f + ex2f(-v * LOG2E_)); }
__device__ __forceinline__ float tanhp(float v) { return 2.0f * rcpf(1.0f + ex2f(-2.0f * v * LOG2E_)) - 1.0f; }

// ---------------- cp.async helpers ----------------
__device__ __forceinline__ void cpa16(unsigned dst, const void* src) {
    asm volatile("cp.async.cg.shared.global [%0], [%1], 16;" :: "r"(dst), "l"(src));
}
__device__ __forceinline__ void cpa_commit() { asm volatile("cp.async.commit_group;"); }
__device__ __forceinline__ void cpa_wait0()  { asm volatile("cp.async.wait_group 0;"); }

// ---------------- weight prep ----------------
__global__ void prep_weights(const float* __restrict__ eWih, const float* __restrict__ eWhh,
                             const float* __restrict__ dWih, const float* __restrict__ dWhh,
                             const float* __restrict__ U,    const float* __restrict__ Ub,
                             const float* __restrict__ Wl,   const float* __restrict__ Wlb,
                             const float* __restrict__ V,
                             const float* __restrict__ ebih, const float* __restrict__ ebhh,
                             const float* __restrict__ dbih, const float* __restrict__ dbhh) {
    int i = blockIdx.x * 256 + threadIdx.x;
    const int Nwe = 128 * 384, Nwd = 256 * 384, Nge = ENC_ * 384, Ngd = DEC_ * 384;
    const int Nuw = HH * HS;
    if (i < Nwe) {
        int k = i / 384, j = i % 384;
        g_Wenc[i] = (j < GG && k < HH) ? eWhh[j * HH + k] : 0.0f;
        return;
    }
    i -= Nwe;
    if (i < Nwd) {
        int k = i / 384, j = i % 384;
        float v = 0.0f;
        if (j < GG) {
            if (k < 126) v = dWih[j * 142 + 16 + k];
            else if (k == 126) v = dWih[j * 142 + 0];
            else if (k >= 128 && k < 254) v = dWhh[j * HH + (k - 128)];
        }
        g_Wdec[i] = v; return;
    }
    i -= Nwd;
    if (i < Nge) {
        int k = i / 384, j = i % 384;
        g_WgiE[i] = (j < GG) ? eWih[j * ENC_ + k] : 0.0f;
        return;
    }
    i -= Nge;
    if (i < Ngd) {
        int k = i / 384, j = i % 384;
        g_WgiD[i] = (j < GG) ? dWih[j * 142 + 1 + k] : 0.0f;
        return;
    }
    i -= Ngd;
    if (i < 384) {
        g_bgE[i] = (i < GG) ? (ebih[i] + ((i < 2 * HH) ? ebhh[i] : 0.0f)) : 0.0f;
        g_bgD[i] = (i < GG) ? (dbih[i] + ((i < 2 * HH) ? dbhh[i] : 0.0f)) : 0.0f;
        return;
    }
    i -= 384;
    if (i < Nuw) { int k = i / HS, j = i % HS; g_UWTp[i] = (j < HH) ? U[j * HH + k] : 0.0f; return; }
    i -= Nuw;
    if (i < Nuw) { int k = i / HS, j = i % HS; g_WlTp[i] = (j < HH) ? Wl[j * HH + k] : 0.0f; return; }
    i -= Nuw;
    if (i < HS) { g_Ubp[i] = (i < HH) ? Ub[i] : 0.0f; return; }
    i -= HS;
    if (i < HS) { g_Wlbp[i] = (i < HH) ? Wlb[i] : 0.0f; return; }
    i -= HS;
    if (i < HS) { g_Vp[i] = (i < HH) ? V[i] : 0.0f; }
}

// ---------------- s2h MLP ----------------
__global__ void s2h_kernel(const float* __restrict__ ann,
                           const float* __restrict__ W1, const float* __restrict__ b1,
                           const float* __restrict__ W2, const float* __restrict__ b2,
                           float* __restrict__ h) {
    __shared__ float a[ANN_];
    __shared__ float mid[96];
    int b = blockIdx.x;
    int tid = threadIdx.x;
    if (tid < ANN_) a[tid] = ann[b * ANN_ + tid];
    __syncthreads();
    if (tid < 96) {
        float acc = b1[tid];
        #pragma unroll
        for (int k = 0; k < ANN_; k++) acc += W1[tid * ANN_ + k] * a[k];
        mid[tid] = fmaxf(acc, 0.0f);
    }
    __syncthreads();
    if (tid < HH) {
        float acc = b2[tid];
        #pragma unroll 4
        for (int k = 0; k < 96; k++) acc += W2[tid * 96 + k] * mid[k];
        h[(size_t)b * HS + tid] = acc;
    }
}

// ---------------- gi GEMM (bias folded) ----------------
template <int KD>
__global__ __launch_bounds__(384) void gi_kernel(const float* __restrict__ in,
                                                 const float* __restrict__ Wg,
                                                 const float* __restrict__ bg,
                                                 float* __restrict__ gi) {
    __shared__ float s_w[KD * 384];
    __shared__ float s_in[KD * 16];
    const int tid = threadIdx.x;
    const int b0 = blockIdx.x * 16;
    for (int i = tid; i < KD * 96; i += 384)
        reinterpret_cast<float4*>(s_w)[i] = reinterpret_cast<const float4*>(Wg)[i];
    for (int i = tid; i < KD * 16; i += 384) {
        int r = i / KD, k = i % KD;
        s_in[k * 16 + r] = in[(size_t)(b0 + r) * KD + k];
    }
    __syncthreads();
    float acc[16];
    #pragma unroll
    for (int r = 0; r < 16; r++) acc[r] = 0.0f;
    #pragma unroll 4
    for (int k = 0; k < KD; k++) {
        float w = s_w[k * 384 + tid];
        const float4* sp = reinterpret_cast<const float4*>(s_in + k * 16);
        float4 v0 = sp[0], v1 = sp[1], v2 = sp[2], v3 = sp[3];
        acc[0]  += w * v0.x; acc[1]  += w * v0.y; acc[2]  += w * v0.z; acc[3]  += w * v0.w;
        acc[4]  += w * v1.x; acc[5]  += w * v1.y; acc[6]  += w * v1.z; acc[7]  += w * v1.w;
        acc[8]  += w * v2.x; acc[9]  += w * v2.y; acc[10] += w * v2.z; acc[11] += w * v2.w;
        acc[12] += w * v3.x; acc[13] += w * v3.y; acc[14] += w * v3.z; acc[15] += w * v3.w;
    }
    float bb = bg[tid];
    #pragma unroll
    for (int r = 0; r < 16; r++) gi[(size_t)(b0 + r) * 384 + tid] = acc[r] + bb;
}

// ---------------- encoder GRU step ----------------
__global__ __launch_bounds__(384, 2) void gruE_kernel(
        const float* __restrict__ h_in,
        const float* __restrict__ W,      // [128][384]
        const float* __restrict__ gi,     // [row][384], biases folded
        const float* __restrict__ bhh,
        float* __restrict__ h_out) {
    constexpr int KP = 128, NC = 8, CHF = 16 * 384;
    extern __shared__ float sm[];
    float* s_in   = sm;
    float* pool   = sm + KP * PIN;
    float* s_preA = pool;
    float* s_preB = pool + GG * 15;

    const int tid = threadIdx.x;
    const int b0 = blockIdx.x * ROWS;
    const int nrow = min(ROWS, BB - b0);
    unsigned pool_sa = (unsigned)__cvta_generic_to_shared(pool);

    {
        const float* src = W + (size_t)tid * 4;
        #pragma unroll
        for (int v = 0; v < 4; v++)
            cpa16(pool_sa + (unsigned)(tid + 384 * v) * 16u, src + 1536 * v);
        cpa_commit();
    }
    for (int i = tid; i < HH * ROWS; i += 384) {
        int r = i / HH, k = i % HH;
        s_in[k * PIN + r] = (r < nrow) ? h_in[(size_t)(b0 + r) * HS + k] : 0.0f;
    }
    if (tid < 2 * ROWS) {
        int k = tid / ROWS, r = tid % ROWS;
        s_in[(HH + k) * PIN + r] = 0.0f;
    }
    cpa_wait0();
    __syncthreads();

    float acc[ROWS];
    #pragma unroll
    for (int r = 0; r < ROWS; r++) acc[r] = 0.0f;

    for (int c = 0; c < NC; c++) {
        const int cur = c & 1;
        if (c + 1 < NC) {
            const float* src = W + (size_t)(c + 1) * CHF + (size_t)tid * 4;
            unsigned dst = pool_sa + (unsigned)((1 - cur) * CHF + tid * 4) * 4u;
            #pragma unroll
            for (int v = 0; v < 4; v++)
                cpa16(dst + (unsigned)v * 384u * 16u, src + 1536 * v);
            cpa_commit();
        }
        const float* wp = pool + cur * CHF + tid;
        const float* ip = s_in + c * 16 * PIN;
        #pragma unroll
        for (int kk = 0; kk < 16; kk++) {
            float w = wp[kk * 384];
            const float* sp = ip + kk * PIN;
            float4 v0 = *reinterpret_cast<const float4*>(sp);
            float4 v1 = *reinterpret_cast<const float4*>(sp + 4);
            float4 v2 = *reinterpret_cast<const float4*>(sp + 8);
            float2 v3 = *reinterpret_cast<const float2*>(sp + 12);
            acc[0]  += w * v0.x; acc[1]  += w * v0.y; acc[2]  += w * v0.z; acc[3]  += w * v0.w;
            acc[4]  += w * v1.x; acc[5]  += w * v1.y; acc[6]  += w * v1.z; acc[7]  += w * v1.w;
            acc[8]  += w * v2.x; acc[9]  += w * v2.y; acc[10] += w * v2.z; acc[11] += w * v2.w;
            acc[12] += w * v3.x; acc[13] += w * v3.y;
        }
        if (c + 1 < NC) cpa_wait0();
        __syncthreads();
    }

    float giv[ROWS];
    #pragma unroll
    for (int r = 0; r < ROWS; r++)
        giv[r] = (r < nrow) ? gi[(size_t)(b0 + r) * 384 + tid] : 0.0f;
    if (tid < GG) {
        #pragma unroll
        for (int r = 0; r < ROWS; r++) s_preA[tid * 15 + r] = acc[r] + giv[r];
        if (tid >= 2 * HH) {
            #pragma unroll
            for (int r = 0; r < ROWS; r++) s_preB[(tid - 2 * HH) * 15 + r] = giv[r];
        }
    }
    __syncthreads();

    for (int i = tid; i < ROWS * 128; i += 384) {
        int r = i >> 7;
        int j = i & 127;
        if (r >= nrow) continue;
        if (j < HH) {
            float pr = s_preA[j * 15 + r];
            float pz = s_preA[(HH + j) * 15 + r];
            float nx = s_preB[j * 15 + r];
            float nh = s_preA[(2 * HH + j) * 15 + r] - nx + bhh[2 * HH + j];
            float rg = sigf(pr);
            float zg = sigf(pz);
            float nn = tanhp(nx + rg * nh);
            float hv = s_in[j * PIN + r];
            h_out[(size_t)(b0 + r) * HS + j] = (1.0f - zg) * nn + zg * hv;
        } else {
            h_out[(size_t)(b0 + r) * HS + j] = 0.0f;
        }
    }
}

// ---------------- decoder GRU step (x from g_x) ----------------
__global__ __launch_bounds__(384, 2) void gruD_kernel(
        const float* __restrict__ h_in,
        const float* __restrict__ x,      // [row][HS]: attn 0..125, prev 126
        const float* __restrict__ W,      // [256][384]
        const float* __restrict__ gi,     // [row][384], biases folded
        const float* __restrict__ bhh,
        float* __restrict__ h_out,
        const float* __restrict__ h2oW, const float* __restrict__ h2ob,
        float* __restrict__ out) {
    constexpr int KP = 256, NC = 16, XDP = 128, CHF = 16 * 384;
    extern __shared__ float sm[];
    float* s_in   = sm;                        // 256*PIN
    float* pool   = sm + KP * PIN;             // 2*CHF
    float* s_preA = pool;
    float* s_preB = pool + GG * 15;
    float* s_out  = pool + GG * 15 + HH * 15;  // 14

    const int tid = threadIdx.x;
    const int lane = tid & 31;
    const int b0 = blockIdx.x * ROWS;
    const int nrow = min(ROWS, BB - b0);
    unsigned pool_sa = (unsigned)__cvta_generic_to_shared(pool);

    {
        const float* src = W + (size_t)tid * 4;
        #pragma unroll
        for (int v = 0; v < 4; v++)
            cpa16(pool_sa + (unsigned)(tid + 384 * v) * 16u, src + 1536 * v);
        cpa_commit();
    }
    for (int i = tid; i < 127 * ROWS; i += 384) {
        int r = i / 127, k = i % 127;
        s_in[k * PIN + r] = (r < nrow) ? x[(size_t)(b0 + r) * HS + k] : 0.0f;
    }
    if (tid < ROWS) s_in[127 * PIN + tid] = 0.0f;
    for (int i = tid; i < HH * ROWS; i += 384) {
        int r = i / HH, k = i % HH;
        s_in[(XDP + k) * PIN + r] = (r < nrow) ? h_in[(size_t)(b0 + r) * HS + k] : 0.0f;
    }
    if (tid < 2 * ROWS) {
        int k = tid / ROWS, r = tid % ROWS;
        s_in[(XDP + HH + k) * PIN + r] = 0.0f;
    }
    cpa_wait0();
    __syncthreads();

    float acc[ROWS], accx[ROWS];
    #pragma unroll
    for (int r = 0; r < ROWS; r++) { acc[r] = 0.0f; accx[r] = 0.0f; }

    for (int c = 0; c < NC; c++) {
        const int cur = c & 1;
        if (c + 1 < NC) {
            const float* src = W + (size_t)(c + 1) * CHF + (size_t)tid * 4;
            unsigned dst = pool_sa + (unsigned)((1 - cur) * CHF + tid * 4) * 4u;
            #pragma unroll
            for (int v = 0; v < 4; v++)
                cpa16(dst + (unsigned)v * 384u * 16u, src + 1536 * v);
            cpa_commit();
        }
        const float* wp = pool + cur * CHF + tid;
        const float* ip = s_in + c * 16 * PIN;
        #pragma unroll
        for (int kk = 0; kk < 16; kk++) {
            float w = wp[kk * 384];
            const float* sp = ip + kk * PIN;
            float4 v0 = *reinterpret_cast<const float4*>(sp);
            float4 v1 = *reinterpret_cast<const float4*>(sp + 4);
            float4 v2 = *reinterpret_cast<const float4*>(sp + 8);
            float2 v3 = *reinterpret_cast<const float2*>(sp + 12);
            acc[0]  += w * v0.x; acc[1]  += w * v0.y; acc[2]  += w * v0.z; acc[3]  += w * v0.w;
            acc[4]  += w * v1.x; acc[5]  += w * v1.y; acc[6]  += w * v1.z; acc[7]  += w * v1.w;
            acc[8]  += w * v2.x; acc[9]  += w * v2.y; acc[10] += w * v2.z; acc[11] += w * v2.w;
            acc[12] += w * v3.x; acc[13] += w * v3.y;
        }
        if (c == 7) {
            #pragma unroll
            for (int r = 0; r < ROWS; r++) accx[r] = acc[r];
        }
        if (c + 1 < NC) cpa_wait0();
        __syncthreads();
    }

    float giv[ROWS];
    #pragma unroll
    for (int r = 0; r < ROWS; r++)
        giv[r] = (r < nrow) ? gi[(size_t)(b0 + r) * 384 + tid] : 0.0f;
    if (tid < GG) {
        #pragma unroll
        for (int r = 0; r < ROWS; r++) s_preA[tid * 15 + r] = acc[r] + giv[r];
        if (tid >= 2 * HH) {
            #pragma unroll
            for (int r = 0; r < ROWS; r++) s_preB[(tid - 2 * HH) * 15 + r] = accx[r] + giv[r];
        }
    }
    if (tid < ROWS) s_out[tid] = 0.0f;
    __syncthreads();

    for (int i = tid; i < ROWS * 128; i += 384) {
        int r = i >> 7;
        int j = i & 127;
        float val = 0.0f;
        if (r < nrow && j < HH) {
            float pr = s_preA[j * 15 + r];
            float pz = s_preA[(HH + j) * 15 + r];
            float nx = s_preB[j * 15 + r];
            float nh = s_preA[(2 * HH + j) * 15 + r] - nx + bhh[2 * HH + j];
            float rg = sigf(pr);
            float zg = sigf(pz);
            float nn = tanhp(nx + rg * nh);
            float hv = s_in[(XDP + j) * PIN + r];
            float hnew = (1.0f - zg) * nn + zg * hv;
            h_out[(size_t)(b0 + r) * HS + j] = hnew;
            val = hnew * h2oW[j];
        }
        #pragma unroll
        for (int off = 16; off; off >>= 1) val += __shfl_down_sync(0xffffffffu, val, off);
        if (lane == 0 && r < nrow) atomicAdd(&s_out[r], val);
    }
    __syncthreads();
    if (tid < nrow) out[b0 + tid] = s_out[tid] + h2ob[0];
}

// ---------------- dense [rows x 126] @ [126 x 128] + bias; fp32 or bf16 out --
template <bool BF16OUT>
__global__ __launch_bounds__(256, 2) void lin_kernel(const float* __restrict__ in,
                                                     const float* __restrict__ Wp,
                                                     const float* __restrict__ biasp,
                                                     float* __restrict__ outf,
                                                     __nv_bfloat16* __restrict__ outb) {
    constexpr int P2 = 36;
    extern __shared__ float sm[];
    float* s_w  = sm;
    float* s_in = sm + HH * HS;
    const int tid = threadIdx.x;
    const int b0 = blockIdx.x * 32;

    {
        const float4* src = reinterpret_cast<const float4*>(Wp);
        float4* dst = reinterpret_cast<float4*>(s_w);
        for (int v = tid; v < HH * HS / 4; v += 256) dst[v] = src[v];
    }
    for (int idx = tid; idx < HH * 32; idx += 256) {
        int r = idx / HH, k = idx % HH;
        s_in[k * P2 + r] = in[(size_t)(b0 + r) * HS + k];
    }
    __syncthreads();

    const int j = tid & 127;
    const int half = tid >> 7;
    float acc[16];
    #pragma unroll
    for (int r = 0; r < 16; r++) acc[r] = 0.0f;
    #pragma unroll 2
    for (int k = 0; k < HH; k++) {
        float w = s_w[k * HS + j];
        const float4* sp = reinterpret_cast<const float4*>(s_in + k * P2 + half * 16);
        float4 v0 = sp[0], v1 = sp[1], v2 = sp[2], v3 = sp[3];
        acc[0]  += w * v0.x; acc[1]  += w * v0.y; acc[2]  += w * v0.z; acc[3]  += w * v0.w;
        acc[4]  += w * v1.x; acc[5]  += w * v1.y; acc[6]  += w * v1.z; acc[7]  += w * v1.w;
        acc[8]  += w * v2.x; acc[9]  += w * v2.y; acc[10] += w * v2.z; acc[11] += w * v2.w;
        acc[12] += w * v3.x; acc[13] += w * v3.y; acc[14] += w * v3.z; acc[15] += w * v3.w;
    }
    float bj = biasp[j];
    #pragma unroll
    for (int r = 0; r < 16; r++) {
        size_t idx = (size_t)(b0 + half * 16 + r) * HS + j;
        if (BF16OUT) outb[idx] = __float2bfloat16(acc[r] + bj);
        else         outf[idx] = acc[r] + bj;
    }
}

// ---------------- scores: bf16 Uo stream ----------------
__global__ __launch_bounds__(256) void score_kernel(
        const __nv_bfloat16* __restrict__ Uobf, const float* __restrict__ Wh,
        const float* __restrict__ Vp, const float* __restrict__ Vb,
        float* __restrict__ scores) {
    const int tid = threadIdx.x;
    const int warp = tid >> 5, lane = tid & 31;
    const int g = lane >> 3, q = lane & 7;
    const int bi = blockIdx.x & 127;
    const int t0 = (blockIdx.x >> 7) * 14;
    const int row = bi * 32 + warp * 4 + g;

    float4 wh[4], vv[4];
    #pragma unroll
    for (int m = 0; m < 4; m++) {
        wh[m] = *(reinterpret_cast<const float4*>(Wh + (size_t)row * HS) + q * 4 + m);
        vv[m] = *(reinterpret_cast<const float4*>(Vp) + q * 4 + m);
    }
    const float vb = Vb[0];

    #pragma unroll 2
    for (int t = t0; t < t0 + 14; t++) {
        const uint4* up = reinterpret_cast<const uint4*>(Uobf + ((size_t)t * BB + row) * HS);
        uint4 p0 = up[2 * q];
        uint4 p1 = up[2 * q + 1];
        float a = 0.0f;
        {
            float2 u0 = __bfloat1622float2(*reinterpret_cast<const __nv_bfloat162*>(&p0.x));
            float2 u1 = __bfloat1622float2(*reinterpret_cast<const __nv_bfloat162*>(&p0.y));
            float2 u2 = __bfloat1622float2(*reinterpret_cast<const __nv_bfloat162*>(&p0.z));
            float2 u3 = __bfloat1622float2(*reinterpret_cast<const __nv_bfloat162*>(&p0.w));
            a += tanha(u0.x + wh[0].x) * vv[0].x + tanha(u0.y + wh[0].y) * vv[0].y;
            a += tanha(u1.x + wh[0].z) * vv[0].z + tanha(u1.y + wh[0].w) * vv[0].w;
            a += tanha(u2.x + wh[1].x) * vv[1].x + tanha(u2.y + wh[1].y) * vv[1].y;
            a += tanha(u3.x + wh[1].z) * vv[1].z + tanha(u3.y + wh[1].w) * vv[1].w;
        }
        {
            float2 u0 = __bfloat1622float2(*reinterpret_cast<const __nv_bfloat162*>(&p1.x));
            float2 u1 = __bfloat1622float2(*reinterpret_cast<const __nv_bfloat162*>(&p1.y));
            float2 u2 = __bfloat1622float2(*reinterpret_cast<const __nv_bfloat162*>(&p1.z));
            float2 u3 = __bfloat1622float2(*reinterpret_cast<const __nv_bfloat162*>(&p1.w));
            a += tanha(u0.x + wh[2].x) * vv[2].x + tanha(u0.y + wh[2].y) * vv[2].y;
            a += tanha(u1.x + wh[2].z) * vv[2].z + tanha(u1.y + wh[2].w) * vv[2].w;
            a += tanha(u2.x + wh[3].x) * vv[3].x + tanha(u2.y + wh[3].y) * vv[3].y;
            a += tanha(u3.x + wh[3].z) * vv[3].z + tanha(u3.y + wh[3].w) * vv[3].w;
        }
        a += __shfl_xor_sync(0xffffffffu, a, 1);
        a += __shfl_xor_sync(0xffffffffu, a, 2);
        a += __shfl_xor_sync(0xffffffffu, a, 4);
        if (q == 0) scores[(size_t)t * BB + row] = a + vb;
    }
}

// ---------------- softmax + context + x assembly ----------------
__global__ __launch_bounds__(128) void ctx_kernel(
        const float* __restrict__ scores, const float* __restrict__ enc_out,
        const float* __restrict__ enc_data, const float* __restrict__ outbuf,
        float* __restrict__ x, int step) {
    __shared__ float sal[TT * 8];
    const int tid = threadIdx.x;
    const int warp = tid >> 5, lane = tid & 31;
    const int b0 = blockIdx.x * 8;

    if (tid < 8) {
        int b = b0 + tid;
        float mx = -1e30f;
        for (int t = 0; t < TT; t++) {
            float v = scores[(size_t)t * BB + b];
            sal[t * 8 + tid] = v;
            mx = fmaxf(mx, v);
        }
        float sum = 0.0f;
        for (int t = 0; t < TT; t++) {
            float e = ex2f((sal[t * 8 + tid] - mx) * LOG2E_);
            sal[t * 8 + tid] = e;
            sum += e;
        }
        float inv = rcpf(sum);
        for (int t = 0; t < TT; t++) sal[t * 8 + tid] *= inv;
    }
    __syncthreads();

    const int r0 = 2 * warp, r1 = r0 + 1;
    float4 a0 = {0.f, 0.f, 0.f, 0.f}, a1 = {0.f, 0.f, 0.f, 0.f};
    #pragma unroll 2
    for (int t = 0; t < TT; t++) {
        float al0 = sal[t * 8 + r0], al1 = sal[t * 8 + r1];
        float4 e0 = *(reinterpret_cast<const float4*>(enc_out + ((size_t)t * BB + b0 + r0) * HS) + lane);
        float4 e1 = *(reinterpret_cast<const float4*>(enc_out + ((size_t)t * BB + b0 + r1) * HS) + lane);
        a0.x += al0 * e0.x; a0.y += al0 * e0.y; a0.z += al0 * e0.z; a0.w += al0 * e0.w;
        a1.x += al1 * e1.x; a1.y += al1 * e1.y; a1.z += al1 * e1.z; a1.w += al1 * e1.w;
    }
    *(reinterpret_cast<float4*>(x + (size_t)(b0 + r0) * HS) + lane) = a0;
    *(reinterpret_cast<float4*>(x + (size_t)(b0 + r1) * HS) + lane) = a1;
    __syncthreads();
    if (tid < 8) {
        float prev = (step == 0) ? enc_data[((size_t)(TT - 1) * BB + b0 + tid) * ENC_]
                                 : outbuf[(size_t)(step - 1) * BB + b0 + tid];
        x[(size_t)(b0 + tid) * HS + 126] = prev;
    }
}

// ---------------- host side ----------------
extern "C" void kernel_launch(void* const* d_in, const int* in_sizes, int n_in,
                              void* d_out, int out_size) {
    const float* ann      = (const float*)d_in[0];
    const float* enc_data = (const float*)d_in[1];
    const float* dec_data = (const float*)d_in[2];
    const float* s2h_W1   = (const float*)d_in[3];
    const float* s2h_b1   = (const float*)d_in[4];
    const float* s2h_W2   = (const float*)d_in[5];
    const float* s2h_b2   = (const float*)d_in[6];
    const float* enc_Wih  = (const float*)d_in[7];
    const float* enc_Whh  = (const float*)d_in[8];
    const float* enc_bih  = (const float*)d_in[9];
    const float* enc_bhh  = (const float*)d_in[10];
    const float* dec_Wih  = (const float*)d_in[11];
    const float* dec_Whh  = (const float*)d_in[12];
    const float* dec_bih  = (const float*)d_in[13];
    const float* dec_bhh  = (const float*)d_in[14];
    const float* U_W      = (const float*)d_in[15];
    const float* U_b      = (const float*)d_in[16];
    const float* Wl_W     = (const float*)d_in[17];
    const float* Wl_b     = (const float*)d_in[18];
    const float* V_W      = (const float*)d_in[19];
    const float* V_b      = (const float*)d_in[20];
    const float* h2o_W    = (const float*)d_in[21];
    const float* h2o_b    = (const float*)d_in[22];
    float* outp = (float*)d_out;

    float *h0, *h1, *enc_out, *Wh, *scores, *x, *giE, *giD;
    float *Wenc, *Wdec, *WgiE, *WgiD, *bgE, *bgD, *UWTp, *WlTp, *Ubp, *Wlbp, *Vp;
    __nv_bfloat16* Uobf;
    cudaGetSymbolAddress((void**)&h0, g_h0);
    cudaGetSymbolAddress((void**)&h1, g_h1);
    cudaGetSymbolAddress((void**)&enc_out, g_enc_out);
    cudaGetSymbolAddress((void**)&Uobf, g_Uobf);
    cudaGetSymbolAddress((void**)&Wh, g_Wh);
    cudaGetSymbolAddress((void**)&scores, g_scores);
    cudaGetSymbolAddress((void**)&x, g_x);
    cudaGetSymbolAddress((void**)&giE, g_giE);
    cudaGetSymbolAddress((void**)&giD, g_giD);
    cudaGetSymbolAddress((void**)&Wenc, g_Wenc);
    cudaGetSymbolAddress((void**)&Wdec, g_Wdec);
    cudaGetSymbolAddress((void**)&WgiE, g_WgiE);
    cudaGetSymbolAddress((void**)&WgiD, g_WgiD);
    cudaGetSymbolAddress((void**)&bgE, g_bgE);
    cudaGetSymbolAddress((void**)&bgD, g_bgD);
    cudaGetSymbolAddress((void**)&UWTp, g_UWTp);
    cudaGetSymbolAddress((void**)&WlTp, g_WlTp);
    cudaGetSymbolAddress((void**)&Ubp, g_Ubp);
    cudaGetSymbolAddress((void**)&Wlbp, g_Wlbp);
    cudaGetSymbolAddress((void**)&Vp, g_Vp);

    const size_t sm_enc = (size_t)(128 * PIN + 2 * 16 * 384) * 4;
    const size_t sm_dec = (size_t)(256 * PIN + 2 * 16 * 384) * 4;
    const size_t sm_uo  = (size_t)(HH * HS + HH * 36) * 4;
    cudaFuncSetAttribute((const void*)gruE_kernel,
                         cudaFuncAttributeMaxDynamicSharedMemorySize, (int)sm_enc);
    cudaFuncSetAttribute((const void*)gruD_kernel,
                         cudaFuncAttributeMaxDynamicSharedMemorySize, (int)sm_dec);
    cudaFuncSetAttribute((const void*)lin_kernel<false>,
                         cudaFuncAttributeMaxDynamicSharedMemorySize, (int)sm_uo);
    cudaFuncSetAttribute((const void*)lin_kernel<true>,
                         cudaFuncAttributeMaxDynamicSharedMemorySize, (int)sm_uo);

    const int total_w = 128 * 384 + 256 * 384 + ENC_ * 384 + DEC_ * 384 + 384
                      + 2 * HH * HS + 3 * HS;
    prep_weights<<<(total_w + 255) / 256, 256>>>(enc_Wih, enc_Whh, dec_Wih, dec_Whh,
                                                 U_W, U_b, Wl_W, Wl_b, V_W,
                                                 enc_bih, enc_bhh, dec_bih, dec_bhh);

    s2h_kernel<<<BB, 128>>>(ann, s2h_W1, s2h_b1, s2h_W2, s2h_b2, h0);

    gi_kernel<ENC_><<<TT * BB / 16, 384>>>(enc_data, WgiE, bgE, giE);
    gi_kernel<DEC_><<<NSTEPS * BB / 16, 384>>>(dec_data, WgiD, bgD, giD);

    for (int t = 0; t < TT; t++) {
        const float* hin = (t == 0) ? h0 : enc_out + (size_t)(t - 1) * BB * HS;
        gruE_kernel<<<NBLK, 384, sm_enc>>>(
            hin, Wenc, giE + (size_t)t * BB * 384, enc_bhh,
            enc_out + (size_t)t * BB * HS);
    }

    // Uo in bf16 (written once, streamed 28x)
    lin_kernel<true><<<TT * BB / 32, 256, sm_uo>>>(enc_out, UWTp, Ubp, nullptr, Uobf);

    const float* enc_last = enc_out + (size_t)(TT - 1) * BB * HS;
    for (int s = 0; s < NSTEPS; s++) {
        const float* hcur = (s == 0) ? enc_last : ((s & 1) ? h0 : h1);
        float* hnext      = (s & 1) ? h1 : h0;
        lin_kernel<false><<<BB / 32, 256, sm_uo>>>(hcur, WlTp, Wlbp, Wh, nullptr);
        score_kernel<<<128 * 4, 256>>>(Uobf, Wh, Vp, V_b, scores);
        ctx_kernel<<<BB / 8, 128>>>(scores, enc_out, enc_data, outp, x, s);
        gruD_kernel<<<NBLK, 384, sm_dec>>>(
            hcur, x, Wdec, giD + (size_t)s * BB * 384, dec_bhh, hnext,
            h2o_W, h2o_b, outp + (size_t)s * BB);
    }
}

// round 11
// speedup vs baseline: 1.4816x; 1.0942x over previous
#include <cuda_runtime.h>
#include <cuda_bf16.h>
#include <cstdint>
#include <math.h>

#define BB     4096
#define TT     56
#define NSTEPS 28
#define HH     126
#define GG     378
#define ANN_   30
#define ENC_   20
#define DEC_   15

#define HS     128      // padded hidden stride
#define ROWS   14
#define NBLK   ((BB + ROWS - 1) / ROWS)   // 293
#define PIN    20       // s_in pitch

// ---------------- scratch (device globals; no allocations) ----------------
__device__ float g_h0[BB * HS];
__device__ float g_h1[BB * HS];
__device__ float g_enc_out[TT * BB * HS];
__device__ __nv_bfloat16 g_enc_bf[(size_t)TT * BB * HS];
__device__ __nv_bfloat16 g_Uobf[(size_t)TT * BB * HS];
__device__ float g_Wh[BB * HS];
__device__ float g_scores[TT * BB];
__device__ float g_x[BB * HS];                 // [attn(126), prev, pad]
__device__ float g_giE[(size_t)TT * BB * 384];
__device__ float g_giD[(size_t)NSTEPS * BB * 384];
__device__ float g_Wenc[128 * 384];
__device__ float g_Wdec[256 * 384];
__device__ float g_WgiE[ENC_ * 384];
__device__ float g_WgiD[DEC_ * 384];
__device__ float g_bgE[384];
__device__ float g_bgD[384];
__device__ float g_UWTp[HH * HS];
__device__ float g_WlTp[HH * HS];
__device__ float g_Ubp[HS];
__device__ float g_Wlbp[HS];
__device__ float g_Vp[HS];

// ---------------- fast transcendentals ----------------
__device__ __forceinline__ float ex2f(float x) { float y; asm("ex2.approx.f32 %0, %1;" : "=f"(y) : "f"(x)); return y; }
__device__ __forceinline__ float rcpf(float x) { float y; asm("rcp.approx.f32 %0, %1;" : "=f"(y) : "f"(x)); return y; }
__device__ __forceinline__ float tanha(float x) { float y; asm("tanh.approx.f32 %0, %1;" : "=f"(y) : "f"(x)); return y; }
#define LOG2E_ 1.4426950408889634f
__device__ __forceinline__ float sigf(float v)  { return rcpf(1.0f + ex2f(-v * LOG2E_)); }
__device__ __forceinline__ float tanhp(float v) { return 2.0f * rcpf(1.0f + ex2f(-2.0f * v * LOG2E_)) - 1.0f; }

// ---------------- cp.async helpers ----------------
__device__ __forceinline__ void cpa16(unsigned dst, const void* src) {
    asm volatile("cp.async.cg.shared.global [%0], [%1], 16;" :: "r"(dst), "l"(src));
}
__device__ __forceinline__ void cpa_commit() { asm volatile("cp.async.commit_group;"); }
__device__ __forceinline__ void cpa_wait0()  { asm volatile("cp.async.wait_group 0;"); }

// ---------------- weight prep ----------------
__global__ void prep_weights(const float* __restrict__ eWih, const float* __restrict__ eWhh,
                             const float* __restrict__ dWih, const float* __restrict__ dWhh,
                             const float* __restrict__ U,    const float* __restrict__ Ub,
                             const float* __restrict__ Wl,   const float* __restrict__ Wlb,
                             const float* __restrict__ V,
                             const float* __restrict__ ebih, const float* __restrict__ ebhh,
                             const float* __restrict__ dbih, const float* __restrict__ dbhh) {
    int i = blockIdx.x * 256 + threadIdx.x;
    const int Nwe = 128 * 384, Nwd = 256 * 384, Nge = ENC_ * 384, Ngd = DEC_ * 384;
    const int Nuw = HH * HS;
    if (i < Nwe) {
        int k = i / 384, j = i % 384;
        g_Wenc[i] = (j < GG && k < HH) ? eWhh[j * HH + k] : 0.0f;
        return;
    }
    i -= Nwe;
    if (i < Nwd) {
        int k = i / 384, j = i % 384;
        float v = 0.0f;
        if (j < GG) {
            if (k < 126) v = dWih[j * 142 + 16 + k];
            else if (k == 126) v = dWih[j * 142 + 0];
            else if (k >= 128 && k < 254) v = dWhh[j * HH + (k - 128)];
        }
        g_Wdec[i] = v; return;
    }
    i -= Nwd;
    if (i < Nge) {
        int k = i / 384, j = i % 384;
        g_WgiE[i] = (j < GG) ? eWih[j * ENC_ + k] : 0.0f;
        return;
    }
    i -= Nge;
    if (i < Ngd) {
        int k = i / 384, j = i % 384;
        g_WgiD[i] = (j < GG) ? dWih[j * 142 + 1 + k] : 0.0f;
        return;
    }
    i -= Ngd;
    if (i < 384) {
        g_bgE[i] = (i < GG) ? (ebih[i] + ((i < 2 * HH) ? ebhh[i] : 0.0f)) : 0.0f;
        g_bgD[i] = (i < GG) ? (dbih[i] + ((i < 2 * HH) ? dbhh[i] : 0.0f)) : 0.0f;
        return;
    }
    i -= 384;
    if (i < Nuw) { int k = i / HS, j = i % HS; g_UWTp[i] = (j < HH) ? U[j * HH + k] : 0.0f; return; }
    i -= Nuw;
    if (i < Nuw) { int k = i / HS, j = i % HS; g_WlTp[i] = (j < HH) ? Wl[j * HH + k] : 0.0f; return; }
    i -= Nuw;
    if (i < HS) { g_Ubp[i] = (i < HH) ? Ub[i] : 0.0f; return; }
    i -= HS;
    if (i < HS) { g_Wlbp[i] = (i < HH) ? Wlb[i] : 0.0f; return; }
    i -= HS;
    if (i < HS) { g_Vp[i] = (i < HH) ? V[i] : 0.0f; }
}

// ---------------- s2h MLP ----------------
__global__ void s2h_kernel(const float* __restrict__ ann,
                           const float* __restrict__ W1, const float* __restrict__ b1,
                           const float* __restrict__ W2, const float* __restrict__ b2,
                           float* __restrict__ h) {
    __shared__ float a[ANN_];
    __shared__ float mid[96];
    int b = blockIdx.x;
    int tid = threadIdx.x;
    if (tid < ANN_) a[tid] = ann[b * ANN_ + tid];
    __syncthreads();
    if (tid < 96) {
        float acc = b1[tid];
        #pragma unroll
        for (int k = 0; k < ANN_; k++) acc += W1[tid * ANN_ + k] * a[k];
        mid[tid] = fmaxf(acc, 0.0f);
    }
    __syncthreads();
    if (tid < HH) {
        float acc = b2[tid];
        #pragma unroll 4
        for (int k = 0; k < 96; k++) acc += W2[tid * 96 + k] * mid[k];
        h[(size_t)b * HS + tid] = acc;
    }
}

// ---------------- gi GEMM (bias folded) ----------------
template <int KD>
__global__ __launch_bounds__(384) void gi_kernel(const float* __restrict__ in,
                                                 const float* __restrict__ Wg,
                                                 const float* __restrict__ bg,
                                                 float* __restrict__ gi) {
    __shared__ float s_w[KD * 384];
    __shared__ float s_in[KD * 16];
    const int tid = threadIdx.x;
    const int b0 = blockIdx.x * 16;
    for (int i = tid; i < KD * 96; i += 384)
        reinterpret_cast<float4*>(s_w)[i] = reinterpret_cast<const float4*>(Wg)[i];
    for (int i = tid; i < KD * 16; i += 384) {
        int r = i / KD, k = i % KD;
        s_in[k * 16 + r] = in[(size_t)(b0 + r) * KD + k];
    }
    __syncthreads();
    float acc[16];
    #pragma unroll
    for (int r = 0; r < 16; r++) acc[r] = 0.0f;
    #pragma unroll 4
    for (int k = 0; k < KD; k++) {
        float w = s_w[k * 384 + tid];
        const float4* sp = reinterpret_cast<const float4*>(s_in + k * 16);
        float4 v0 = sp[0], v1 = sp[1], v2 = sp[2], v3 = sp[3];
        acc[0]  += w * v0.x; acc[1]  += w * v0.y; acc[2]  += w * v0.z; acc[3]  += w * v0.w;
        acc[4]  += w * v1.x; acc[5]  += w * v1.y; acc[6]  += w * v1.z; acc[7]  += w * v1.w;
        acc[8]  += w * v2.x; acc[9]  += w * v2.y; acc[10] += w * v2.z; acc[11] += w * v2.w;
        acc[12] += w * v3.x; acc[13] += w * v3.y; acc[14] += w * v3.z; acc[15] += w * v3.w;
    }
    float bb = bg[tid];
    #pragma unroll
    for (int r = 0; r < 16; r++) gi[(size_t)(b0 + r) * 384 + tid] = acc[r] + bb;
}

// ---------------- encoder GRU step ----------------
__global__ __launch_bounds__(384, 2) void gruE_kernel(
        const float* __restrict__ h_in,
        const float* __restrict__ W,      // [128][384]
        const float* __restrict__ gi,     // [row][384], biases folded
        const float* __restrict__ bhh,
        float* __restrict__ h_out,
        __nv_bfloat16* __restrict__ h_out_bf) {
    constexpr int KP = 128, NC = 8, CHF = 16 * 384;
    extern __shared__ float sm[];
    float* s_in   = sm;                        // KP*PIN
    float* pool   = sm + KP * PIN;             // 2*CHF
    float* s_gi   = pool + 2 * CHF;            // ROWS*384
    float* s_preA = pool;
    float* s_preB = pool + GG * 15;

    const int tid = threadIdx.x;
    const int b0 = blockIdx.x * ROWS;
    const int nrow = min(ROWS, BB - b0);
    unsigned pool_sa = (unsigned)__cvta_generic_to_shared(pool);
    unsigned sgi_sa  = (unsigned)__cvta_generic_to_shared(s_gi);

    // prefetch gi (contiguous rows) + weight chunk 0
    {
        const float* gsrc = gi + (size_t)b0 * 384;
        for (int idx = tid; idx < nrow * 96; idx += 384)
            cpa16(sgi_sa + (unsigned)idx * 16u, gsrc + idx * 4);
        const float* src = W + (size_t)tid * 4;
        #pragma unroll
        for (int v = 0; v < 4; v++)
            cpa16(pool_sa + (unsigned)(tid + 384 * v) * 16u, src + 1536 * v);
        cpa_commit();
    }
    for (int i = tid; i < HH * ROWS; i += 384) {
        int r = i / HH, k = i % HH;
        s_in[k * PIN + r] = (r < nrow) ? h_in[(size_t)(b0 + r) * HS + k] : 0.0f;
    }
    if (tid < 2 * ROWS) {
        int k = tid / ROWS, r = tid % ROWS;
        s_in[(HH + k) * PIN + r] = 0.0f;
    }
    cpa_wait0();
    __syncthreads();

    float acc[ROWS];
    #pragma unroll
    for (int r = 0; r < ROWS; r++) acc[r] = 0.0f;

    for (int c = 0; c < NC; c++) {
        const int cur = c & 1;
        if (c + 1 < NC) {
            const float* src = W + (size_t)(c + 1) * CHF + (size_t)tid * 4;
            unsigned dst = pool_sa + (unsigned)((1 - cur) * CHF + tid * 4) * 4u;
            #pragma unroll
            for (int v = 0; v < 4; v++)
                cpa16(dst + (unsigned)v * 384u * 16u, src + 1536 * v);
            cpa_commit();
        }
        const float* wp = pool + cur * CHF + tid;
        const float* ip = s_in + c * 16 * PIN;
        #pragma unroll
        for (int kk = 0; kk < 16; kk++) {
            float w = wp[kk * 384];
            const float* sp = ip + kk * PIN;
            float4 v0 = *reinterpret_cast<const float4*>(sp);
            float4 v1 = *reinterpret_cast<const float4*>(sp + 4);
            float4 v2 = *reinterpret_cast<const float4*>(sp + 8);
            float2 v3 = *reinterpret_cast<const float2*>(sp + 12);
            acc[0]  += w * v0.x; acc[1]  += w * v0.y; acc[2]  += w * v0.z; acc[3]  += w * v0.w;
            acc[4]  += w * v1.x; acc[5]  += w * v1.y; acc[6]  += w * v1.z; acc[7]  += w * v1.w;
            acc[8]  += w * v2.x; acc[9]  += w * v2.y; acc[10] += w * v2.z; acc[11] += w * v2.w;
            acc[12] += w * v3.x; acc[13] += w * v3.y;
        }
        if (c + 1 < NC) cpa_wait0();
        __syncthreads();
    }

    // add gi (from prefetched smem) + write preacts
    if (tid < GG) {
        #pragma unroll
        for (int r = 0; r < ROWS; r++) {
            float gv = (r < nrow) ? s_gi[r * 384 + tid] : 0.0f;
            s_preA[tid * 15 + r] = acc[r] + gv;
            if (tid >= 2 * HH) s_preB[(tid - 2 * HH) * 15 + r] = gv;
        }
    }
    __syncthreads();

    for (int i = tid; i < ROWS * 128; i += 384) {
        int r = i >> 7;
        int j = i & 127;
        if (r >= nrow) continue;
        size_t oidx = (size_t)(b0 + r) * HS + j;
        if (j < HH) {
            float pr = s_preA[j * 15 + r];
            float pz = s_preA[(HH + j) * 15 + r];
            float nx = s_preB[j * 15 + r];
            float nh = s_preA[(2 * HH + j) * 15 + r] - nx + bhh[2 * HH + j];
            float rg = sigf(pr);
            float zg = sigf(pz);
            float nn = tanhp(nx + rg * nh);
            float hv = s_in[j * PIN + r];
            float hnew = (1.0f - zg) * nn + zg * hv;
            h_out[oidx] = hnew;
            h_out_bf[oidx] = __float2bfloat16(hnew);
        } else {
            h_out[oidx] = 0.0f;
            h_out_bf[oidx] = __float2bfloat16(0.0f);
        }
    }
}

// ---------------- decoder GRU step + fused Wh for next step ----------------
__global__ __launch_bounds__(384, 2) void gruD_kernel(
        const float* __restrict__ h_in,
        const float* __restrict__ x,      // [row][HS]: attn 0..125, prev 126
        const float* __restrict__ W,      // [256][384]
        const float* __restrict__ gi,     // [row][384], biases folded
        const float* __restrict__ bhh,
        float* __restrict__ h_out,
        const float* __restrict__ h2oW, const float* __restrict__ h2ob,
        float* __restrict__ out,
        const float* __restrict__ WlTp, const float* __restrict__ Wlbp,
        float* __restrict__ Wh) {
    constexpr int KP = 256, NC = 16, XDP = 128, CHF = 16 * 384;
    extern __shared__ float sm[];
    float* s_in   = sm;                        // KP*PIN
    float* pool   = sm + KP * PIN;             // 2*CHF
    float* s_gi   = pool + 2 * CHF;            // ROWS*384
    float* s_preA = pool;
    float* s_preB = pool + GG * 15;
    float* s_out  = pool + GG * 15 + HH * 15;  // 14

    const int tid = threadIdx.x;
    const int lane = tid & 31;
    const int b0 = blockIdx.x * ROWS;
    const int nrow = min(ROWS, BB - b0);
    unsigned pool_sa = (unsigned)__cvta_generic_to_shared(pool);
    unsigned sgi_sa  = (unsigned)__cvta_generic_to_shared(s_gi);

    {
        const float* gsrc = gi + (size_t)b0 * 384;
        for (int idx = tid; idx < nrow * 96; idx += 384)
            cpa16(sgi_sa + (unsigned)idx * 16u, gsrc + idx * 4);
        const float* src = W + (size_t)tid * 4;
        #pragma unroll
        for (int v = 0; v < 4; v++)
            cpa16(pool_sa + (unsigned)(tid + 384 * v) * 16u, src + 1536 * v);
        cpa_commit();
    }
    for (int i = tid; i < 127 * ROWS; i += 384) {
        int r = i / 127, k = i % 127;
        s_in[k * PIN + r] = (r < nrow) ? x[(size_t)(b0 + r) * HS + k] : 0.0f;
    }
    if (tid < ROWS) s_in[127 * PIN + tid] = 0.0f;
    for (int i = tid; i < HH * ROWS; i += 384) {
        int r = i / HH, k = i % HH;
        s_in[(XDP + k) * PIN + r] = (r < nrow) ? h_in[(size_t)(b0 + r) * HS + k] : 0.0f;
    }
    if (tid < 2 * ROWS) {
        int k = tid / ROWS, r = tid % ROWS;
        s_in[(XDP + HH + k) * PIN + r] = 0.0f;
    }
    cpa_wait0();
    __syncthreads();

    float acc[ROWS], accx[ROWS];
    #pragma unroll
    for (int r = 0; r < ROWS; r++) { acc[r] = 0.0f; accx[r] = 0.0f; }

    for (int c = 0; c < NC; c++) {
        const int cur = c & 1;
        if (c + 1 < NC) {
            const float* src = W + (size_t)(c + 1) * CHF + (size_t)tid * 4;
            unsigned dst = pool_sa + (unsigned)((1 - cur) * CHF + tid * 4) * 4u;
            #pragma unroll
            for (int v = 0; v < 4; v++)
                cpa16(dst + (unsigned)v * 384u * 16u, src + 1536 * v);
            cpa_commit();
        }
        const float* wp = pool + cur * CHF + tid;
        const float* ip = s_in + c * 16 * PIN;
        #pragma unroll
        for (int kk = 0; kk < 16; kk++) {
            float w = wp[kk * 384];
            const float* sp = ip + kk * PIN;
            float4 v0 = *reinterpret_cast<const float4*>(sp);
            float4 v1 = *reinterpret_cast<const float4*>(sp + 4);
            float4 v2 = *reinterpret_cast<const float4*>(sp + 8);
            float2 v3 = *reinterpret_cast<const float2*>(sp + 12);
            acc[0]  += w * v0.x; acc[1]  += w * v0.y; acc[2]  += w * v0.z; acc[3]  += w * v0.w;
            acc[4]  += w * v1.x; acc[5]  += w * v1.y; acc[6]  += w * v1.z; acc[7]  += w * v1.w;
            acc[8]  += w * v2.x; acc[9]  += w * v2.y; acc[10] += w * v2.z; acc[11] += w * v2.w;
            acc[12] += w * v3.x; acc[13] += w * v3.y;
        }
        if (c == 7) {
            #pragma unroll
            for (int r = 0; r < ROWS; r++) accx[r] = acc[r];
        }
        if (c + 1 < NC) cpa_wait0();
        __syncthreads();
    }

    if (tid < GG) {
        #pragma unroll
        for (int r = 0; r < ROWS; r++) {
            float gv = (r < nrow) ? s_gi[r * 384 + tid] : 0.0f;
            s_preA[tid * 15 + r] = acc[r] + gv;
            if (tid >= 2 * HH) s_preB[(tid - 2 * HH) * 15 + r] = accx[r] + gv;
        }
    }
    if (tid < ROWS) s_out[tid] = 0.0f;
    __syncthreads();

    // gates + h2o; hnew also written back into s_in h-region for Wh GEMM
    for (int i = tid; i < ROWS * 128; i += 384) {
        int r = i >> 7;
        int j = i & 127;
        float val = 0.0f;
        if (r < nrow && j < HH) {
            float pr = s_preA[j * 15 + r];
            float pz = s_preA[(HH + j) * 15 + r];
            float nx = s_preB[j * 15 + r];
            float nh = s_preA[(2 * HH + j) * 15 + r] - nx + bhh[2 * HH + j];
            float rg = sigf(pr);
            float zg = sigf(pz);
            float nn = tanhp(nx + rg * nh);
            float hv = s_in[(XDP + j) * PIN + r];
            float hnew = (1.0f - zg) * nn + zg * hv;
            h_out[(size_t)(b0 + r) * HS + j] = hnew;
            s_in[(XDP + j) * PIN + r] = hnew;
            val = hnew * h2oW[j];
        }
        #pragma unroll
        for (int off = 16; off; off >>= 1) val += __shfl_down_sync(0xffffffffu, val, off);
        if (lane == 0 && r < nrow) atomicAdd(&s_out[r], val);
    }
    __syncthreads();
    if (tid < nrow) out[b0 + tid] = s_out[tid] + h2ob[0];

    // fused Wh for the NEXT step: Wh = hnew @ Wl^T + b
    if (tid < 256) {
        int j = tid & 127, half = tid >> 7;
        float wa[7];
        #pragma unroll
        for (int i = 0; i < 7; i++) wa[i] = 0.0f;
        #pragma unroll 2
        for (int k = 0; k < HH; k++) {
            float w = WlTp[k * HS + j];
            const float* sp = s_in + (XDP + k) * PIN + half * 7;
            #pragma unroll
            for (int i = 0; i < 7; i++) wa[i] += w * sp[i];
        }
        float bj = Wlbp[j];
        #pragma unroll
        for (int i = 0; i < 7; i++) {
            int r = half * 7 + i;
            if (r < nrow) Wh[(size_t)(b0 + r) * HS + j] = wa[i] + bj;
        }
    }
}

// ---------------- dense [rows x 126] @ [126 x 128] + bias; fp32 or bf16 out --
template <bool BF16OUT>
__global__ __launch_bounds__(256, 2) void lin_kernel(const float* __restrict__ in,
                                                     const float* __restrict__ Wp,
                                                     const float* __restrict__ biasp,
                                                     float* __restrict__ outf,
                                                     __nv_bfloat16* __restrict__ outb) {
    constexpr int P2 = 36;
    extern __shared__ float sm[];
    float* s_w  = sm;
    float* s_in = sm + HH * HS;
    const int tid = threadIdx.x;
    const int b0 = blockIdx.x * 32;

    {
        const float4* src = reinterpret_cast<const float4*>(Wp);
        float4* dst = reinterpret_cast<float4*>(s_w);
        for (int v = tid; v < HH * HS / 4; v += 256) dst[v] = src[v];
    }
    for (int idx = tid; idx < HH * 32; idx += 256) {
        int r = idx / HH, k = idx % HH;
        s_in[k * P2 + r] = in[(size_t)(b0 + r) * HS + k];
    }
    __syncthreads();

    const int j = tid & 127;
    const int half = tid >> 7;
    float acc[16];
    #pragma unroll
    for (int r = 0; r < 16; r++) acc[r] = 0.0f;
    #pragma unroll 2
    for (int k = 0; k < HH; k++) {
        float w = s_w[k * HS + j];
        const float4* sp = reinterpret_cast<const float4*>(s_in + k * P2 + half * 16);
        float4 v0 = sp[0], v1 = sp[1], v2 = sp[2], v3 = sp[3];
        acc[0]  += w * v0.x; acc[1]  += w * v0.y; acc[2]  += w * v0.z; acc[3]  += w * v0.w;
        acc[4]  += w * v1.x; acc[5]  += w * v1.y; acc[6]  += w * v1.z; acc[7]  += w * v1.w;
        acc[8]  += w * v2.x; acc[9]  += w * v2.y; acc[10] += w * v2.z; acc[11] += w * v2.w;
        acc[12] += w * v3.x; acc[13] += w * v3.y; acc[14] += w * v3.z; acc[15] += w * v3.w;
    }
    float bj = biasp[j];
    #pragma unroll
    for (int r = 0; r < 16; r++) {
        size_t idx = (size_t)(b0 + half * 16 + r) * HS + j;
        if (BF16OUT) outb[idx] = __float2bfloat16(acc[r] + bj);
        else         outf[idx] = acc[r] + bj;
    }
}

// ---------------- scores: bf16 Uo stream ----------------
__global__ __launch_bounds__(256) void score_kernel(
        const __nv_bfloat16* __restrict__ Uobf, const float* __restrict__ Wh,
        const float* __restrict__ Vp, const float* __restrict__ Vb,
        float* __restrict__ scores) {
    const int tid = threadIdx.x;
    const int warp = tid >> 5, lane = tid & 31;
    const int g = lane >> 3, q = lane & 7;
    const int bi = blockIdx.x & 127;
    const int t0 = (blockIdx.x >> 7) * 14;
    const int row = bi * 32 + warp * 4 + g;

    float4 wh[4], vv[4];
    #pragma unroll
    for (int m = 0; m < 4; m++) {
        wh[m] = *(reinterpret_cast<const float4*>(Wh + (size_t)row * HS) + q * 4 + m);
        vv[m] = *(reinterpret_cast<const float4*>(Vp) + q * 4 + m);
    }
    const float vb = Vb[0];

    #pragma unroll 2
    for (int t = t0; t < t0 + 14; t++) {
        const uint4* up = reinterpret_cast<const uint4*>(Uobf + ((size_t)t * BB + row) * HS);
        uint4 p0 = up[2 * q];
        uint4 p1 = up[2 * q + 1];
        float a = 0.0f;
        {
            float2 u0 = __bfloat1622float2(*reinterpret_cast<const __nv_bfloat162*>(&p0.x));
            float2 u1 = __bfloat1622float2(*reinterpret_cast<const __nv_bfloat162*>(&p0.y));
            float2 u2 = __bfloat1622float2(*reinterpret_cast<const __nv_bfloat162*>(&p0.z));
            float2 u3 = __bfloat1622float2(*reinterpret_cast<const __nv_bfloat162*>(&p0.w));
            a += tanha(u0.x + wh[0].x) * vv[0].x + tanha(u0.y + wh[0].y) * vv[0].y;
            a += tanha(u1.x + wh[0].z) * vv[0].z + tanha(u1.y + wh[0].w) * vv[0].w;
            a += tanha(u2.x + wh[1].x) * vv[1].x + tanha(u2.y + wh[1].y) * vv[1].y;
            a += tanha(u3.x + wh[1].z) * vv[1].z + tanha(u3.y + wh[1].w) * vv[1].w;
        }
        {
            float2 u0 = __bfloat1622float2(*reinterpret_cast<const __nv_bfloat162*>(&p1.x));
            float2 u1 = __bfloat1622float2(*reinterpret_cast<const __nv_bfloat162*>(&p1.y));
            float2 u2 = __bfloat1622float2(*reinterpret_cast<const __nv_bfloat162*>(&p1.z));
            float2 u3 = __bfloat1622float2(*reinterpret_cast<const __nv_bfloat162*>(&p1.w));
            a += tanha(u0.x + wh[2].x) * vv[2].x + tanha(u0.y + wh[2].y) * vv[2].y;
            a += tanha(u1.x + wh[2].z) * vv[2].z + tanha(u1.y + wh[2].w) * vv[2].w;
            a += tanha(u2.x + wh[3].x) * vv[3].x + tanha(u2.y + wh[3].y) * vv[3].y;
            a += tanha(u3.x + wh[3].z) * vv[3].z + tanha(u3.y + wh[3].w) * vv[3].w;
        }
        a += __shfl_xor_sync(0xffffffffu, a, 1);
        a += __shfl_xor_sync(0xffffffffu, a, 2);
        a += __shfl_xor_sync(0xffffffffu, a, 4);
        if (q == 0) scores[(size_t)t * BB + row] = a + vb;
    }
}

// ---------------- softmax + context (bf16 enc stream) + x assembly ----------
__global__ __launch_bounds__(128) void ctx_kernel(
        const float* __restrict__ scores, const __nv_bfloat16* __restrict__ encbf,
        const float* __restrict__ enc_data, const float* __restrict__ outbuf,
        float* __restrict__ x, int step) {
    __shared__ float sal[TT * 8];
    const int tid = threadIdx.x;
    const int warp = tid >> 5, lane = tid & 31;
    const int b0 = blockIdx.x * 8;

    if (tid < 8) {
        int b = b0 + tid;
        float mx = -1e30f;
        for (int t = 0; t < TT; t++) {
            float v = scores[(size_t)t * BB + b];
            sal[t * 8 + tid] = v;
            mx = fmaxf(mx, v);
        }
        float sum = 0.0f;
        for (int t = 0; t < TT; t++) {
            float e = ex2f((sal[t * 8 + tid] - mx) * LOG2E_);
            sal[t * 8 + tid] = e;
            sum += e;
        }
        float inv = rcpf(sum);
        for (int t = 0; t < TT; t++) sal[t * 8 + tid] *= inv;
    }
    __syncthreads();

    const int r0 = 2 * warp, r1 = r0 + 1;
    float4 a0 = {0.f, 0.f, 0.f, 0.f}, a1 = {0.f, 0.f, 0.f, 0.f};
    #pragma unroll 4
    for (int t = 0; t < TT; t++) {
        float al0 = sal[t * 8 + r0], al1 = sal[t * 8 + r1];
        uint2 p0 = *(reinterpret_cast<const uint2*>(encbf + ((size_t)t * BB + b0 + r0) * HS) + lane);
        uint2 p1 = *(reinterpret_cast<const uint2*>(encbf + ((size_t)t * BB + b0 + r1) * HS) + lane);
        float2 e00 = __bfloat1622float2(*reinterpret_cast<const __nv_bfloat162*>(&p0.x));
        float2 e01 = __bfloat1622float2(*reinterpret_cast<const __nv_bfloat162*>(&p0.y));
        float2 e10 = __bfloat1622float2(*reinterpret_cast<const __nv_bfloat162*>(&p1.x));
        float2 e11 = __bfloat1622float2(*reinterpret_cast<const __nv_bfloat162*>(&p1.y));
        a0.x += al0 * e00.x; a0.y += al0 * e00.y; a0.z += al0 * e01.x; a0.w += al0 * e01.y;
        a1.x += al1 * e10.x; a1.y += al1 * e10.y; a1.z += al1 * e11.x; a1.w += al1 * e11.y;
    }
    *(reinterpret_cast<float4*>(x + (size_t)(b0 + r0) * HS) + lane) = a0;
    *(reinterpret_cast<float4*>(x + (size_t)(b0 + r1) * HS) + lane) = a1;
    __syncthreads();
    if (tid < 8) {
        float prev = (step == 0) ? enc_data[((size_t)(TT - 1) * BB + b0 + tid) * ENC_]
                                 : outbuf[(size_t)(step - 1) * BB + b0 + tid];
        x[(size_t)(b0 + tid) * HS + 126] = prev;
    }
}

// ---------------- host side ----------------
extern "C" void kernel_launch(void* const* d_in, const int* in_sizes, int n_in,
                              void* d_out, int out_size) {
    const float* ann      = (const float*)d_in[0];
    const float* enc_data = (const float*)d_in[1];
    const float* dec_data = (const float*)d_in[2];
    const float* s2h_W1   = (const float*)d_in[3];
    const float* s2h_b1   = (const float*)d_in[4];
    const float* s2h_W2   = (const float*)d_in[5];
    const float* s2h_b2   = (const float*)d_in[6];
    const float* enc_Wih  = (const float*)d_in[7];
    const float* enc_Whh  = (const float*)d_in[8];
    const float* enc_bih  = (const float*)d_in[9];
    const float* enc_bhh  = (const float*)d_in[10];
    const float* dec_Wih  = (const float*)d_in[11];
    const float* dec_Whh  = (const float*)d_in[12];
    const float* dec_bih  = (const float*)d_in[13];
    const float* dec_bhh  = (const float*)d_in[14];
    const float* U_W      = (const float*)d_in[15];
    const float* U_b      = (const float*)d_in[16];
    const float* Wl_W     = (const float*)d_in[17];
    const float* Wl_b     = (const float*)d_in[18];
    const float* V_W      = (const float*)d_in[19];
    const float* V_b      = (const float*)d_in[20];
    const float* h2o_W    = (const float*)d_in[21];
    const float* h2o_b    = (const float*)d_in[22];
    float* outp = (float*)d_out;

    float *h0, *h1, *enc_out, *Wh, *scores, *x, *giE, *giD;
    float *Wenc, *Wdec, *WgiE, *WgiD, *bgE, *bgD, *UWTp, *WlTp, *Ubp, *Wlbp, *Vp;
    __nv_bfloat16 *Uobf, *encbf;
    cudaGetSymbolAddress((void**)&h0, g_h0);
    cudaGetSymbolAddress((void**)&h1, g_h1);
    cudaGetSymbolAddress((void**)&enc_out, g_enc_out);
    cudaGetSymbolAddress((void**)&encbf, g_enc_bf);
    cudaGetSymbolAddress((void**)&Uobf, g_Uobf);
    cudaGetSymbolAddress((void**)&Wh, g_Wh);
    cudaGetSymbolAddress((void**)&scores, g_scores);
    cudaGetSymbolAddress((void**)&x, g_x);
    cudaGetSymbolAddress((void**)&giE, g_giE);
    cudaGetSymbolAddress((void**)&giD, g_giD);
    cudaGetSymbolAddress((void**)&Wenc, g_Wenc);
    cudaGetSymbolAddress((void**)&Wdec, g_Wdec);
    cudaGetSymbolAddress((void**)&WgiE, g_WgiE);
    cudaGetSymbolAddress((void**)&WgiD, g_WgiD);
    cudaGetSymbolAddress((void**)&bgE, g_bgE);
    cudaGetSymbolAddress((void**)&bgD, g_bgD);
    cudaGetSymbolAddress((void**)&UWTp, g_UWTp);
    cudaGetSymbolAddress((void**)&WlTp, g_WlTp);
    cudaGetSymbolAddress((void**)&Ubp, g_Ubp);
    cudaGetSymbolAddress((void**)&Wlbp, g_Wlbp);
    cudaGetSymbolAddress((void**)&Vp, g_Vp);

    const size_t sm_enc = (size_t)(128 * PIN + 2 * 16 * 384 + ROWS * 384) * 4;  // 80896
    const size_t sm_dec = (size_t)(256 * PIN + 2 * 16 * 384 + ROWS * 384) * 4;  // 91136
    const size_t sm_uo  = (size_t)(HH * HS + HH * 36) * 4;
    cudaFuncSetAttribute((const void*)gruE_kernel,
                         cudaFuncAttributeMaxDynamicSharedMemorySize, (int)sm_enc);
    cudaFuncSetAttribute((const void*)gruD_kernel,
                         cudaFuncAttributeMaxDynamicSharedMemorySize, (int)sm_dec);
    cudaFuncSetAttribute((const void*)lin_kernel<false>,
                         cudaFuncAttributeMaxDynamicSharedMemorySize, (int)sm_uo);
    cudaFuncSetAttribute((const void*)lin_kernel<true>,
                         cudaFuncAttributeMaxDynamicSharedMemorySize, (int)sm_uo);

    const int total_w = 128 * 384 + 256 * 384 + ENC_ * 384 + DEC_ * 384 + 384
                      + 2 * HH * HS + 3 * HS;
    prep_weights<<<(total_w + 255) / 256, 256>>>(enc_Wih, enc_Whh, dec_Wih, dec_Whh,
                                                 U_W, U_b, Wl_W, Wl_b, V_W,
                                                 enc_bih, enc_bhh, dec_bih, dec_bhh);

    s2h_kernel<<<BB, 128>>>(ann, s2h_W1, s2h_b1, s2h_W2, s2h_b2, h0);

    gi_kernel<ENC_><<<TT * BB / 16, 384>>>(enc_data, WgiE, bgE, giE);
    gi_kernel<DEC_><<<NSTEPS * BB / 16, 384>>>(dec_data, WgiD, bgD, giD);

    for (int t = 0; t < TT; t++) {
        const float* hin = (t == 0) ? h0 : enc_out + (size_t)(t - 1) * BB * HS;
        gruE_kernel<<<NBLK, 384, sm_enc>>>(
            hin, Wenc, giE + (size_t)t * BB * 384, enc_bhh,
            enc_out + (size_t)t * BB * HS, encbf + (size_t)t * BB * HS);
    }

    // Uo in bf16 (written once, streamed 28x)
    lin_kernel<true><<<TT * BB / 32, 256, sm_uo>>>(enc_out, UWTp, Ubp, nullptr, Uobf);

    const float* enc_last = enc_out + (size_t)(TT - 1) * BB * HS;
    // Wh for step 0
    lin_kernel<false><<<BB / 32, 256, sm_uo>>>(enc_last, WlTp, Wlbp, Wh, nullptr);

    for (int s = 0; s < NSTEPS; s++) {
        const float* hcur = (s == 0) ? enc_last : ((s & 1) ? h0 : h1);
        float* hnext      = (s & 1) ? h1 : h0;
        score_kernel<<<128 * 4, 256>>>(Uobf, Wh, Vp, V_b, scores);
        ctx_kernel<<<BB / 8, 128>>>(scores, encbf, enc_data, outp, x, s);
        gruD_kernel<<<NBLK, 384, sm_dec>>>(
            hcur, x, Wdec, giD + (size_t)s * BB * 384, dec_bhh, hnext,
            h2o_W, h2o_b, outp + (size_t)s * BB, WlTp, Wlbp, Wh);
    }
}

// round 12
// speedup vs baseline: 1.4984x; 1.0113x over previous
#include <cuda_runtime.h>
#include <cuda_bf16.h>
#include <cstdint>
#include <math.h>

#define BB     4096
#define TT     56
#define NSTEPS 28
#define HH     126
#define GG     378
#define ANN_   30
#define ENC_   20
#define DEC_   15

#define HS     128      // padded hidden stride
#define ROWS   14
#define NBLK   ((BB + ROWS - 1) / ROWS)   // 293
#define PIN    20       // s_in pitch

// ---------------- scratch (device globals; no allocations) ----------------
__device__ float g_h0[BB * HS];
__device__ float g_h1[BB * HS];
__device__ float g_enc_out[TT * BB * HS];
__device__ __nv_bfloat16 g_enc_bf[(size_t)TT * BB * HS];
__device__ __nv_bfloat16 g_Uobf[(size_t)TT * BB * HS];
__device__ float g_Wh[BB * HS];
__device__ float g_x[BB * HS];                 // [attn(126), prev, pad]
__device__ float g_giE[(size_t)TT * BB * 384];
__device__ float g_giD[(size_t)NSTEPS * BB * 384];
__device__ float g_Wenc[128 * 384];
__device__ float g_Wdec[256 * 384];
__device__ float g_WgiE[ENC_ * 384];
__device__ float g_WgiD[DEC_ * 384];
__device__ float g_bgE[384];
__device__ float g_bgD[384];
__device__ float g_UWTp[HH * HS];
__device__ float g_WlTp[HH * HS];
__device__ float g_Ubp[HS];
__device__ float g_Wlbp[HS];
__device__ float g_Vp[HS];

// ---------------- fast transcendentals ----------------
__device__ __forceinline__ float ex2f(float x) { float y; asm("ex2.approx.f32 %0, %1;" : "=f"(y) : "f"(x)); return y; }
__device__ __forceinline__ float rcpf(float x) { float y; asm("rcp.approx.f32 %0, %1;" : "=f"(y) : "f"(x)); return y; }
__device__ __forceinline__ float tanha(float x) { float y; asm("tanh.approx.f32 %0, %1;" : "=f"(y) : "f"(x)); return y; }
#define LOG2E_ 1.4426950408889634f
__device__ __forceinline__ float sigf(float v)  { return rcpf(1.0f + ex2f(-v * LOG2E_)); }
__device__ __forceinline__ float tanhp(float v) { return 2.0f * rcpf(1.0f + ex2f(-2.0f * v * LOG2E_)) - 1.0f; }

// ---------------- cp.async helpers ----------------
__device__ __forceinline__ void cpa16(unsigned dst, const void* src) {
    asm volatile("cp.async.cg.shared.global [%0], [%1], 16;" :: "r"(dst), "l"(src));
}
__device__ __forceinline__ void cpa_commit() { asm volatile("cp.async.commit_group;"); }
__device__ __forceinline__ void cpa_wait0()  { asm volatile("cp.async.wait_group 0;"); }

// ---------------- weight prep ----------------
__global__ void prep_weights(const float* __restrict__ eWih, const float* __restrict__ eWhh,
                             const float* __restrict__ dWih, const float* __restrict__ dWhh,
                             const float* __restrict__ U,    const float* __restrict__ Ub,
                             const float* __restrict__ Wl,   const float* __restrict__ Wlb,
                             const float* __restrict__ V,
                             const float* __restrict__ ebih, const float* __restrict__ ebhh,
                             const float* __restrict__ dbih, const float* __restrict__ dbhh) {
    int i = blockIdx.x * 256 + threadIdx.x;
    const int Nwe = 128 * 384, Nwd = 256 * 384, Nge = ENC_ * 384, Ngd = DEC_ * 384;
    const int Nuw = HH * HS;
    if (i < Nwe) {
        int k = i / 384, j = i % 384;
        g_Wenc[i] = (j < GG && k < HH) ? eWhh[j * HH + k] : 0.0f;
        return;
    }
    i -= Nwe;
    if (i < Nwd) {
        int k = i / 384, j = i % 384;
        float v = 0.0f;
        if (j < GG) {
            if (k < 126) v = dWih[j * 142 + 16 + k];
            else if (k == 126) v = dWih[j * 142 + 0];
            else if (k >= 128 && k < 254) v = dWhh[j * HH + (k - 128)];
        }
        g_Wdec[i] = v; return;
    }
    i -= Nwd;
    if (i < Nge) {
        int k = i / 384, j = i % 384;
        g_WgiE[i] = (j < GG) ? eWih[j * ENC_ + k] : 0.0f;
        return;
    }
    i -= Nge;
    if (i < Ngd) {
        int k = i / 384, j = i % 384;
        g_WgiD[i] = (j < GG) ? dWih[j * 142 + 1 + k] : 0.0f;
        return;
    }
    i -= Ngd;
    if (i < 384) {
        g_bgE[i] = (i < GG) ? (ebih[i] + ((i < 2 * HH) ? ebhh[i] : 0.0f)) : 0.0f;
        g_bgD[i] = (i < GG) ? (dbih[i] + ((i < 2 * HH) ? dbhh[i] : 0.0f)) : 0.0f;
        return;
    }
    i -= 384;
    if (i < Nuw) { int k = i / HS, j = i % HS; g_UWTp[i] = (j < HH) ? U[j * HH + k] : 0.0f; return; }
    i -= Nuw;
    if (i < Nuw) { int k = i / HS, j = i % HS; g_WlTp[i] = (j < HH) ? Wl[j * HH + k] : 0.0f; return; }
    i -= Nuw;
    if (i < HS) { g_Ubp[i] = (i < HH) ? Ub[i] : 0.0f; return; }
    i -= HS;
    if (i < HS) { g_Wlbp[i] = (i < HH) ? Wlb[i] : 0.0f; return; }
    i -= HS;
    if (i < HS) { g_Vp[i] = (i < HH) ? V[i] : 0.0f; }
}

// ---------------- s2h MLP ----------------
__global__ void s2h_kernel(const float* __restrict__ ann,
                           const float* __restrict__ W1, const float* __restrict__ b1,
                           const float* __restrict__ W2, const float* __restrict__ b2,
                           float* __restrict__ h) {
    __shared__ float a[ANN_];
    __shared__ float mid[96];
    int b = blockIdx.x;
    int tid = threadIdx.x;
    if (tid < ANN_) a[tid] = ann[b * ANN_ + tid];
    __syncthreads();
    if (tid < 96) {
        float acc = b1[tid];
        #pragma unroll
        for (int k = 0; k < ANN_; k++) acc += W1[tid * ANN_ + k] * a[k];
        mid[tid] = fmaxf(acc, 0.0f);
    }
    __syncthreads();
    if (tid < HH) {
        float acc = b2[tid];
        #pragma unroll 4
        for (int k = 0; k < 96; k++) acc += W2[tid * 96 + k] * mid[k];
        h[(size_t)b * HS + tid] = acc;
    }
}

// ---------------- gi GEMM (bias folded) ----------------
template <int KD>
__global__ __launch_bounds__(384) void gi_kernel(const float* __restrict__ in,
                                                 const float* __restrict__ Wg,
                                                 const float* __restrict__ bg,
                                                 float* __restrict__ gi) {
    __shared__ float s_w[KD * 384];
    __shared__ float s_in[KD * 16];
    const int tid = threadIdx.x;
    const int b0 = blockIdx.x * 16;
    for (int i = tid; i < KD * 96; i += 384)
        reinterpret_cast<float4*>(s_w)[i] = reinterpret_cast<const float4*>(Wg)[i];
    for (int i = tid; i < KD * 16; i += 384) {
        int r = i / KD, k = i % KD;
        s_in[k * 16 + r] = in[(size_t)(b0 + r) * KD + k];
    }
    __syncthreads();
    float acc[16];
    #pragma unroll
    for (int r = 0; r < 16; r++) acc[r] = 0.0f;
    #pragma unroll 4
    for (int k = 0; k < KD; k++) {
        float w = s_w[k * 384 + tid];
        const float4* sp = reinterpret_cast<const float4*>(s_in + k * 16);
        float4 v0 = sp[0], v1 = sp[1], v2 = sp[2], v3 = sp[3];
        acc[0]  += w * v0.x; acc[1]  += w * v0.y; acc[2]  += w * v0.z; acc[3]  += w * v0.w;
        acc[4]  += w * v1.x; acc[5]  += w * v1.y; acc[6]  += w * v1.z; acc[7]  += w * v1.w;
        acc[8]  += w * v2.x; acc[9]  += w * v2.y; acc[10] += w * v2.z; acc[11] += w * v2.w;
        acc[12] += w * v3.x; acc[13] += w * v3.y; acc[14] += w * v3.z; acc[15] += w * v3.w;
    }
    float bb = bg[tid];
    #pragma unroll
    for (int r = 0; r < 16; r++) gi[(size_t)(b0 + r) * 384 + tid] = acc[r] + bb;
}

// ---------------- encoder GRU step ----------------
__global__ __launch_bounds__(384, 2) void gruE_kernel(
        const float* __restrict__ h_in,
        const float* __restrict__ W,      // [128][384]
        const float* __restrict__ gi,     // [row][384], biases folded
        const float* __restrict__ bhh,
        float* __restrict__ h_out,
        __nv_bfloat16* __restrict__ h_out_bf) {
    constexpr int KP = 128, NC = 8, CHF = 16 * 384;
    extern __shared__ float sm[];
    float* s_in   = sm;                        // KP*PIN
    float* pool   = sm + KP * PIN;             // 2*CHF
    float* s_gi   = pool + 2 * CHF;            // ROWS*384
    float* s_preA = pool;
    float* s_preB = pool + GG * 15;

    const int tid = threadIdx.x;
    const int b0 = blockIdx.x * ROWS;
    const int nrow = min(ROWS, BB - b0);
    unsigned pool_sa = (unsigned)__cvta_generic_to_shared(pool);
    unsigned sgi_sa  = (unsigned)__cvta_generic_to_shared(s_gi);

    {
        const float* gsrc = gi + (size_t)b0 * 384;
        for (int idx = tid; idx < nrow * 96; idx += 384)
            cpa16(sgi_sa + (unsigned)idx * 16u, gsrc + idx * 4);
        const float* src = W + (size_t)tid * 4;
        #pragma unroll
        for (int v = 0; v < 4; v++)
            cpa16(pool_sa + (unsigned)(tid + 384 * v) * 16u, src + 1536 * v);
        cpa_commit();
    }
    for (int i = tid; i < HH * ROWS; i += 384) {
        int r = i / HH, k = i % HH;
        s_in[k * PIN + r] = (r < nrow) ? h_in[(size_t)(b0 + r) * HS + k] : 0.0f;
    }
    if (tid < 2 * ROWS) {
        int k = tid / ROWS, r = tid % ROWS;
        s_in[(HH + k) * PIN + r] = 0.0f;
    }
    cpa_wait0();
    __syncthreads();

    float acc[ROWS];
    #pragma unroll
    for (int r = 0; r < ROWS; r++) acc[r] = 0.0f;

    for (int c = 0; c < NC; c++) {
        const int cur = c & 1;
        if (c + 1 < NC) {
            const float* src = W + (size_t)(c + 1) * CHF + (size_t)tid * 4;
            unsigned dst = pool_sa + (unsigned)((1 - cur) * CHF + tid * 4) * 4u;
            #pragma unroll
            for (int v = 0; v < 4; v++)
                cpa16(dst + (unsigned)v * 384u * 16u, src + 1536 * v);
            cpa_commit();
        }
        const float* wp = pool + cur * CHF + tid;
        const float* ip = s_in + c * 16 * PIN;
        #pragma unroll
        for (int kk = 0; kk < 16; kk++) {
            float w = wp[kk * 384];
            const float* sp = ip + kk * PIN;
            float4 v0 = *reinterpret_cast<const float4*>(sp);
            float4 v1 = *reinterpret_cast<const float4*>(sp + 4);
            float4 v2 = *reinterpret_cast<const float4*>(sp + 8);
            float2 v3 = *reinterpret_cast<const float2*>(sp + 12);
            acc[0]  += w * v0.x; acc[1]  += w * v0.y; acc[2]  += w * v0.z; acc[3]  += w * v0.w;
            acc[4]  += w * v1.x; acc[5]  += w * v1.y; acc[6]  += w * v1.z; acc[7]  += w * v1.w;
            acc[8]  += w * v2.x; acc[9]  += w * v2.y; acc[10] += w * v2.z; acc[11] += w * v2.w;
            acc[12] += w * v3.x; acc[13] += w * v3.y;
        }
        if (c + 1 < NC) cpa_wait0();
        __syncthreads();
    }

    if (tid < GG) {
        #pragma unroll
        for (int r = 0; r < ROWS; r++) {
            float gv = (r < nrow) ? s_gi[r * 384 + tid] : 0.0f;
            s_preA[tid * 15 + r] = acc[r] + gv;
            if (tid >= 2 * HH) s_preB[(tid - 2 * HH) * 15 + r] = gv;
        }
    }
    __syncthreads();

    for (int i = tid; i < ROWS * 128; i += 384) {
        int r = i >> 7;
        int j = i & 127;
        if (r >= nrow) continue;
        size_t oidx = (size_t)(b0 + r) * HS + j;
        if (j < HH) {
            float pr = s_preA[j * 15 + r];
            float pz = s_preA[(HH + j) * 15 + r];
            float nx = s_preB[j * 15 + r];
            float nh = s_preA[(2 * HH + j) * 15 + r] - nx + bhh[2 * HH + j];
            float rg = sigf(pr);
            float zg = sigf(pz);
            float nn = tanhp(nx + rg * nh);
            float hv = s_in[j * PIN + r];
            float hnew = (1.0f - zg) * nn + zg * hv;
            h_out[oidx] = hnew;
            h_out_bf[oidx] = __float2bfloat16(hnew);
        } else {
            h_out[oidx] = 0.0f;
            h_out_bf[oidx] = __float2bfloat16(0.0f);
        }
    }
}

// ---------------- decoder GRU step + fused Wh for next step ----------------
__global__ __launch_bounds__(384, 2) void gruD_kernel(
        const float* __restrict__ h_in,
        const float* __restrict__ x,      // [row][HS]: attn 0..125, prev 126
        const float* __restrict__ W,      // [256][384]
        const float* __restrict__ gi,     // [row][384], biases folded
        const float* __restrict__ bhh,
        float* __restrict__ h_out,
        const float* __restrict__ h2oW, const float* __restrict__ h2ob,
        float* __restrict__ out,
        const float* __restrict__ WlTp, const float* __restrict__ Wlbp,
        float* __restrict__ Wh) {
    constexpr int KP = 256, NC = 16, XDP = 128, CHF = 16 * 384;
    extern __shared__ float sm[];
    float* s_in   = sm;                        // KP*PIN
    float* pool   = sm + KP * PIN;             // 2*CHF
    float* s_gi   = pool + 2 * CHF;            // ROWS*384
    float* s_preA = pool;
    float* s_preB = pool + GG * 15;
    float* s_out  = pool + GG * 15 + HH * 15;  // 14

    const int tid = threadIdx.x;
    const int lane = tid & 31;
    const int b0 = blockIdx.x * ROWS;
    const int nrow = min(ROWS, BB - b0);
    unsigned pool_sa = (unsigned)__cvta_generic_to_shared(pool);
    unsigned sgi_sa  = (unsigned)__cvta_generic_to_shared(s_gi);

    {
        const float* gsrc = gi + (size_t)b0 * 384;
        for (int idx = tid; idx < nrow * 96; idx += 384)
            cpa16(sgi_sa + (unsigned)idx * 16u, gsrc + idx * 4);
        const float* src = W + (size_t)tid * 4;
        #pragma unroll
        for (int v = 0; v < 4; v++)
            cpa16(pool_sa + (unsigned)(tid + 384 * v) * 16u, src + 1536 * v);
        cpa_commit();
    }
    for (int i = tid; i < 127 * ROWS; i += 384) {
        int r = i / 127, k = i % 127;
        s_in[k * PIN + r] = (r < nrow) ? x[(size_t)(b0 + r) * HS + k] : 0.0f;
    }
    if (tid < ROWS) s_in[127 * PIN + tid] = 0.0f;
    for (int i = tid; i < HH * ROWS; i += 384) {
        int r = i / HH, k = i % HH;
        s_in[(XDP + k) * PIN + r] = (r < nrow) ? h_in[(size_t)(b0 + r) * HS + k] : 0.0f;
    }
    if (tid < 2 * ROWS) {
        int k = tid / ROWS, r = tid % ROWS;
        s_in[(XDP + HH + k) * PIN + r] = 0.0f;
    }
    cpa_wait0();
    __syncthreads();

    float acc[ROWS], accx[ROWS];
    #pragma unroll
    for (int r = 0; r < ROWS; r++) { acc[r] = 0.0f; accx[r] = 0.0f; }

    for (int c = 0; c < NC; c++) {
        const int cur = c & 1;
        if (c + 1 < NC) {
            const float* src = W + (size_t)(c + 1) * CHF + (size_t)tid * 4;
            unsigned dst = pool_sa + (unsigned)((1 - cur) * CHF + tid * 4) * 4u;
            #pragma unroll
            for (int v = 0; v < 4; v++)
                cpa16(dst + (unsigned)v * 384u * 16u, src + 1536 * v);
            cpa_commit();
        }
        const float* wp = pool + cur * CHF + tid;
        const float* ip = s_in + c * 16 * PIN;
        #pragma unroll
        for (int kk = 0; kk < 16; kk++) {
            float w = wp[kk * 384];
            const float* sp = ip + kk * PIN;
            float4 v0 = *reinterpret_cast<const float4*>(sp);
            float4 v1 = *reinterpret_cast<const float4*>(sp + 4);
            float4 v2 = *reinterpret_cast<const float4*>(sp + 8);
            float2 v3 = *reinterpret_cast<const float2*>(sp + 12);
            acc[0]  += w * v0.x; acc[1]  += w * v0.y; acc[2]  += w * v0.z; acc[3]  += w * v0.w;
            acc[4]  += w * v1.x; acc[5]  += w * v1.y; acc[6]  += w * v1.z; acc[7]  += w * v1.w;
            acc[8]  += w * v2.x; acc[9]  += w * v2.y; acc[10] += w * v2.z; acc[11] += w * v2.w;
            acc[12] += w * v3.x; acc[13] += w * v3.y;
        }
        if (c == 7) {
            #pragma unroll
            for (int r = 0; r < ROWS; r++) accx[r] = acc[r];
        }
        if (c + 1 < NC) cpa_wait0();
        __syncthreads();
    }

    if (tid < GG) {
        #pragma unroll
        for (int r = 0; r < ROWS; r++) {
            float gv = (r < nrow) ? s_gi[r * 384 + tid] : 0.0f;
            s_preA[tid * 15 + r] = acc[r] + gv;
            if (tid >= 2 * HH) s_preB[(tid - 2 * HH) * 15 + r] = accx[r] + gv;
        }
    }
    if (tid < ROWS) s_out[tid] = 0.0f;
    __syncthreads();

    // gates + h2o; hnew written back into s_in h-region for Wh GEMM
    for (int i = tid; i < ROWS * 128; i += 384) {
        int r = i >> 7;
        int j = i & 127;
        float val = 0.0f;
        if (r < nrow && j < HH) {
            float pr = s_preA[j * 15 + r];
            float pz = s_preA[(HH + j) * 15 + r];
            float nx = s_preB[j * 15 + r];
            float nh = s_preA[(2 * HH + j) * 15 + r] - nx + bhh[2 * HH + j];
            float rg = sigf(pr);
            float zg = sigf(pz);
            float nn = tanhp(nx + rg * nh);
            float hv = s_in[(XDP + j) * PIN + r];
            float hnew = (1.0f - zg) * nn + zg * hv;
            h_out[(size_t)(b0 + r) * HS + j] = hnew;
            s_in[(XDP + j) * PIN + r] = hnew;
            val = hnew * h2oW[j];
        }
        #pragma unroll
        for (int off = 16; off; off >>= 1) val += __shfl_down_sync(0xffffffffu, val, off);
        if (lane == 0 && r < nrow) atomicAdd(&s_out[r], val);
    }
    __syncthreads();
    if (tid < nrow) out[b0 + tid] = s_out[tid] + h2ob[0];

    // fused Wh for the NEXT step
    if (tid < 256) {
        int j = tid & 127, half = tid >> 7;
        float wa[7];
        #pragma unroll
        for (int i = 0; i < 7; i++) wa[i] = 0.0f;
        #pragma unroll 2
        for (int k = 0; k < HH; k++) {
            float w = WlTp[k * HS + j];
            const float* sp = s_in + (XDP + k) * PIN + half * 7;
            #pragma unroll
            for (int i = 0; i < 7; i++) wa[i] += w * sp[i];
        }
        float bj = Wlbp[j];
        #pragma unroll
        for (int i = 0; i < 7; i++) {
            int r = half * 7 + i;
            if (r < nrow) Wh[(size_t)(b0 + r) * HS + j] = wa[i] + bj;
        }
    }
}

// ---------------- dense [rows x 126] @ [126 x 128] + bias; fp32 or bf16 out --
template <bool BF16OUT>
__global__ __launch_bounds__(256, 2) void lin_kernel(const float* __restrict__ in,
                                                     const float* __restrict__ Wp,
                                                     const float* __restrict__ biasp,
                                                     float* __restrict__ outf,
                                                     __nv_bfloat16* __restrict__ outb) {
    constexpr int P2 = 36;
    extern __shared__ float sm[];
    float* s_w  = sm;
    float* s_in = sm + HH * HS;
    const int tid = threadIdx.x;
    const int b0 = blockIdx.x * 32;

    {
        const float4* src = reinterpret_cast<const float4*>(Wp);
        float4* dst = reinterpret_cast<float4*>(s_w);
        for (int v = tid; v < HH * HS / 4; v += 256) dst[v] = src[v];
    }
    for (int idx = tid; idx < HH * 32; idx += 256) {
        int r = idx / HH, k = idx % HH;
        s_in[k * P2 + r] = in[(size_t)(b0 + r) * HS + k];
    }
    __syncthreads();

    const int j = tid & 127;
    const int half = tid >> 7;
    float acc[16];
    #pragma unroll
    for (int r = 0; r < 16; r++) acc[r] = 0.0f;
    #pragma unroll 2
    for (int k = 0; k < HH; k++) {
        float w = s_w[k * HS + j];
        const float4* sp = reinterpret_cast<const float4*>(s_in + k * P2 + half * 16);
        float4 v0 = sp[0], v1 = sp[1], v2 = sp[2], v3 = sp[3];
        acc[0]  += w * v0.x; acc[1]  += w * v0.y; acc[2]  += w * v0.z; acc[3]  += w * v0.w;
        acc[4]  += w * v1.x; acc[5]  += w * v1.y; acc[6]  += w * v1.z; acc[7]  += w * v1.w;
        acc[8]  += w * v2.x; acc[9]  += w * v2.y; acc[10] += w * v2.z; acc[11] += w * v2.w;
        acc[12] += w * v3.x; acc[13] += w * v3.y; acc[14] += w * v3.z; acc[15] += w * v3.w;
    }
    float bj = biasp[j];
    #pragma unroll
    for (int r = 0; r < 16; r++) {
        size_t idx = (size_t)(b0 + half * 16 + r) * HS + j;
        if (BF16OUT) outb[idx] = __float2bfloat16(acc[r] + bj);
        else         outf[idx] = acc[r] + bj;
    }
}

// ---------------- fused attention: scores + softmax + context + x ----------
// 1024 blocks x 128 threads; warp w owns batch row b0+w end-to-end.
__global__ __launch_bounds__(128) void attn_kernel(
        const __nv_bfloat16* __restrict__ Uobf, const float* __restrict__ Wh,
        const float* __restrict__ Vp, const float* __restrict__ Vb,
        const __nv_bfloat16* __restrict__ encbf,
        const float* __restrict__ enc_data, const float* __restrict__ outbuf,
        float* __restrict__ x, int step) {
    __shared__ float sal[TT * 4];
    const int tid = threadIdx.x;
    const int warp = tid >> 5, lane = tid & 31;
    const int row = blockIdx.x * 4 + warp;

    const float4 wh = *(reinterpret_cast<const float4*>(Wh + (size_t)row * HS) + lane);
    const float4 vv = *(reinterpret_cast<const float4*>(Vp) + lane);
    const float vb = Vb[0];

    // Phase 1: scores over all t (bf16 Uo stream, 8B/lane)
    #pragma unroll 4
    for (int t = 0; t < TT; t++) {
        uint2 p = *(reinterpret_cast<const uint2*>(Uobf + ((size_t)t * BB + row) * HS) + lane);
        float2 u0 = __bfloat1622float2(*reinterpret_cast<const __nv_bfloat162*>(&p.x));
        float2 u1 = __bfloat1622float2(*reinterpret_cast<const __nv_bfloat162*>(&p.y));
        float a = tanha(u0.x + wh.x) * vv.x + tanha(u0.y + wh.y) * vv.y
                + tanha(u1.x + wh.z) * vv.z + tanha(u1.y + wh.w) * vv.w;
        #pragma unroll
        for (int off = 16; off; off >>= 1) a += __shfl_down_sync(0xffffffffu, a, off);
        if (lane == 0) sal[t * 4 + warp] = a + vb;
    }
    __syncthreads();

    // Phase 2: softmax over t (one thread per row)
    if (tid < 4) {
        float mx = -1e30f;
        for (int t = 0; t < TT; t++) mx = fmaxf(mx, sal[t * 4 + tid]);
        float sum = 0.0f;
        for (int t = 0; t < TT; t++) {
            float e = ex2f((sal[t * 4 + tid] - mx) * LOG2E_);
            sal[t * 4 + tid] = e;
            sum += e;
        }
        float inv = rcpf(sum);
        for (int t = 0; t < TT; t++) sal[t * 4 + tid] *= inv;
    }
    __syncthreads();

    // Phase 3: context (bf16 enc stream) -> x cols; lane 31 stores only 124,125
    float4 acc = {0.f, 0.f, 0.f, 0.f};
    #pragma unroll 4
    for (int t = 0; t < TT; t++) {
        float al = sal[t * 4 + warp];
        uint2 p = *(reinterpret_cast<const uint2*>(encbf + ((size_t)t * BB + row) * HS) + lane);
        float2 e0 = __bfloat1622float2(*reinterpret_cast<const __nv_bfloat162*>(&p.x));
        float2 e1 = __bfloat1622float2(*reinterpret_cast<const __nv_bfloat162*>(&p.y));
        acc.x += al * e0.x; acc.y += al * e0.y; acc.z += al * e1.x; acc.w += al * e1.y;
    }
    float* xr = x + (size_t)row * HS;
    if (lane < 31) {
        *(reinterpret_cast<float4*>(xr) + lane) = acc;
    } else {
        xr[124] = acc.x;
        xr[125] = acc.y;
    }
    if (lane == 0) {
        float prev = (step == 0) ? enc_data[((size_t)(TT - 1) * BB + row) * ENC_]
                                 : outbuf[(size_t)(step - 1) * BB + row];
        xr[126] = prev;
    }
}

// ---------------- host side ----------------
extern "C" void kernel_launch(void* const* d_in, const int* in_sizes, int n_in,
                              void* d_out, int out_size) {
    const float* ann      = (const float*)d_in[0];
    const float* enc_data = (const float*)d_in[1];
    const float* dec_data = (const float*)d_in[2];
    const float* s2h_W1   = (const float*)d_in[3];
    const float* s2h_b1   = (const float*)d_in[4];
    const float* s2h_W2   = (const float*)d_in[5];
    const float* s2h_b2   = (const float*)d_in[6];
    const float* enc_Wih  = (const float*)d_in[7];
    const float* enc_Whh  = (const float*)d_in[8];
    const float* enc_bih  = (const float*)d_in[9];
    const float* enc_bhh  = (const float*)d_in[10];
    const float* dec_Wih  = (const float*)d_in[11];
    const float* dec_Whh  = (const float*)d_in[12];
    const float* dec_bih  = (const float*)d_in[13];
    const float* dec_bhh  = (const float*)d_in[14];
    const float* U_W      = (const float*)d_in[15];
    const float* U_b      = (const float*)d_in[16];
    const float* Wl_W     = (const float*)d_in[17];
    const float* Wl_b     = (const float*)d_in[18];
    const float* V_W      = (const float*)d_in[19];
    const float* V_b      = (const float*)d_in[20];
    const float* h2o_W    = (const float*)d_in[21];
    const float* h2o_b    = (const float*)d_in[22];
    float* outp = (float*)d_out;

    float *h0, *h1, *enc_out, *Wh, *x, *giE, *giD;
    float *Wenc, *Wdec, *WgiE, *WgiD, *bgE, *bgD, *UWTp, *WlTp, *Ubp, *Wlbp, *Vp;
    __nv_bfloat16 *Uobf, *encbf;
    cudaGetSymbolAddress((void**)&h0, g_h0);
    cudaGetSymbolAddress((void**)&h1, g_h1);
    cudaGetSymbolAddress((void**)&enc_out, g_enc_out);
    cudaGetSymbolAddress((void**)&encbf, g_enc_bf);
    cudaGetSymbolAddress((void**)&Uobf, g_Uobf);
    cudaGetSymbolAddress((void**)&Wh, g_Wh);
    cudaGetSymbolAddress((void**)&x, g_x);
    cudaGetSymbolAddress((void**)&giE, g_giE);
    cudaGetSymbolAddress((void**)&giD, g_giD);
    cudaGetSymbolAddress((void**)&Wenc, g_Wenc);
    cudaGetSymbolAddress((void**)&Wdec, g_Wdec);
    cudaGetSymbolAddress((void**)&WgiE, g_WgiE);
    cudaGetSymbolAddress((void**)&WgiD, g_WgiD);
    cudaGetSymbolAddress((void**)&bgE, g_bgE);
    cudaGetSymbolAddress((void**)&bgD, g_bgD);
    cudaGetSymbolAddress((void**)&UWTp, g_UWTp);
    cudaGetSymbolAddress((void**)&WlTp, g_WlTp);
    cudaGetSymbolAddress((void**)&Ubp, g_Ubp);
    cudaGetSymbolAddress((void**)&Wlbp, g_Wlbp);
    cudaGetSymbolAddress((void**)&Vp, g_Vp);

    const size_t sm_enc = (size_t)(128 * PIN + 2 * 16 * 384 + ROWS * 384) * 4;  // 80896
    const size_t sm_dec = (size_t)(256 * PIN + 2 * 16 * 384 + ROWS * 384) * 4;  // 91136
    const size_t sm_uo  = (size_t)(HH * HS + HH * 36) * 4;
    cudaFuncSetAttribute((const void*)gruE_kernel,
                         cudaFuncAttributeMaxDynamicSharedMemorySize, (int)sm_enc);
    cudaFuncSetAttribute((const void*)gruD_kernel,
                         cudaFuncAttributeMaxDynamicSharedMemorySize, (int)sm_dec);
    cudaFuncSetAttribute((const void*)lin_kernel<false>,
                         cudaFuncAttributeMaxDynamicSharedMemorySize, (int)sm_uo);
    cudaFuncSetAttribute((const void*)lin_kernel<true>,
                         cudaFuncAttributeMaxDynamicSharedMemorySize, (int)sm_uo);

    const int total_w = 128 * 384 + 256 * 384 + ENC_ * 384 + DEC_ * 384 + 384
                      + 2 * HH * HS + 3 * HS;
    prep_weights<<<(total_w + 255) / 256, 256>>>(enc_Wih, enc_Whh, dec_Wih, dec_Whh,
                                                 U_W, U_b, Wl_W, Wl_b, V_W,
                                                 enc_bih, enc_bhh, dec_bih, dec_bhh);

    s2h_kernel<<<BB, 128>>>(ann, s2h_W1, s2h_b1, s2h_W2, s2h_b2, h0);

    gi_kernel<ENC_><<<TT * BB / 16, 384>>>(enc_data, WgiE, bgE, giE);
    gi_kernel<DEC_><<<NSTEPS * BB / 16, 384>>>(dec_data, WgiD, bgD, giD);

    for (int t = 0; t < TT; t++) {
        const float* hin = (t == 0) ? h0 : enc_out + (size_t)(t - 1) * BB * HS;
        gruE_kernel<<<NBLK, 384, sm_enc>>>(
            hin, Wenc, giE + (size_t)t * BB * 384, enc_bhh,
            enc_out + (size_t)t * BB * HS, encbf + (size_t)t * BB * HS);
    }

    // Uo in bf16 (written once, streamed 28x)
    lin_kernel<true><<<TT * BB / 32, 256, sm_uo>>>(enc_out, UWTp, Ubp, nullptr, Uobf);

    const float* enc_last = enc_out + (size_t)(TT - 1) * BB * HS;
    // Wh for step 0
    lin_kernel<false><<<BB / 32, 256, sm_uo>>>(enc_last, WlTp, Wlbp, Wh, nullptr);

    for (int s = 0; s < NSTEPS; s++) {
        const float* hcur = (s == 0) ? enc_last : ((s & 1) ? h0 : h1);
        float* hnext      = (s & 1) ? h1 : h0;
        attn_kernel<<<BB / 4, 128>>>(Uobf, Wh, Vp, V_b, encbf, enc_data, outp, x, s);
        gruD_kernel<<<NBLK, 384, sm_dec>>>(
            hcur, x, Wdec, giD + (size_t)s * BB * 384, dec_bhh, hnext,
            h2o_W, h2o_b, outp + (size_t)s * BB, WlTp, Wlbp, Wh);
    }
}

// round 13
// speedup vs baseline: 1.5239x; 1.0170x over previous
#include <cuda_runtime.h>
#include <cuda_bf16.h>
#include <cstdint>
#include <math.h>

#define BB     4096
#define TT     56
#define NSTEPS 28
#define HH     126
#define GG     378
#define ANN_   30
#define ENC_   20
#define DEC_   15

#define HS     128      // padded hidden stride
#define ROWS   14
#define NBLK   ((BB + ROWS - 1) / ROWS)   // 293
#define PIN    20       // s_in pitch

// ---------------- scratch (device globals; no allocations) ----------------
__device__ float g_h0[BB * HS];
__device__ float g_h1[BB * HS];
__device__ float g_enc_out[TT * BB * HS];
__device__ __nv_bfloat16 g_enc_bf[(size_t)TT * BB * HS];
__device__ __nv_bfloat16 g_Uobf[(size_t)TT * BB * HS];
__device__ float g_Wh[BB * HS];
__device__ float g_x[BB * HS];                 // [attn(126), prev, pad]
__device__ float g_giE[(size_t)TT * BB * 384];
__device__ float g_giD[(size_t)NSTEPS * BB * 384];
__device__ float g_Wenc[128 * 384];
__device__ float g_Wdec[256 * 384];
__device__ float g_WgiE[ENC_ * 384];
__device__ float g_WgiD[DEC_ * 384];
__device__ float g_bgE[384];
__device__ float g_bgD[384];
__device__ float g_UWTp[HH * HS];
__device__ float g_WlTp[HH * HS];
__device__ float g_Ubp[HS];
__device__ float g_Wlbp[HS];
__device__ float g_Vp[HS];

// ---------------- fast transcendentals ----------------
__device__ __forceinline__ float ex2f(float x) { float y; asm("ex2.approx.f32 %0, %1;" : "=f"(y) : "f"(x)); return y; }
__device__ __forceinline__ float rcpf(float x) { float y; asm("rcp.approx.f32 %0, %1;" : "=f"(y) : "f"(x)); return y; }
__device__ __forceinline__ float tanha(float x) { float y; asm("tanh.approx.f32 %0, %1;" : "=f"(y) : "f"(x)); return y; }
#define LOG2E_ 1.4426950408889634f
__device__ __forceinline__ float sigf(float v)  { return rcpf(1.0f + ex2f(-v * LOG2E_)); }
__device__ __forceinline__ float tanhp(float v) { return 2.0f * rcpf(1.0f + ex2f(-2.0f * v * LOG2E_)) - 1.0f; }

// ---------------- packed f32x2 FMA (Blackwell FFMA2, PTX-only) --------------
__device__ __forceinline__ unsigned long long dupf(float w) {
    unsigned long long r; asm("mov.b64 %0, {%1, %1};" : "=l"(r) : "f"(w)); return r;
}
__device__ __forceinline__ void fma2(unsigned long long& d, unsigned long long a, unsigned long long b) {
    asm("fma.rn.f32x2 %0, %1, %2, %0;" : "+l"(d) : "l"(a), "l"(b));
}
__device__ __forceinline__ float2 unpk(unsigned long long v) {
    float2 f; asm("mov.b64 {%0, %1}, %2;" : "=f"(f.x), "=f"(f.y) : "l"(v)); return f;
}

// ---------------- cp.async helpers ----------------
__device__ __forceinline__ void cpa16(unsigned dst, const void* src) {
    asm volatile("cp.async.cg.shared.global [%0], [%1], 16;" :: "r"(dst), "l"(src));
}
__device__ __forceinline__ void cpa_commit() { asm volatile("cp.async.commit_group;"); }
__device__ __forceinline__ void cpa_wait0()  { asm volatile("cp.async.wait_group 0;"); }

// ---------------- weight prep ----------------
__global__ void prep_weights(const float* __restrict__ eWih, const float* __restrict__ eWhh,
                             const float* __restrict__ dWih, const float* __restrict__ dWhh,
                             const float* __restrict__ U,    const float* __restrict__ Ub,
                             const float* __restrict__ Wl,   const float* __restrict__ Wlb,
                             const float* __restrict__ V,
                             const float* __restrict__ ebih, const float* __restrict__ ebhh,
                             const float* __restrict__ dbih, const float* __restrict__ dbhh) {
    int i = blockIdx.x * 256 + threadIdx.x;
    const int Nwe = 128 * 384, Nwd = 256 * 384, Nge = ENC_ * 384, Ngd = DEC_ * 384;
    const int Nuw = HH * HS;
    if (i < Nwe) {
        int k = i / 384, j = i % 384;
        g_Wenc[i] = (j < GG && k < HH) ? eWhh[j * HH + k] : 0.0f;
        return;
    }
    i -= Nwe;
    if (i < Nwd) {
        int k = i / 384, j = i % 384;
        float v = 0.0f;
        if (j < GG) {
            if (k < 126) v = dWih[j * 142 + 16 + k];
            else if (k == 126) v = dWih[j * 142 + 0];
            else if (k >= 128 && k < 254) v = dWhh[j * HH + (k - 128)];
        }
        g_Wdec[i] = v; return;
    }
    i -= Nwd;
    if (i < Nge) {
        int k = i / 384, j = i % 384;
        g_WgiE[i] = (j < GG) ? eWih[j * ENC_ + k] : 0.0f;
        return;
    }
    i -= Nge;
    if (i < Ngd) {
        int k = i / 384, j = i % 384;
        g_WgiD[i] = (j < GG) ? dWih[j * 142 + 1 + k] : 0.0f;
        return;
    }
    i -= Ngd;
    if (i < 384) {
        g_bgE[i] = (i < GG) ? (ebih[i] + ((i < 2 * HH) ? ebhh[i] : 0.0f)) : 0.0f;
        g_bgD[i] = (i < GG) ? (dbih[i] + ((i < 2 * HH) ? dbhh[i] : 0.0f)) : 0.0f;
        return;
    }
    i -= 384;
    if (i < Nuw) { int k = i / HS, j = i % HS; g_UWTp[i] = (j < HH) ? U[j * HH + k] : 0.0f; return; }
    i -= Nuw;
    if (i < Nuw) { int k = i / HS, j = i % HS; g_WlTp[i] = (j < HH) ? Wl[j * HH + k] : 0.0f; return; }
    i -= Nuw;
    if (i < HS) { g_Ubp[i] = (i < HH) ? Ub[i] : 0.0f; return; }
    i -= HS;
    if (i < HS) { g_Wlbp[i] = (i < HH) ? Wlb[i] : 0.0f; return; }
    i -= HS;
    if (i < HS) { g_Vp[i] = (i < HH) ? V[i] : 0.0f; }
}

// ---------------- s2h MLP ----------------
__global__ void s2h_kernel(const float* __restrict__ ann,
                           const float* __restrict__ W1, const float* __restrict__ b1,
                           const float* __restrict__ W2, const float* __restrict__ b2,
                           float* __restrict__ h) {
    __shared__ float a[ANN_];
    __shared__ float mid[96];
    int b = blockIdx.x;
    int tid = threadIdx.x;
    if (tid < ANN_) a[tid] = ann[b * ANN_ + tid];
    __syncthreads();
    if (tid < 96) {
        float acc = b1[tid];
        #pragma unroll
        for (int k = 0; k < ANN_; k++) acc += W1[tid * ANN_ + k] * a[k];
        mid[tid] = fmaxf(acc, 0.0f);
    }
    __syncthreads();
    if (tid < HH) {
        float acc = b2[tid];
        #pragma unroll 4
        for (int k = 0; k < 96; k++) acc += W2[tid * 96 + k] * mid[k];
        h[(size_t)b * HS + tid] = acc;
    }
}

// ---------------- gi GEMM (bias folded, f32x2) ----------------
template <int KD>
__global__ __launch_bounds__(384) void gi_kernel(const float* __restrict__ in,
                                                 const float* __restrict__ Wg,
                                                 const float* __restrict__ bg,
                                                 float* __restrict__ gi) {
    __shared__ float s_w[KD * 384];
    __shared__ float s_in[KD * 16];
    const int tid = threadIdx.x;
    const int b0 = blockIdx.x * 16;
    for (int i = tid; i < KD * 96; i += 384)
        reinterpret_cast<float4*>(s_w)[i] = reinterpret_cast<const float4*>(Wg)[i];
    for (int i = tid; i < KD * 16; i += 384) {
        int r = i / KD, k = i % KD;
        s_in[k * 16 + r] = in[(size_t)(b0 + r) * KD + k];
    }
    __syncthreads();
    unsigned long long accp[8];
    #pragma unroll
    for (int p = 0; p < 8; p++) accp[p] = dupf(0.0f);
    #pragma unroll 4
    for (int k = 0; k < KD; k++) {
        unsigned long long wd = dupf(s_w[k * 384 + tid]);
        const ulonglong2* sp2 = reinterpret_cast<const ulonglong2*>(s_in + k * 16);
        ulonglong2 q0 = sp2[0], q1 = sp2[1], q2 = sp2[2], q3 = sp2[3];
        fma2(accp[0], wd, q0.x); fma2(accp[1], wd, q0.y);
        fma2(accp[2], wd, q1.x); fma2(accp[3], wd, q1.y);
        fma2(accp[4], wd, q2.x); fma2(accp[5], wd, q2.y);
        fma2(accp[6], wd, q3.x); fma2(accp[7], wd, q3.y);
    }
    float bb = bg[tid];
    #pragma unroll
    for (int p = 0; p < 8; p++) {
        float2 f = unpk(accp[p]);
        gi[(size_t)(b0 + 2 * p) * 384 + tid]     = f.x + bb;
        gi[(size_t)(b0 + 2 * p + 1) * 384 + tid] = f.y + bb;
    }
}

// ---------------- encoder GRU step (f32x2 GEMM) ----------------
__global__ __launch_bounds__(384, 2) void gruE_kernel(
        const float* __restrict__ h_in,
        const float* __restrict__ W,      // [128][384]
        const float* __restrict__ gi,     // [row][384], biases folded
        const float* __restrict__ bhh,
        float* __restrict__ h_out,
        __nv_bfloat16* __restrict__ h_out_bf) {
    constexpr int KP = 128, NC = 8, CHF = 16 * 384;
    extern __shared__ float sm[];
    float* s_in   = sm;                        // KP*PIN
    float* pool   = sm + KP * PIN;             // 2*CHF
    float* s_gi   = pool + 2 * CHF;            // ROWS*384
    float* s_preA = pool;
    float* s_preB = pool + GG * 15;

    const int tid = threadIdx.x;
    const int b0 = blockIdx.x * ROWS;
    const int nrow = min(ROWS, BB - b0);
    unsigned pool_sa = (unsigned)__cvta_generic_to_shared(pool);
    unsigned sgi_sa  = (unsigned)__cvta_generic_to_shared(s_gi);

    {
        const float* gsrc = gi + (size_t)b0 * 384;
        for (int idx = tid; idx < nrow * 96; idx += 384)
            cpa16(sgi_sa + (unsigned)idx * 16u, gsrc + idx * 4);
        const float* src = W + (size_t)tid * 4;
        #pragma unroll
        for (int v = 0; v < 4; v++)
            cpa16(pool_sa + (unsigned)(tid + 384 * v) * 16u, src + 1536 * v);
        cpa_commit();
    }
    for (int i = tid; i < HH * ROWS; i += 384) {
        int r = i / HH, k = i % HH;
        s_in[k * PIN + r] = (r < nrow) ? h_in[(size_t)(b0 + r) * HS + k] : 0.0f;
    }
    if (tid < 2 * ROWS) {
        int k = tid / ROWS, r = tid % ROWS;
        s_in[(HH + k) * PIN + r] = 0.0f;
    }
    cpa_wait0();
    __syncthreads();

    unsigned long long accp[7];
    #pragma unroll
    for (int p = 0; p < 7; p++) accp[p] = dupf(0.0f);

    for (int c = 0; c < NC; c++) {
        const int cur = c & 1;
        if (c + 1 < NC) {
            const float* src = W + (size_t)(c + 1) * CHF + (size_t)tid * 4;
            unsigned dst = pool_sa + (unsigned)((1 - cur) * CHF + tid * 4) * 4u;
            #pragma unroll
            for (int v = 0; v < 4; v++)
                cpa16(dst + (unsigned)v * 384u * 16u, src + 1536 * v);
            cpa_commit();
        }
        const float* wp = pool + cur * CHF + tid;
        const float* ip = s_in + c * 16 * PIN;
        #pragma unroll
        for (int kk = 0; kk < 16; kk++) {
            unsigned long long wd = dupf(wp[kk * 384]);
            const float* sp = ip + kk * PIN;
            const ulonglong2* sp2 = reinterpret_cast<const ulonglong2*>(sp);
            ulonglong2 q0 = sp2[0], q1 = sp2[1], q2 = sp2[2];
            unsigned long long q3 = *reinterpret_cast<const unsigned long long*>(sp + 12);
            fma2(accp[0], wd, q0.x); fma2(accp[1], wd, q0.y);
            fma2(accp[2], wd, q1.x); fma2(accp[3], wd, q1.y);
            fma2(accp[4], wd, q2.x); fma2(accp[5], wd, q2.y);
            fma2(accp[6], wd, q3);
        }
        if (c + 1 < NC) cpa_wait0();
        __syncthreads();
    }

    if (tid < GG) {
        float acc[ROWS];
        #pragma unroll
        for (int p = 0; p < 7; p++) {
            float2 f = unpk(accp[p]);
            acc[2 * p] = f.x; acc[2 * p + 1] = f.y;
        }
        #pragma unroll
        for (int r = 0; r < ROWS; r++) {
            float gv = (r < nrow) ? s_gi[r * 384 + tid] : 0.0f;
            s_preA[tid * 15 + r] = acc[r] + gv;
            if (tid >= 2 * HH) s_preB[(tid - 2 * HH) * 15 + r] = gv;
        }
    }
    __syncthreads();

    for (int i = tid; i < ROWS * 128; i += 384) {
        int r = i >> 7;
        int j = i & 127;
        if (r >= nrow) continue;
        size_t oidx = (size_t)(b0 + r) * HS + j;
        if (j < HH) {
            float pr = s_preA[j * 15 + r];
            float pz = s_preA[(HH + j) * 15 + r];
            float nx = s_preB[j * 15 + r];
            float nh = s_preA[(2 * HH + j) * 15 + r] - nx + bhh[2 * HH + j];
            float rg = sigf(pr);
            float zg = sigf(pz);
            float nn = tanhp(nx + rg * nh);
            float hv = s_in[j * PIN + r];
            float hnew = (1.0f - zg) * nn + zg * hv;
            h_out[oidx] = hnew;
            h_out_bf[oidx] = __float2bfloat16(hnew);
        } else {
            h_out[oidx] = 0.0f;
            h_out_bf[oidx] = __float2bfloat16(0.0f);
        }
    }
}

// ---------------- decoder GRU step (f32x2 GEMM) + fused Wh ----------------
__global__ __launch_bounds__(384, 2) void gruD_kernel(
        const float* __restrict__ h_in,
        const float* __restrict__ x,      // [row][HS]: attn 0..125, prev 126
        const float* __restrict__ W,      // [256][384]
        const float* __restrict__ gi,     // [row][384], biases folded
        const float* __restrict__ bhh,
        float* __restrict__ h_out,
        const float* __restrict__ h2oW, const float* __restrict__ h2ob,
        float* __restrict__ out,
        const float* __restrict__ WlTp, const float* __restrict__ Wlbp,
        float* __restrict__ Wh) {
    constexpr int KP = 256, NC = 16, XDP = 128, CHF = 16 * 384;
    extern __shared__ float sm[];
    float* s_in   = sm;                        // KP*PIN
    float* pool   = sm + KP * PIN;             // 2*CHF
    float* s_gi   = pool + 2 * CHF;            // ROWS*384
    float* s_preA = pool;
    float* s_preB = pool + GG * 15;
    float* s_out  = pool + GG * 15 + HH * 15;  // 14

    const int tid = threadIdx.x;
    const int lane = tid & 31;
    const int b0 = blockIdx.x * ROWS;
    const int nrow = min(ROWS, BB - b0);
    unsigned pool_sa = (unsigned)__cvta_generic_to_shared(pool);
    unsigned sgi_sa  = (unsigned)__cvta_generic_to_shared(s_gi);

    {
        const float* gsrc = gi + (size_t)b0 * 384;
        for (int idx = tid; idx < nrow * 96; idx += 384)
            cpa16(sgi_sa + (unsigned)idx * 16u, gsrc + idx * 4);
        const float* src = W + (size_t)tid * 4;
        #pragma unroll
        for (int v = 0; v < 4; v++)
            cpa16(pool_sa + (unsigned)(tid + 384 * v) * 16u, src + 1536 * v);
        cpa_commit();
    }
    for (int i = tid; i < 127 * ROWS; i += 384) {
        int r = i / 127, k = i % 127;
        s_in[k * PIN + r] = (r < nrow) ? x[(size_t)(b0 + r) * HS + k] : 0.0f;
    }
    if (tid < ROWS) s_in[127 * PIN + tid] = 0.0f;
    for (int i = tid; i < HH * ROWS; i += 384) {
        int r = i / HH, k = i % HH;
        s_in[(XDP + k) * PIN + r] = (r < nrow) ? h_in[(size_t)(b0 + r) * HS + k] : 0.0f;
    }
    if (tid < 2 * ROWS) {
        int k = tid / ROWS, r = tid % ROWS;
        s_in[(XDP + HH + k) * PIN + r] = 0.0f;
    }
    cpa_wait0();
    __syncthreads();

    unsigned long long accp[7], accxp[7];
    #pragma unroll
    for (int p = 0; p < 7; p++) { accp[p] = dupf(0.0f); accxp[p] = dupf(0.0f); }

    for (int c = 0; c < NC; c++) {
        const int cur = c & 1;
        if (c + 1 < NC) {
            const float* src = W + (size_t)(c + 1) * CHF + (size_t)tid * 4;
            unsigned dst = pool_sa + (unsigned)((1 - cur) * CHF + tid * 4) * 4u;
            #pragma unroll
            for (int v = 0; v < 4; v++)
                cpa16(dst + (unsigned)v * 384u * 16u, src + 1536 * v);
            cpa_commit();
        }
        const float* wp = pool + cur * CHF + tid;
        const float* ip = s_in + c * 16 * PIN;
        #pragma unroll
        for (int kk = 0; kk < 16; kk++) {
            unsigned long long wd = dupf(wp[kk * 384]);
            const float* sp = ip + kk * PIN;
            const ulonglong2* sp2 = reinterpret_cast<const ulonglong2*>(sp);
            ulonglong2 q0 = sp2[0], q1 = sp2[1], q2 = sp2[2];
            unsigned long long q3 = *reinterpret_cast<const unsigned long long*>(sp + 12);
            fma2(accp[0], wd, q0.x); fma2(accp[1], wd, q0.y);
            fma2(accp[2], wd, q1.x); fma2(accp[3], wd, q1.y);
            fma2(accp[4], wd, q2.x); fma2(accp[5], wd, q2.y);
            fma2(accp[6], wd, q3);
        }
        if (c == 7) {
            #pragma unroll
            for (int p = 0; p < 7; p++) accxp[p] = accp[p];
        }
        if (c + 1 < NC) cpa_wait0();
        __syncthreads();
    }

    if (tid < GG) {
        float acc[ROWS], accx[ROWS];
        #pragma unroll
        for (int p = 0; p < 7; p++) {
            float2 f = unpk(accp[p]);
            acc[2 * p] = f.x; acc[2 * p + 1] = f.y;
            float2 g = unpk(accxp[p]);
            accx[2 * p] = g.x; accx[2 * p + 1] = g.y;
        }
        #pragma unroll
        for (int r = 0; r < ROWS; r++) {
            float gv = (r < nrow) ? s_gi[r * 384 + tid] : 0.0f;
            s_preA[tid * 15 + r] = acc[r] + gv;
            if (tid >= 2 * HH) s_preB[(tid - 2 * HH) * 15 + r] = accx[r] + gv;
        }
    }
    if (tid < ROWS) s_out[tid] = 0.0f;
    __syncthreads();

    // gates + h2o; hnew written back into s_in h-region for Wh GEMM
    for (int i = tid; i < ROWS * 128; i += 384) {
        int r = i >> 7;
        int j = i & 127;
        float val = 0.0f;
        if (r < nrow && j < HH) {
            float pr = s_preA[j * 15 + r];
            float pz = s_preA[(HH + j) * 15 + r];
            float nx = s_preB[j * 15 + r];
            float nh = s_preA[(2 * HH + j) * 15 + r] - nx + bhh[2 * HH + j];
            float rg = sigf(pr);
            float zg = sigf(pz);
            float nn = tanhp(nx + rg * nh);
            float hv = s_in[(XDP + j) * PIN + r];
            float hnew = (1.0f - zg) * nn + zg * hv;
            h_out[(size_t)(b0 + r) * HS + j] = hnew;
            s_in[(XDP + j) * PIN + r] = hnew;
            val = hnew * h2oW[j];
        }
        #pragma unroll
        for (int off = 16; off; off >>= 1) val += __shfl_down_sync(0xffffffffu, val, off);
        if (lane == 0 && r < nrow) atomicAdd(&s_out[r], val);
    }
    __syncthreads();
    if (tid < nrow) out[b0 + tid] = s_out[tid] + h2ob[0];

    // fused Wh for the NEXT step
    if (tid < 256) {
        int j = tid & 127, half = tid >> 7;
        float wa[7];
        #pragma unroll
        for (int i = 0; i < 7; i++) wa[i] = 0.0f;
        #pragma unroll 2
        for (int k = 0; k < HH; k++) {
            float w = WlTp[k * HS + j];
            const float* sp = s_in + (XDP + k) * PIN + half * 7;
            #pragma unroll
            for (int i = 0; i < 7; i++) wa[i] += w * sp[i];
        }
        float bj = Wlbp[j];
        #pragma unroll
        for (int i = 0; i < 7; i++) {
            int r = half * 7 + i;
            if (r < nrow) Wh[(size_t)(b0 + r) * HS + j] = wa[i] + bj;
        }
    }
}

// ---------------- dense [rows x 126] @ [126 x 128] + bias (f32x2) ----------
template <bool BF16OUT>
__global__ __launch_bounds__(256, 2) void lin_kernel(const float* __restrict__ in,
                                                     const float* __restrict__ Wp,
                                                     const float* __restrict__ biasp,
                                                     float* __restrict__ outf,
                                                     __nv_bfloat16* __restrict__ outb) {
    constexpr int P2 = 36;
    extern __shared__ float sm[];
    float* s_w  = sm;
    float* s_in = sm + HH * HS;
    const int tid = threadIdx.x;
    const int b0 = blockIdx.x * 32;

    {
        const float4* src = reinterpret_cast<const float4*>(Wp);
        float4* dst = reinterpret_cast<float4*>(s_w);
        for (int v = tid; v < HH * HS / 4; v += 256) dst[v] = src[v];
    }
    for (int idx = tid; idx < HH * 32; idx += 256) {
        int r = idx / HH, k = idx % HH;
        s_in[k * P2 + r] = in[(size_t)(b0 + r) * HS + k];
    }
    __syncthreads();

    const int j = tid & 127;
    const int half = tid >> 7;
    unsigned long long accp[8];
    #pragma unroll
    for (int p = 0; p < 8; p++) accp[p] = dupf(0.0f);
    #pragma unroll 2
    for (int k = 0; k < HH; k++) {
        unsigned long long wd = dupf(s_w[k * HS + j]);
        const ulonglong2* sp2 = reinterpret_cast<const ulonglong2*>(s_in + k * P2 + half * 16);
        ulonglong2 q0 = sp2[0], q1 = sp2[1], q2 = sp2[2], q3 = sp2[3];
        fma2(accp[0], wd, q0.x); fma2(accp[1], wd, q0.y);
        fma2(accp[2], wd, q1.x); fma2(accp[3], wd, q1.y);
        fma2(accp[4], wd, q2.x); fma2(accp[5], wd, q2.y);
        fma2(accp[6], wd, q3.x); fma2(accp[7], wd, q3.y);
    }
    float bj = biasp[j];
    #pragma unroll
    for (int p = 0; p < 8; p++) {
        float2 f = unpk(accp[p]);
        size_t i0 = (size_t)(b0 + half * 16 + 2 * p) * HS + j;
        size_t i1 = (size_t)(b0 + half * 16 + 2 * p + 1) * HS + j;
        if (BF16OUT) {
            outb[i0] = __float2bfloat16(f.x + bj);
            outb[i1] = __float2bfloat16(f.y + bj);
        } else {
            outf[i0] = f.x + bj;
            outf[i1] = f.y + bj;
        }
    }
}

// ---------------- fused attention: scores + softmax + context + x ----------
__global__ __launch_bounds__(128) void attn_kernel(
        const __nv_bfloat16* __restrict__ Uobf, const float* __restrict__ Wh,
        const float* __restrict__ Vp, const float* __restrict__ Vb,
        const __nv_bfloat16* __restrict__ encbf,
        const float* __restrict__ enc_data, const float* __restrict__ outbuf,
        float* __restrict__ x, int step) {
    __shared__ float sal[TT * 4];
    const int tid = threadIdx.x;
    const int warp = tid >> 5, lane = tid & 31;
    const int row = blockIdx.x * 4 + warp;

    const float4 wh = *(reinterpret_cast<const float4*>(Wh + (size_t)row * HS) + lane);
    const float4 vv = *(reinterpret_cast<const float4*>(Vp) + lane);
    const float vb = Vb[0];

    #pragma unroll 4
    for (int t = 0; t < TT; t++) {
        uint2 p = *(reinterpret_cast<const uint2*>(Uobf + ((size_t)t * BB + row) * HS) + lane);
        float2 u0 = __bfloat1622float2(*reinterpret_cast<const __nv_bfloat162*>(&p.x));
        float2 u1 = __bfloat1622float2(*reinterpret_cast<const __nv_bfloat162*>(&p.y));
        float a = tanha(u0.x + wh.x) * vv.x + tanha(u0.y + wh.y) * vv.y
                + tanha(u1.x + wh.z) * vv.z + tanha(u1.y + wh.w) * vv.w;
        #pragma unroll
        for (int off = 16; off; off >>= 1) a += __shfl_down_sync(0xffffffffu, a, off);
        if (lane == 0) sal[t * 4 + warp] = a + vb;
    }
    __syncthreads();

    if (tid < 4) {
        float mx = -1e30f;
        for (int t = 0; t < TT; t++) mx = fmaxf(mx, sal[t * 4 + tid]);
        float sum = 0.0f;
        for (int t = 0; t < TT; t++) {
            float e = ex2f((sal[t * 4 + tid] - mx) * LOG2E_);
            sal[t * 4 + tid] = e;
            sum += e;
        }
        float inv = rcpf(sum);
        for (int t = 0; t < TT; t++) sal[t * 4 + tid] *= inv;
    }
    __syncthreads();

    float4 acc = {0.f, 0.f, 0.f, 0.f};
    #pragma unroll 4
    for (int t = 0; t < TT; t++) {
        float al = sal[t * 4 + warp];
        uint2 p = *(reinterpret_cast<const uint2*>(encbf + ((size_t)t * BB + row) * HS) + lane);
        float2 e0 = __bfloat1622float2(*reinterpret_cast<const __nv_bfloat162*>(&p.x));
        float2 e1 = __bfloat1622float2(*reinterpret_cast<const __nv_bfloat162*>(&p.y));
        acc.x += al * e0.x; acc.y += al * e0.y; acc.z += al * e1.x; acc.w += al * e1.y;
    }
    float* xr = x + (size_t)row * HS;
    if (lane < 31) {
        *(reinterpret_cast<float4*>(xr) + lane) = acc;
    } else {
        xr[124] = acc.x;
        xr[125] = acc.y;
    }
    if (lane == 0) {
        float prev = (step == 0) ? enc_data[((size_t)(TT - 1) * BB + row) * ENC_]
                                 : outbuf[(size_t)(step - 1) * BB + row];
        xr[126] = prev;
    }
}

// ---------------- host side ----------------
extern "C" void kernel_launch(void* const* d_in, const int* in_sizes, int n_in,
                              void* d_out, int out_size) {
    const float* ann      = (const float*)d_in[0];
    const float* enc_data = (const float*)d_in[1];
    const float* dec_data = (const float*)d_in[2];
    const float* s2h_W1   = (const float*)d_in[3];
    const float* s2h_b1   = (const float*)d_in[4];
    const float* s2h_W2   = (const float*)d_in[5];
    const float* s2h_b2   = (const float*)d_in[6];
    const float* enc_Wih  = (const float*)d_in[7];
    const float* enc_Whh  = (const float*)d_in[8];
    const float* enc_bih  = (const float*)d_in[9];
    const float* enc_bhh  = (const float*)d_in[10];
    const float* dec_Wih  = (const float*)d_in[11];
    const float* dec_Whh  = (const float*)d_in[12];
    const float* dec_bih  = (const float*)d_in[13];
    const float* dec_bhh  = (const float*)d_in[14];
    const float* U_W      = (const float*)d_in[15];
    const float* U_b      = (const float*)d_in[16];
    const float* Wl_W     = (const float*)d_in[17];
    const float* Wl_b     = (const float*)d_in[18];
    const float* V_W      = (const float*)d_in[19];
    const float* V_b      = (const float*)d_in[20];
    const float* h2o_W    = (const float*)d_in[21];
    const float* h2o_b    = (const float*)d_in[22];
    float* outp = (float*)d_out;

    float *h0, *h1, *enc_out, *Wh, *x, *giE, *giD;
    float *Wenc, *Wdec, *WgiE, *WgiD, *bgE, *bgD, *UWTp, *WlTp, *Ubp, *Wlbp, *Vp;
    __nv_bfloat16 *Uobf, *encbf;
    cudaGetSymbolAddress((void**)&h0, g_h0);
    cudaGetSymbolAddress((void**)&h1, g_h1);
    cudaGetSymbolAddress((void**)&enc_out, g_enc_out);
    cudaGetSymbolAddress((void**)&encbf, g_enc_bf);
    cudaGetSymbolAddress((void**)&Uobf, g_Uobf);
    cudaGetSymbolAddress((void**)&Wh, g_Wh);
    cudaGetSymbolAddress((void**)&x, g_x);
    cudaGetSymbolAddress((void**)&giE, g_giE);
    cudaGetSymbolAddress((void**)&giD, g_giD);
    cudaGetSymbolAddress((void**)&Wenc, g_Wenc);
    cudaGetSymbolAddress((void**)&Wdec, g_Wdec);
    cudaGetSymbolAddress((void**)&WgiE, g_WgiE);
    cudaGetSymbolAddress((void**)&WgiD, g_WgiD);
    cudaGetSymbolAddress((void**)&bgE, g_bgE);
    cudaGetSymbolAddress((void**)&bgD, g_bgD);
    cudaGetSymbolAddress((void**)&UWTp, g_UWTp);
    cudaGetSymbolAddress((void**)&WlTp, g_WlTp);
    cudaGetSymbolAddress((void**)&Ubp, g_Ubp);
    cudaGetSymbolAddress((void**)&Wlbp, g_Wlbp);
    cudaGetSymbolAddress((void**)&Vp, g_Vp);

    const size_t sm_enc = (size_t)(128 * PIN + 2 * 16 * 384 + ROWS * 384) * 4;  // 80896
    const size_t sm_dec = (size_t)(256 * PIN + 2 * 16 * 384 + ROWS * 384) * 4;  // 91136
    const size_t sm_uo  = (size_t)(HH * HS + HH * 36) * 4;
    cudaFuncSetAttribute((const void*)gruE_kernel,
                         cudaFuncAttributeMaxDynamicSharedMemorySize, (int)sm_enc);
    cudaFuncSetAttribute((const void*)gruD_kernel,
                         cudaFuncAttributeMaxDynamicSharedMemorySize, (int)sm_dec);
    cudaFuncSetAttribute((const void*)lin_kernel<false>,
                         cudaFuncAttributeMaxDynamicSharedMemorySize, (int)sm_uo);
    cudaFuncSetAttribute((const void*)lin_kernel<true>,
                         cudaFuncAttributeMaxDynamicSharedMemorySize, (int)sm_uo);

    const int total_w = 128 * 384 + 256 * 384 + ENC_ * 384 + DEC_ * 384 + 384
                      + 2 * HH * HS + 3 * HS;
    prep_weights<<<(total_w + 255) / 256, 256>>>(enc_Wih, enc_Whh, dec_Wih, dec_Whh,
                                                 U_W, U_b, Wl_W, Wl_b, V_W,
                                                 enc_bih, enc_bhh, dec_bih, dec_bhh);

    s2h_kernel<<<BB, 128>>>(ann, s2h_W1, s2h_b1, s2h_W2, s2h_b2, h0);

    gi_kernel<ENC_><<<TT * BB / 16, 384>>>(enc_data, WgiE, bgE, giE);
    gi_kernel<DEC_><<<NSTEPS * BB / 16, 384>>>(dec_data, WgiD, bgD, giD);

    for (int t = 0; t < TT; t++) {
        const float* hin = (t == 0) ? h0 : enc_out + (size_t)(t - 1) * BB * HS;
        gruE_kernel<<<NBLK, 384, sm_enc>>>(
            hin, Wenc, giE + (size_t)t * BB * 384, enc_bhh,
            enc_out + (size_t)t * BB * HS, encbf + (size_t)t * BB * HS);
    }

    // Uo in bf16 (written once, streamed 28x)
    lin_kernel<true><<<TT * BB / 32, 256, sm_uo>>>(enc_out, UWTp, Ubp, nullptr, Uobf);

    const float* enc_last = enc_out + (size_t)(TT - 1) * BB * HS;
    // Wh for step 0
    lin_kernel<false><<<BB / 32, 256, sm_uo>>>(enc_last, WlTp, Wlbp, Wh, nullptr);

    for (int s = 0; s < NSTEPS; s++) {
        const float* hcur = (s == 0) ? enc_last : ((s & 1) ? h0 : h1);
        float* hnext      = (s & 1) ? h1 : h0;
        attn_kernel<<<BB / 4, 128>>>(Uobf, Wh, Vp, V_b, encbf, enc_data, outp, x, s);
        gruD_kernel<<<NBLK, 384, sm_dec>>>(
            hcur, x, Wdec, giD + (size_t)s * BB * 384, dec_bhh, hnext,
            h2o_W, h2o_b, outp + (size_t)s * BB, WlTp, Wlbp, Wh);
    }
}

// round 14
// speedup vs baseline: 1.5420x; 1.0119x over previous
#include <cuda_runtime.h>
#include <cuda_bf16.h>
#include <cstdint>
#include <math.h>

#define BB     4096
#define TT     56
#define NSTEPS 28
#define HH     126
#define GG     378
#define ANN_   30
#define ENC_   20
#define DEC_   15

#define HS     128      // padded hidden stride
#define ROWS   14
#define NBLK   ((BB + ROWS - 1) / ROWS)   // 293

// ---------------- scratch (device globals; no allocations) ----------------
__device__ float g_h0[BB * HS];
__device__ float g_h1[BB * HS];
__device__ float g_enc_out[TT * BB * HS];
__device__ __nv_bfloat16 g_enc_bf[(size_t)TT * BB * HS];
__device__ __nv_bfloat16 g_Uobf[(size_t)TT * BB * HS];
__device__ float g_Wh[BB * HS];
__device__ float g_x[BB * HS];
__device__ float g_giE[(size_t)TT * BB * 384];
__device__ float g_giD[(size_t)NSTEPS * BB * 384];
__device__ float g_Wenc[128 * 384];
__device__ float g_Wdec[256 * 384];
__device__ float g_WgiE[ENC_ * 384];
__device__ float g_WgiD[DEC_ * 384];
__device__ float g_bgE[384];
__device__ float g_bgD[384];
__device__ float g_UWTp[HH * HS];
__device__ float g_WlTp[HH * HS];
__device__ float g_Ubp[HS];
__device__ float g_Wlbp[HS];
__device__ float g_Vp[HS];

// ---------------- fast transcendentals ----------------
__device__ __forceinline__ float ex2f(float x) { float y; asm("ex2.approx.f32 %0, %1;" : "=f"(y) : "f"(x)); return y; }
__device__ __forceinline__ float rcpf(float x) { float y; asm("rcp.approx.f32 %0, %1;" : "=f"(y) : "f"(x)); return y; }
__device__ __forceinline__ float tanha(float x) { float y; asm("tanh.approx.f32 %0, %1;" : "=f"(y) : "f"(x)); return y; }
#define LOG2E_ 1.4426950408889634f
__device__ __forceinline__ float sigf(float v)  { return rcpf(1.0f + ex2f(-v * LOG2E_)); }
__device__ __forceinline__ float tanhp(float v) { return 2.0f * rcpf(1.0f + ex2f(-2.0f * v * LOG2E_)) - 1.0f; }

// ---------------- packed f32x2 FMA ----------------
__device__ __forceinline__ unsigned long long dupf(float w) {
    unsigned long long r; asm("mov.b64 %0, {%1, %1};" : "=l"(r) : "f"(w)); return r;
}
__device__ __forceinline__ void fma2(unsigned long long& d, unsigned long long a, unsigned long long b) {
    asm("fma.rn.f32x2 %0, %1, %2, %0;" : "+l"(d) : "l"(a), "l"(b));
}
__device__ __forceinline__ float2 unpk(unsigned long long v) {
    float2 f; asm("mov.b64 {%0, %1}, %2;" : "=f"(f.x), "=f"(f.y) : "l"(v)); return f;
}

// ---------------- cp.async helpers ----------------
__device__ __forceinline__ void cpa16(unsigned dst, const void* src) {
    asm volatile("cp.async.cg.shared.global [%0], [%1], 16;" :: "r"(dst), "l"(src));
}
__device__ __forceinline__ void cpa_commit() { asm volatile("cp.async.commit_group;"); }
__device__ __forceinline__ void cpa_wait0()  { asm volatile("cp.async.wait_group 0;"); }

// ---------------- weight prep ----------------
__global__ void prep_weights(const float* __restrict__ eWih, const float* __restrict__ eWhh,
                             const float* __restrict__ dWih, const float* __restrict__ dWhh,
                             const float* __restrict__ U,    const float* __restrict__ Ub,
                             const float* __restrict__ Wl,   const float* __restrict__ Wlb,
                             const float* __restrict__ V,
                             const float* __restrict__ ebih, const float* __restrict__ ebhh,
                             const float* __restrict__ dbih, const float* __restrict__ dbhh) {
    int i = blockIdx.x * 256 + threadIdx.x;
    const int Nwe = 128 * 384, Nwd = 256 * 384, Nge = ENC_ * 384, Ngd = DEC_ * 384;
    const int Nuw = HH * HS;
    if (i < Nwe) {
        int k = i / 384, j = i % 384;
        g_Wenc[i] = (j < GG && k < HH) ? eWhh[j * HH + k] : 0.0f;
        return;
    }
    i -= Nwe;
    if (i < Nwd) {
        int k = i / 384, j = i % 384;
        float v = 0.0f;
        if (j < GG) {
            if (k < 126) v = dWih[j * 142 + 16 + k];
            else if (k == 126) v = dWih[j * 142 + 0];
            else if (k >= 128 && k < 254) v = dWhh[j * HH + (k - 128)];
        }
        g_Wdec[i] = v; return;
    }
    i -= Nwd;
    if (i < Nge) {
        int k = i / 384, j = i % 384;
        g_WgiE[i] = (j < GG) ? eWih[j * ENC_ + k] : 0.0f;
        return;
    }
    i -= Nge;
    if (i < Ngd) {
        int k = i / 384, j = i % 384;
        g_WgiD[i] = (j < GG) ? dWih[j * 142 + 1 + k] : 0.0f;
        return;
    }
    i -= Ngd;
    if (i < 384) {
        g_bgE[i] = (i < GG) ? (ebih[i] + ((i < 2 * HH) ? ebhh[i] : 0.0f)) : 0.0f;
        g_bgD[i] = (i < GG) ? (dbih[i] + ((i < 2 * HH) ? dbhh[i] : 0.0f)) : 0.0f;
        return;
    }
    i -= 384;
    if (i < Nuw) { int k = i / HS, j = i % HS; g_UWTp[i] = (j < HH) ? U[j * HH + k] : 0.0f; return; }
    i -= Nuw;
    if (i < Nuw) { int k = i / HS, j = i % HS; g_WlTp[i] = (j < HH) ? Wl[j * HH + k] : 0.0f; return; }
    i -= Nuw;
    if (i < HS) { g_Ubp[i] = (i < HH) ? Ub[i] : 0.0f; return; }
    i -= HS;
    if (i < HS) { g_Wlbp[i] = (i < HH) ? Wlb[i] : 0.0f; return; }
    i -= HS;
    if (i < HS) { g_Vp[i] = (i < HH) ? V[i] : 0.0f; }
}

// ---------------- s2h MLP ----------------
__global__ void s2h_kernel(const float* __restrict__ ann,
                           const float* __restrict__ W1, const float* __restrict__ b1,
                           const float* __restrict__ W2, const float* __restrict__ b2,
                           float* __restrict__ h) {
    __shared__ float a[ANN_];
    __shared__ float mid[96];
    int b = blockIdx.x;
    int tid = threadIdx.x;
    if (tid < ANN_) a[tid] = ann[b * ANN_ + tid];
    __syncthreads();
    if (tid < 96) {
        float acc = b1[tid];
        #pragma unroll
        for (int k = 0; k < ANN_; k++) acc += W1[tid * ANN_ + k] * a[k];
        mid[tid] = fmaxf(acc, 0.0f);
    }
    __syncthreads();
    if (tid < HH) {
        float acc = b2[tid];
        #pragma unroll 4
        for (int k = 0; k < 96; k++) acc += W2[tid * 96 + k] * mid[k];
        h[(size_t)b * HS + tid] = acc;
    }
}

// ---------------- gi GEMM (bias folded, f32x2) ----------------
template <int KD>
__global__ __launch_bounds__(384) void gi_kernel(const float* __restrict__ in,
                                                 const float* __restrict__ Wg,
                                                 const float* __restrict__ bg,
                                                 float* __restrict__ gi) {
    __shared__ float s_w[KD * 384];
    __shared__ float s_in[KD * 16];
    const int tid = threadIdx.x;
    const int b0 = blockIdx.x * 16;
    for (int i = tid; i < KD * 96; i += 384)
        reinterpret_cast<float4*>(s_w)[i] = reinterpret_cast<const float4*>(Wg)[i];
    for (int i = tid; i < KD * 16; i += 384) {
        int r = i / KD, k = i % KD;
        s_in[k * 16 + r] = in[(size_t)(b0 + r) * KD + k];
    }
    __syncthreads();
    unsigned long long accp[8];
    #pragma unroll
    for (int p = 0; p < 8; p++) accp[p] = dupf(0.0f);
    #pragma unroll 4
    for (int k = 0; k < KD; k++) {
        unsigned long long wd = dupf(s_w[k * 384 + tid]);
        const ulonglong2* sp2 = reinterpret_cast<const ulonglong2*>(s_in + k * 16);
        ulonglong2 q0 = sp2[0], q1 = sp2[1], q2 = sp2[2], q3 = sp2[3];
        fma2(accp[0], wd, q0.x); fma2(accp[1], wd, q0.y);
        fma2(accp[2], wd, q1.x); fma2(accp[3], wd, q1.y);
        fma2(accp[4], wd, q2.x); fma2(accp[5], wd, q2.y);
        fma2(accp[6], wd, q3.x); fma2(accp[7], wd, q3.y);
    }
    float bb = bg[tid];
    #pragma unroll
    for (int p = 0; p < 8; p++) {
        float2 f = unpk(accp[p]);
        gi[(size_t)(b0 + 2 * p) * 384 + tid]     = f.x + bb;
        gi[(size_t)(b0 + 2 * p + 1) * 384 + tid] = f.y + bb;
    }
}

// ---------------- encoder GRU step: 192 thr, 2 cols/thread ----------------
__global__ __launch_bounds__(192, 2) void gruE_kernel(
        const float* __restrict__ h_in,
        const float* __restrict__ W,      // [128][384]
        const float* __restrict__ gi,     // [row][384], biases folded
        const float* __restrict__ bhh,
        float* __restrict__ h_out,
        __nv_bfloat16* __restrict__ h_out_bf) {
    constexpr int KP = 128, NC = 8, CHF = 16 * 384;
    extern __shared__ float sm[];
    float* s_in   = sm;                        // 128*16
    float* pool   = sm + KP * 16;              // 2*CHF
    float* s_gi   = pool + 2 * CHF;            // ROWS*384
    float* s_preA = pool;
    float* s_preB = pool + GG * 15;

    const int tid = threadIdx.x;
    const int b0 = blockIdx.x * ROWS;
    const int nrow = min(ROWS, BB - b0);
    unsigned pool_sa = (unsigned)__cvta_generic_to_shared(pool);
    unsigned sgi_sa  = (unsigned)__cvta_generic_to_shared(s_gi);

    {
        const float* gsrc = gi + (size_t)b0 * 384;
        for (int idx = tid; idx < nrow * 96; idx += 192)
            cpa16(sgi_sa + (unsigned)idx * 16u, gsrc + idx * 4);
        #pragma unroll
        for (int v = 0; v < 8; v++) {
            int u = tid + 192 * v;
            cpa16(pool_sa + (unsigned)u * 16u, W + (size_t)u * 4);
        }
        cpa_commit();
    }
    for (int i = tid; i < HH * ROWS; i += 192) {
        int r = i / HH, k = i % HH;
        s_in[k * 16 + r] = (r < nrow) ? h_in[(size_t)(b0 + r) * HS + k] : 0.0f;
    }
    for (int i = tid; i < 2 * 16; i += 192)
        s_in[HH * 16 + i] = 0.0f;   // pad k=126,127 (covers r pads too)
    for (int i = tid; i < HH; i += 192) {
        #pragma unroll
        for (int r = nrow; r < ROWS; r++) ;   // nrow==ROWS except last block
    }
    if (nrow < ROWS) {
        for (int i = tid; i < HH * (ROWS - nrow); i += 192) {
            int k = i / (ROWS - nrow), r = nrow + i % (ROWS - nrow);
            s_in[k * 16 + r] = 0.0f;
        }
    }
    cpa_wait0();
    __syncthreads();

    unsigned long long a0[7], a1[7];
    #pragma unroll
    for (int p = 0; p < 7; p++) { a0[p] = dupf(0.0f); a1[p] = dupf(0.0f); }

    for (int c = 0; c < NC; c++) {
        const int cur = c & 1;
        if (c + 1 < NC) {
            const float* base = W + (size_t)(c + 1) * CHF;
            unsigned dstb = pool_sa + (unsigned)(1 - cur) * CHF * 4u;
            #pragma unroll
            for (int v = 0; v < 8; v++) {
                int u = tid + 192 * v;
                cpa16(dstb + (unsigned)u * 16u, base + (size_t)u * 4);
            }
            cpa_commit();
        }
        const float* wp = pool + cur * CHF + tid;
        const float* ip = s_in + c * 16 * 16;
        #pragma unroll
        for (int kk = 0; kk < 16; kk++) {
            unsigned long long w0 = dupf(wp[kk * 384]);
            unsigned long long w1 = dupf(wp[kk * 384 + 192]);
            const float* sp = ip + kk * 16;
            const ulonglong2* sp2 = reinterpret_cast<const ulonglong2*>(sp);
            ulonglong2 q0 = sp2[0], q1 = sp2[1], q2 = sp2[2];
            unsigned long long q3 = *reinterpret_cast<const unsigned long long*>(sp + 12);
            fma2(a0[0], w0, q0.x); fma2(a0[1], w0, q0.y);
            fma2(a0[2], w0, q1.x); fma2(a0[3], w0, q1.y);
            fma2(a0[4], w0, q2.x); fma2(a0[5], w0, q2.y);
            fma2(a0[6], w0, q3);
            fma2(a1[0], w1, q0.x); fma2(a1[1], w1, q0.y);
            fma2(a1[2], w1, q1.x); fma2(a1[3], w1, q1.y);
            fma2(a1[4], w1, q2.x); fma2(a1[5], w1, q2.y);
            fma2(a1[6], w1, q3);
        }
        if (c + 1 < NC) cpa_wait0();
        __syncthreads();
    }

    {
        const int c0 = tid, c1 = tid + 192;
        float f0[ROWS], f1[ROWS];
        #pragma unroll
        for (int p = 0; p < 7; p++) {
            float2 u = unpk(a0[p]); f0[2*p] = u.x; f0[2*p+1] = u.y;
            float2 v = unpk(a1[p]); f1[2*p] = v.x; f1[2*p+1] = v.y;
        }
        #pragma unroll
        for (int r = 0; r < ROWS; r++) {
            float gv0 = s_gi[r * 384 + c0];
            s_preA[c0 * 15 + r] = f0[r] + gv0;
        }
        if (c1 < GG) {
            #pragma unroll
            for (int r = 0; r < ROWS; r++) {
                float gv1 = s_gi[r * 384 + c1];
                s_preA[c1 * 15 + r] = f1[r] + gv1;
                if (c1 >= 2 * HH) s_preB[(c1 - 2 * HH) * 15 + r] = gv1;
            }
        }
    }
    __syncthreads();

    for (int i = tid; i < ROWS * 128; i += 192) {
        int r = i >> 7;
        int j = i & 127;
        if (r >= nrow) continue;
        size_t oidx = (size_t)(b0 + r) * HS + j;
        if (j < HH) {
            float pr = s_preA[j * 15 + r];
            float pz = s_preA[(HH + j) * 15 + r];
            float nx = s_preB[j * 15 + r];
            float nh = s_preA[(2 * HH + j) * 15 + r] - nx + bhh[2 * HH + j];
            float rg = sigf(pr);
            float zg = sigf(pz);
            float nn = tanhp(nx + rg * nh);
            float hv = s_in[j * 16 + r];
            float hnew = (1.0f - zg) * nn + zg * hv;
            h_out[oidx] = hnew;
            h_out_bf[oidx] = __float2bfloat16(hnew);
        } else {
            h_out[oidx] = 0.0f;
            h_out_bf[oidx] = __float2bfloat16(0.0f);
        }
    }
}

// ---------------- decoder GRU step: 192 thr, 2 cols/thread + fused Wh -------
__global__ __launch_bounds__(192, 2) void gruD_kernel(
        const float* __restrict__ h_in,
        const float* __restrict__ x,
        const float* __restrict__ W,      // [256][384]
        const float* __restrict__ gi,
        const float* __restrict__ bhh,
        float* __restrict__ h_out,
        const float* __restrict__ h2oW, const float* __restrict__ h2ob,
        float* __restrict__ out,
        const float* __restrict__ WlTp, const float* __restrict__ Wlbp,
        float* __restrict__ Wh) {
    constexpr int KP = 256, NC = 16, XDP = 128, CHF = 16 * 384;
    extern __shared__ float sm[];
    float* s_in   = sm;                        // 256*16
    float* pool   = sm + KP * 16;              // 2*CHF
    float* s_gi   = pool + 2 * CHF;            // ROWS*384
    float* s_preA = pool;
    float* s_preB = pool + GG * 15;
    float* s_out  = pool + GG * 15 + HH * 15;  // 14

    const int tid = threadIdx.x;
    const int lane = tid & 31;
    const int b0 = blockIdx.x * ROWS;
    const int nrow = min(ROWS, BB - b0);
    unsigned pool_sa = (unsigned)__cvta_generic_to_shared(pool);
    unsigned sgi_sa  = (unsigned)__cvta_generic_to_shared(s_gi);

    {
        const float* gsrc = gi + (size_t)b0 * 384;
        for (int idx = tid; idx < nrow * 96; idx += 192)
            cpa16(sgi_sa + (unsigned)idx * 16u, gsrc + idx * 4);
        #pragma unroll
        for (int v = 0; v < 8; v++) {
            int u = tid + 192 * v;
            cpa16(pool_sa + (unsigned)u * 16u, W + (size_t)u * 4);
        }
        cpa_commit();
    }
    for (int i = tid; i < 127 * ROWS; i += 192) {
        int r = i / 127, k = i % 127;
        s_in[k * 16 + r] = (r < nrow) ? x[(size_t)(b0 + r) * HS + k] : 0.0f;
    }
    for (int i = tid; i < 16; i += 192) s_in[127 * 16 + i] = 0.0f;
    for (int i = tid; i < HH * ROWS; i += 192) {
        int r = i / HH, k = i % HH;
        s_in[(XDP + k) * 16 + r] = (r < nrow) ? h_in[(size_t)(b0 + r) * HS + k] : 0.0f;
    }
    for (int i = tid; i < 2 * 16; i += 192) s_in[(XDP + HH) * 16 + i] = 0.0f;
    if (nrow < ROWS) {
        for (int i = tid; i < 127 * (ROWS - nrow); i += 192) {
            int k = i / (ROWS - nrow), r = nrow + i % (ROWS - nrow);
            s_in[k * 16 + r] = 0.0f;
        }
    }
    cpa_wait0();
    __syncthreads();

    unsigned long long a0[7], a1[7], ax1[7];
    #pragma unroll
    for (int p = 0; p < 7; p++) { a0[p] = dupf(0.0f); a1[p] = dupf(0.0f); ax1[p] = dupf(0.0f); }

    for (int c = 0; c < NC; c++) {
        const int cur = c & 1;
        if (c + 1 < NC) {
            const float* base = W + (size_t)(c + 1) * CHF;
            unsigned dstb = pool_sa + (unsigned)(1 - cur) * CHF * 4u;
            #pragma unroll
            for (int v = 0; v < 8; v++) {
                int u = tid + 192 * v;
                cpa16(dstb + (unsigned)u * 16u, base + (size_t)u * 4);
            }
            cpa_commit();
        }
        const float* wp = pool + cur * CHF + tid;
        const float* ip = s_in + c * 16 * 16;
        #pragma unroll
        for (int kk = 0; kk < 16; kk++) {
            unsigned long long w0 = dupf(wp[kk * 384]);
            unsigned long long w1 = dupf(wp[kk * 384 + 192]);
            const float* sp = ip + kk * 16;
            const ulonglong2* sp2 = reinterpret_cast<const ulonglong2*>(sp);
            ulonglong2 q0 = sp2[0], q1 = sp2[1], q2 = sp2[2];
            unsigned long long q3 = *reinterpret_cast<const unsigned long long*>(sp + 12);
            fma2(a0[0], w0, q0.x); fma2(a0[1], w0, q0.y);
            fma2(a0[2], w0, q1.x); fma2(a0[3], w0, q1.y);
            fma2(a0[4], w0, q2.x); fma2(a0[5], w0, q2.y);
            fma2(a0[6], w0, q3);
            fma2(a1[0], w1, q0.x); fma2(a1[1], w1, q0.y);
            fma2(a1[2], w1, q1.x); fma2(a1[3], w1, q1.y);
            fma2(a1[4], w1, q2.x); fma2(a1[5], w1, q2.y);
            fma2(a1[6], w1, q3);
        }
        if (c == 7) {
            #pragma unroll
            for (int p = 0; p < 7; p++) ax1[p] = a1[p];   // only col1 can be n-gate
        }
        if (c + 1 < NC) cpa_wait0();
        __syncthreads();
    }

    {
        const int c0 = tid, c1 = tid + 192;
        float f0[ROWS], f1[ROWS], fx1[ROWS];
        #pragma unroll
        for (int p = 0; p < 7; p++) {
            float2 u = unpk(a0[p]); f0[2*p] = u.x; f0[2*p+1] = u.y;
            float2 v = unpk(a1[p]); f1[2*p] = v.x; f1[2*p+1] = v.y;
            float2 w = unpk(ax1[p]); fx1[2*p] = w.x; fx1[2*p+1] = w.y;
        }
        #pragma unroll
        for (int r = 0; r < ROWS; r++) {
            float gv0 = s_gi[r * 384 + c0];
            s_preA[c0 * 15 + r] = f0[r] + gv0;
        }
        if (c1 < GG) {
            #pragma unroll
            for (int r = 0; r < ROWS; r++) {
                float gv1 = s_gi[r * 384 + c1];
                s_preA[c1 * 15 + r] = f1[r] + gv1;
                if (c1 >= 2 * HH) s_preB[(c1 - 2 * HH) * 15 + r] = fx1[r] + gv1;
            }
        }
    }
    if (tid < ROWS) s_out[tid] = 0.0f;
    __syncthreads();

    // gates + h2o; hnew written back into s_in h-region for Wh GEMM
    for (int i = tid; i < ROWS * 128; i += 192) {
        int r = i >> 7;
        int j = i & 127;
        float val = 0.0f;
        if (r < nrow && j < HH) {
            float pr = s_preA[j * 15 + r];
            float pz = s_preA[(HH + j) * 15 + r];
            float nx = s_preB[j * 15 + r];
            float nh = s_preA[(2 * HH + j) * 15 + r] - nx + bhh[2 * HH + j];
            float rg = sigf(pr);
            float zg = sigf(pz);
            float nn = tanhp(nx + rg * nh);
            float hv = s_in[(XDP + j) * 16 + r];
            float hnew = (1.0f - zg) * nn + zg * hv;
            h_out[(size_t)(b0 + r) * HS + j] = hnew;
            s_in[(XDP + j) * 16 + r] = hnew;
            val = hnew * h2oW[j];
        }
        #pragma unroll
        for (int off = 16; off; off >>= 1) val += __shfl_down_sync(0xffffffffu, val, off);
        if (lane == 0 && r < nrow) atomicAdd(&s_out[r], val);
    }
    __syncthreads();
    if (tid < nrow) out[b0 + tid] = s_out[tid] + h2ob[0];

    // fused Wh for the NEXT step (threads 0..127, col j, 14 rows via f32x2)
    if (tid < 128) {
        const int j = tid;
        unsigned long long wa[7];
        #pragma unroll
        for (int p = 0; p < 7; p++) wa[p] = dupf(0.0f);
        #pragma unroll 2
        for (int k = 0; k < HH; k++) {
            unsigned long long wd = dupf(WlTp[k * HS + j]);
            const float* sp = s_in + (XDP + k) * 16;
            const ulonglong2* sp2 = reinterpret_cast<const ulonglong2*>(sp);
            ulonglong2 q0 = sp2[0], q1 = sp2[1], q2 = sp2[2];
            unsigned long long q3 = *reinterpret_cast<const unsigned long long*>(sp + 12);
            fma2(wa[0], wd, q0.x); fma2(wa[1], wd, q0.y);
            fma2(wa[2], wd, q1.x); fma2(wa[3], wd, q1.y);
            fma2(wa[4], wd, q2.x); fma2(wa[5], wd, q2.y);
            fma2(wa[6], wd, q3);
        }
        float bj = Wlbp[j];
        #pragma unroll
        for (int p = 0; p < 7; p++) {
            float2 f = unpk(wa[p]);
            if (2 * p < nrow)     Wh[(size_t)(b0 + 2 * p) * HS + j]     = f.x + bj;
            if (2 * p + 1 < nrow) Wh[(size_t)(b0 + 2 * p + 1) * HS + j] = f.y + bj;
        }
    }
}

// ---------------- dense [rows x 126] @ [126 x 128] + bias (f32x2) ----------
template <bool BF16OUT>
__global__ __launch_bounds__(256, 2) void lin_kernel(const float* __restrict__ in,
                                                     const float* __restrict__ Wp,
                                                     const float* __restrict__ biasp,
                                                     float* __restrict__ outf,
                                                     __nv_bfloat16* __restrict__ outb) {
    constexpr int P2 = 36;
    extern __shared__ float sm[];
    float* s_w  = sm;
    float* s_in = sm + HH * HS;
    const int tid = threadIdx.x;
    const int b0 = blockIdx.x * 32;

    {
        const float4* src = reinterpret_cast<const float4*>(Wp);
        float4* dst = reinterpret_cast<float4*>(s_w);
        for (int v = tid; v < HH * HS / 4; v += 256) dst[v] = src[v];
    }
    for (int idx = tid; idx < HH * 32; idx += 256) {
        int r = idx / HH, k = idx % HH;
        s_in[k * P2 + r] = in[(size_t)(b0 + r) * HS + k];
    }
    __syncthreads();

    const int j = tid & 127;
    const int half = tid >> 7;
    unsigned long long accp[8];
    #pragma unroll
    for (int p = 0; p < 8; p++) accp[p] = dupf(0.0f);
    #pragma unroll 2
    for (int k = 0; k < HH; k++) {
        unsigned long long wd = dupf(s_w[k * HS + j]);
        const ulonglong2* sp2 = reinterpret_cast<const ulonglong2*>(s_in + k * P2 + half * 16);
        ulonglong2 q0 = sp2[0], q1 = sp2[1], q2 = sp2[2], q3 = sp2[3];
        fma2(accp[0], wd, q0.x); fma2(accp[1], wd, q0.y);
        fma2(accp[2], wd, q1.x); fma2(accp[3], wd, q1.y);
        fma2(accp[4], wd, q2.x); fma2(accp[5], wd, q2.y);
        fma2(accp[6], wd, q3.x); fma2(accp[7], wd, q3.y);
    }
    float bj = biasp[j];
    #pragma unroll
    for (int p = 0; p < 8; p++) {
        float2 f = unpk(accp[p]);
        size_t i0 = (size_t)(b0 + half * 16 + 2 * p) * HS + j;
        size_t i1 = (size_t)(b0 + half * 16 + 2 * p + 1) * HS + j;
        if (BF16OUT) {
            outb[i0] = __float2bfloat16(f.x + bj);
            outb[i1] = __float2bfloat16(f.y + bj);
        } else {
            outf[i0] = f.x + bj;
            outf[i1] = f.y + bj;
        }
    }
}

// ---------------- fused attention: scores + softmax + context + x ----------
__global__ __launch_bounds__(128) void attn_kernel(
        const __nv_bfloat16* __restrict__ Uobf, const float* __restrict__ Wh,
        const float* __restrict__ Vp, const float* __restrict__ Vb,
        const __nv_bfloat16* __restrict__ encbf,
        const float* __restrict__ enc_data, const float* __restrict__ outbuf,
        float* __restrict__ x, int step) {
    __shared__ float sal[TT * 4];
    const int tid = threadIdx.x;
    const int warp = tid >> 5, lane = tid & 31;
    const int row = blockIdx.x * 4 + warp;

    const float4 wh = *(reinterpret_cast<const float4*>(Wh + (size_t)row * HS) + lane);
    const float4 vv = *(reinterpret_cast<const float4*>(Vp) + lane);
    const float vb = Vb[0];

    #pragma unroll 4
    for (int t = 0; t < TT; t++) {
        uint2 p = *(reinterpret_cast<const uint2*>(Uobf + ((size_t)t * BB + row) * HS) + lane);
        float2 u0 = __bfloat1622float2(*reinterpret_cast<const __nv_bfloat162*>(&p.x));
        float2 u1 = __bfloat1622float2(*reinterpret_cast<const __nv_bfloat162*>(&p.y));
        float a = tanha(u0.x + wh.x) * vv.x + tanha(u0.y + wh.y) * vv.y
                + tanha(u1.x + wh.z) * vv.z + tanha(u1.y + wh.w) * vv.w;
        #pragma unroll
        for (int off = 16; off; off >>= 1) a += __shfl_down_sync(0xffffffffu, a, off);
        if (lane == 0) sal[t * 4 + warp] = a + vb;
    }
    __syncthreads();

    if (tid < 4) {
        float mx = -1e30f;
        for (int t = 0; t < TT; t++) mx = fmaxf(mx, sal[t * 4 + tid]);
        float sum = 0.0f;
        for (int t = 0; t < TT; t++) {
            float e = ex2f((sal[t * 4 + tid] - mx) * LOG2E_);
            sal[t * 4 + tid] = e;
            sum += e;
        }
        float inv = rcpf(sum);
        for (int t = 0; t < TT; t++) sal[t * 4 + tid] *= inv;
    }
    __syncthreads();

    float4 acc = {0.f, 0.f, 0.f, 0.f};
    #pragma unroll 4
    for (int t = 0; t < TT; t++) {
        float al = sal[t * 4 + warp];
        uint2 p = *(reinterpret_cast<const uint2*>(encbf + ((size_t)t * BB + row) * HS) + lane);
        float2 e0 = __bfloat1622float2(*reinterpret_cast<const __nv_bfloat162*>(&p.x));
        float2 e1 = __bfloat1622float2(*reinterpret_cast<const __nv_bfloat162*>(&p.y));
        acc.x += al * e0.x; acc.y += al * e0.y; acc.z += al * e1.x; acc.w += al * e1.y;
    }
    float* xr = x + (size_t)row * HS;
    if (lane < 31) {
        *(reinterpret_cast<float4*>(xr) + lane) = acc;
    } else {
        xr[124] = acc.x;
        xr[125] = acc.y;
    }
    if (lane == 0) {
        float prev = (step == 0) ? enc_data[((size_t)(TT - 1) * BB + row) * ENC_]
                                 : outbuf[(size_t)(step - 1) * BB + row];
        xr[126] = prev;
    }
}

// ---------------- host side ----------------
extern "C" void kernel_launch(void* const* d_in, const int* in_sizes, int n_in,
                              void* d_out, int out_size) {
    const float* ann      = (const float*)d_in[0];
    const float* enc_data = (const float*)d_in[1];
    const float* dec_data = (const float*)d_in[2];
    const float* s2h_W1   = (const float*)d_in[3];
    const float* s2h_b1   = (const float*)d_in[4];
    const float* s2h_W2   = (const float*)d_in[5];
    const float* s2h_b2   = (const float*)d_in[6];
    const float* enc_Wih  = (const float*)d_in[7];
    const float* enc_Whh  = (const float*)d_in[8];
    const float* enc_bih  = (const float*)d_in[9];
    const float* enc_bhh  = (const float*)d_in[10];
    const float* dec_Wih  = (const float*)d_in[11];
    const float* dec_Whh  = (const float*)d_in[12];
    const float* dec_bih  = (const float*)d_in[13];
    const float* dec_bhh  = (const float*)d_in[14];
    const float* U_W      = (const float*)d_in[15];
    const float* U_b      = (const float*)d_in[16];
    const float* Wl_W     = (const float*)d_in[17];
    const float* Wl_b     = (const float*)d_in[18];
    const float* V_W      = (const float*)d_in[19];
    const float* V_b      = (const float*)d_in[20];
    const float* h2o_W    = (const float*)d_in[21];
    const float* h2o_b    = (const float*)d_in[22];
    float* outp = (float*)d_out;

    float *h0, *h1, *enc_out, *Wh, *x, *giE, *giD;
    float *Wenc, *Wdec, *WgiE, *WgiD, *bgE, *bgD, *UWTp, *WlTp, *Ubp, *Wlbp, *Vp;
    __nv_bfloat16 *Uobf, *encbf;
    cudaGetSymbolAddress((void**)&h0, g_h0);
    cudaGetSymbolAddress((void**)&h1, g_h1);
    cudaGetSymbolAddress((void**)&enc_out, g_enc_out);
    cudaGetSymbolAddress((void**)&encbf, g_enc_bf);
    cudaGetSymbolAddress((void**)&Uobf, g_Uobf);
    cudaGetSymbolAddress((void**)&Wh, g_Wh);
    cudaGetSymbolAddress((void**)&x, g_x);
    cudaGetSymbolAddress((void**)&giE, g_giE);
    cudaGetSymbolAddress((void**)&giD, g_giD);
    cudaGetSymbolAddress((void**)&Wenc, g_Wenc);
    cudaGetSymbolAddress((void**)&Wdec, g_Wdec);
    cudaGetSymbolAddress((void**)&WgiE, g_WgiE);
    cudaGetSymbolAddress((void**)&WgiD, g_WgiD);
    cudaGetSymbolAddress((void**)&bgE, g_bgE);
    cudaGetSymbolAddress((void**)&bgD, g_bgD);
    cudaGetSymbolAddress((void**)&UWTp, g_UWTp);
    cudaGetSymbolAddress((void**)&WlTp, g_WlTp);
    cudaGetSymbolAddress((void**)&Ubp, g_Ubp);
    cudaGetSymbolAddress((void**)&Wlbp, g_Wlbp);
    cudaGetSymbolAddress((void**)&Vp, g_Vp);

    const size_t sm_enc = (size_t)(128 * 16 + 2 * 16 * 384 + ROWS * 384) * 4;  // 78848
    const size_t sm_dec = (size_t)(256 * 16 + 2 * 16 * 384 + ROWS * 384) * 4;  // 87040
    const size_t sm_uo  = (size_t)(HH * HS + HH * 36) * 4;
    cudaFuncSetAttribute((const void*)gruE_kernel,
                         cudaFuncAttributeMaxDynamicSharedMemorySize, (int)sm_enc);
    cudaFuncSetAttribute((const void*)gruD_kernel,
                         cudaFuncAttributeMaxDynamicSharedMemorySize, (int)sm_dec);
    cudaFuncSetAttribute((const void*)lin_kernel<false>,
                         cudaFuncAttributeMaxDynamicSharedMemorySize, (int)sm_uo);
    cudaFuncSetAttribute((const void*)lin_kernel<true>,
                         cudaFuncAttributeMaxDynamicSharedMemorySize, (int)sm_uo);

    const int total_w = 128 * 384 + 256 * 384 + ENC_ * 384 + DEC_ * 384 + 384
                      + 2 * HH * HS + 3 * HS;
    prep_weights<<<(total_w + 255) / 256, 256>>>(enc_Wih, enc_Whh, dec_Wih, dec_Whh,
                                                 U_W, U_b, Wl_W, Wl_b, V_W,
                                                 enc_bih, enc_bhh, dec_bih, dec_bhh);

    s2h_kernel<<<BB, 128>>>(ann, s2h_W1, s2h_b1, s2h_W2, s2h_b2, h0);

    gi_kernel<ENC_><<<TT * BB / 16, 384>>>(enc_data, WgiE, bgE, giE);

    for (int t = 0; t < TT; t++) {
        const float* hin = (t == 0) ? h0 : enc_out + (size_t)(t - 1) * BB * HS;
        gruE_kernel<<<NBLK, 192, sm_enc>>>(
            hin, Wenc, giE + (size_t)t * BB * 384, enc_bhh,
            enc_out + (size_t)t * BB * HS, encbf + (size_t)t * BB * HS);
    }

    // giD launched here (overlaps nothing critical; also shifts ncu -s capture
    // onto an encoder GRU instance for diagnostics)
    gi_kernel<DEC_><<<NSTEPS * BB / 16, 384>>>(dec_data, WgiD, bgD, giD);

    // Uo in bf16 (written once, streamed 28x)
    lin_kernel<true><<<TT * BB / 32, 256, sm_uo>>>(enc_out, UWTp, Ubp, nullptr, Uobf);

    const float* enc_last = enc_out + (size_t)(TT - 1) * BB * HS;
    lin_kernel<false><<<BB / 32, 256, sm_uo>>>(enc_last, WlTp, Wlbp, Wh, nullptr);

    for (int s = 0; s < NSTEPS; s++) {
        const float* hcur = (s == 0) ? enc_last : ((s & 1) ? h0 : h1);
        float* hnext      = (s & 1) ? h1 : h0;
        attn_kernel<<<BB / 4, 128>>>(Uobf, Wh, Vp, V_b, encbf, enc_data, outp, x, s);
        gruD_kernel<<<NBLK, 192, sm_dec>>>(
            hcur, x, Wdec, giD + (size_t)s * BB * 384, dec_bhh, hnext,
            h2o_W, h2o_b, outp + (size_t)s * BB, WlTp, Wlbp, Wh);
    }
}